// round 5
// baseline (speedup 1.0000x reference)
#include <cuda_runtime.h>
#include <math.h>
#include <stdint.h>

// Problem constants
#define BB   4
#define LQd  256
#define NSd  24
#define NTd  128
#define Dd   512
#define Hd   8
#define DKd  64

// ---------------- scratch ----------------
#define OFF_QS   0
#define OFF_QW   524288
#define OFF_KS   1048576
#define OFF_VS   1097728
#define OFF_KW   1146880
#define OFF_VW   7438336
#define OFF_ATT  13729792
#define OFF_CTXS 13926400
#define OFF_CTXW 14450688
#define OFF_CAT  14974976
#define OFF_WH   16023552
#define OFF_WL   (OFF_WH + 2621440)
#define OFF_AH   (OFF_WL + 2621440)       // split activations hi
#define OFF_AL   (OFF_AH + 13205504)      // split activations lo
#define SCRATCH_TOTAL (OFF_AL + 13205504)
__device__ float g_scratch[SCRATCH_TOTAL];

// weight order: wq_s wk_s wv_s wq_w wk_w wv_w fcs_w fcw_w fco_w
#define WOFF(i) ((i) * 262144)
// activation split sub-offsets (within AH/AL)
#define AQ   0
#define AKS  524288
#define AVS  573440
#define AKW  622592
#define AVW  6914048

// ---------------- tf32 helpers ----------------
__device__ __forceinline__ uint32_t f2tf32(float x) {
    uint32_t r;
    asm("cvt.rna.tf32.f32 %0, %1;" : "=r"(r) : "f"(x));
    return r;
}
__device__ __forceinline__ void split_tf32(float x, uint32_t& hi, uint32_t& lo) {
    hi = f2tf32(x);
    lo = f2tf32(x - __uint_as_float(hi));
}
__device__ __forceinline__ void mma_tf32(float d[4],
                                         uint32_t a0, uint32_t a1, uint32_t a2, uint32_t a3,
                                         uint32_t b0, uint32_t b1) {
    asm volatile(
        "mma.sync.aligned.m16n8k8.row.col.f32.tf32.tf32.f32 "
        "{%0,%1,%2,%3},{%4,%5,%6,%7},{%8,%9},{%0,%1,%2,%3};"
        : "+f"(d[0]), "+f"(d[1]), "+f"(d[2]), "+f"(d[3])
        : "r"(a0), "r"(a1), "r"(a2), "r"(a3), "r"(b0), "r"(b1));
}

__device__ __forceinline__ void cp_async16(uint32_t smem_addr, const void* gptr, int src_bytes) {
    asm volatile("cp.async.cg.shared.global [%0], [%1], 16, %2;"
                 :: "r"(smem_addr), "l"(gptr), "r"(src_bytes) : "memory");
}
__device__ __forceinline__ void cp_commit() { asm volatile("cp.async.commit_group;" ::: "memory"); }
template <int N>
__device__ __forceinline__ void cp_wait() { asm volatile("cp.async.wait_group %0;" :: "n"(N) : "memory"); }

// ---------------- prep: split weights + activations ----------------
struct PrepArgs2 {
    const float* src[14];
    float* dsth[14];
    float* dstl[14];
    int n[14];
};

__global__ __launch_bounds__(256) void prep_split2(PrepArgs2 args)
{
    int w = blockIdx.y;
    int n = args.n[w];
    const float* s = args.src[w];
    float* dh = args.dsth[w];
    float* dl = args.dstl[w];
    for (int i = blockIdx.x * 256 + threadIdx.x; i < n; i += gridDim.x * 256) {
        float x = s[i];
        uint32_t hi, lo;
        split_tf32(x, hi, lo);
        dh[i] = __uint_as_float(hi);
        dl[i] = __uint_as_float(lo);
    }
}

// ---------------- GEMM, both operands pre-split ----------------
// 128x128 tile, BK=32, 512 threads (16 warps 4x4, warp tile 32x32)
#define GAPAD 36
#define GBPAD 136
#define G_AS  (128 * GAPAD)          // 4608
#define G_BS  (32 * GBPAD)           // 4352
#define PSTAGE (2 * G_AS + 2 * G_BS) // 17920 floats
#define PSMEM_BYTES (2 * PSTAGE * 4) // 143360

__global__ __launch_bounds__(512) void gemm_presplit(
    const float* __restrict__ Ah0, const float* __restrict__ Al0,
    const float* __restrict__ Ah1, const float* __restrict__ Al1,
    const float* __restrict__ Bh0, const float* __restrict__ Bl0,
    const float* __restrict__ Bh1, const float* __restrict__ Bl1,
    const float* __restrict__ bias0, const float* __restrict__ bias1,
    float* __restrict__ C0, float* __restrict__ C1,
    int M, int N, int K, int lda, int ldb, int ldc)
{
    extern __shared__ float gsm[];

    const int z = blockIdx.z;
    const float* Ah_g = z ? Ah1 : Ah0;
    const float* Al_g = z ? Al1 : Al0;
    const float* Bh_g = z ? Bh1 : Bh0;
    const float* Bl_g = z ? Bl1 : Bl0;
    const float* bias = z ? bias1 : bias0;
    float* C          = z ? C1 : C0;

    const int tid = threadIdx.x;
    const int wid = tid >> 5;
    const int lane = tid & 31;
    const int g = lane >> 2;
    const int t = lane & 3;
    const int wm = wid & 3;
    const int wn = wid >> 2;
    const int row0 = blockIdx.y * 128;
    const int col0 = blockIdx.x * 128;

    float dm[2][4][4], dc[2][4][4];
    #pragma unroll
    for (int mt = 0; mt < 2; mt++)
        #pragma unroll
        for (int nt = 0; nt < 4; nt++)
            #pragma unroll
            for (int j = 0; j < 4; j++) { dm[mt][nt][j] = 0.f; dc[mt][nt][j] = 0.f; }

    const int ktiles = K >> 5;

    {
        float* Ahs = gsm;
        float* Als = Ahs + G_AS;
        float* Bhs = Als + G_AS;
        float* Bls = Bhs + G_BS;
        #pragma unroll
        for (int i = 0; i < 2; i++) {
            int id = tid + 512 * i;
            int ar = id >> 3, ac = id & 7;
            int r = row0 + ar;
            int rc = r < M ? r : (M - 1);
            int pb = r < M ? 16 : 0;
            cp_async16((uint32_t)__cvta_generic_to_shared(&Ahs[ar * GAPAD + ac * 4]),
                       &Ah_g[(size_t)rc * lda + ac * 4], pb);
            cp_async16((uint32_t)__cvta_generic_to_shared(&Als[ar * GAPAD + ac * 4]),
                       &Al_g[(size_t)rc * lda + ac * 4], pb);
            int br = id >> 5, bc = id & 31;
            cp_async16((uint32_t)__cvta_generic_to_shared(&Bhs[br * GBPAD + bc * 4]),
                       &Bh_g[(size_t)br * ldb + col0 + bc * 4], 16);
            cp_async16((uint32_t)__cvta_generic_to_shared(&Bls[br * GBPAD + bc * 4]),
                       &Bl_g[(size_t)br * ldb + col0 + bc * 4], 16);
        }
        cp_commit();
    }

    for (int kt = 0; kt < ktiles; kt++) {
        if (kt + 1 < ktiles) {
            float* Ahs = gsm + ((kt + 1) & 1) * PSTAGE;
            float* Als = Ahs + G_AS;
            float* Bhs = Als + G_AS;
            float* Bls = Bhs + G_BS;
            int k0 = (kt + 1) << 5;
            #pragma unroll
            for (int i = 0; i < 2; i++) {
                int id = tid + 512 * i;
                int ar = id >> 3, ac = id & 7;
                int r = row0 + ar;
                int rc = r < M ? r : (M - 1);
                int pb = r < M ? 16 : 0;
                cp_async16((uint32_t)__cvta_generic_to_shared(&Ahs[ar * GAPAD + ac * 4]),
                           &Ah_g[(size_t)rc * lda + k0 + ac * 4], pb);
                cp_async16((uint32_t)__cvta_generic_to_shared(&Als[ar * GAPAD + ac * 4]),
                           &Al_g[(size_t)rc * lda + k0 + ac * 4], pb);
                int br = id >> 5, bc = id & 31;
                cp_async16((uint32_t)__cvta_generic_to_shared(&Bhs[br * GBPAD + bc * 4]),
                           &Bh_g[(size_t)(k0 + br) * ldb + col0 + bc * 4], 16);
                cp_async16((uint32_t)__cvta_generic_to_shared(&Bls[br * GBPAD + bc * 4]),
                           &Bl_g[(size_t)(k0 + br) * ldb + col0 + bc * 4], 16);
            }
            cp_commit();
            cp_wait<1>();
        } else {
            cp_wait<0>();
        }
        __syncthreads();

        const float* Ahs = gsm + (kt & 1) * PSTAGE;
        const float* Als = Ahs + G_AS;
        const float* Bhs = Als + G_AS;
        const float* Bls = Bhs + G_BS;

        #pragma unroll
        for (int ks = 0; ks < 4; ks++) {
            const int k = ks * 8;
            uint32_t ah[2][4], al[2][4];
            #pragma unroll
            for (int mt = 0; mt < 2; mt++) {
                int r0 = wm * 32 + mt * 16 + g;
                ah[mt][0] = __float_as_uint(Ahs[r0 * GAPAD + k + t]);
                ah[mt][1] = __float_as_uint(Ahs[(r0 + 8) * GAPAD + k + t]);
                ah[mt][2] = __float_as_uint(Ahs[r0 * GAPAD + k + t + 4]);
                ah[mt][3] = __float_as_uint(Ahs[(r0 + 8) * GAPAD + k + t + 4]);
                al[mt][0] = __float_as_uint(Als[r0 * GAPAD + k + t]);
                al[mt][1] = __float_as_uint(Als[(r0 + 8) * GAPAD + k + t]);
                al[mt][2] = __float_as_uint(Als[r0 * GAPAD + k + t + 4]);
                al[mt][3] = __float_as_uint(Als[(r0 + 8) * GAPAD + k + t + 4]);
            }
            #pragma unroll
            for (int nt = 0; nt < 4; nt++) {
                int c = wn * 32 + nt * 8 + g;
                uint32_t bh0 = __float_as_uint(Bhs[(k + t) * GBPAD + c]);
                uint32_t bh1 = __float_as_uint(Bhs[(k + t + 4) * GBPAD + c]);
                uint32_t bl0 = __float_as_uint(Bls[(k + t) * GBPAD + c]);
                uint32_t bl1 = __float_as_uint(Bls[(k + t + 4) * GBPAD + c]);
                #pragma unroll
                for (int mt = 0; mt < 2; mt++) {
                    mma_tf32(dm[mt][nt], ah[mt][0], ah[mt][1], ah[mt][2], ah[mt][3], bh0, bh1);
                    mma_tf32(dc[mt][nt], ah[mt][0], ah[mt][1], ah[mt][2], ah[mt][3], bl0, bl1);
                    mma_tf32(dc[mt][nt], al[mt][0], al[mt][1], al[mt][2], al[mt][3], bh0, bh1);
                }
            }
        }
        __syncthreads();
    }

    #pragma unroll
    for (int mt = 0; mt < 2; mt++) {
        #pragma unroll
        for (int nt = 0; nt < 4; nt++) {
            int r = row0 + wm * 32 + mt * 16 + g;
            int c = col0 + wn * 32 + nt * 8 + 2 * t;
            float2 bz = *(const float2*)&bias[c];
            if (r < M) {
                float2 o = make_float2(dm[mt][nt][0] + dc[mt][nt][0] + bz.x,
                                       dm[mt][nt][1] + dc[mt][nt][1] + bz.y);
                *(float2*)&C[(size_t)r * ldc + c] = o;
            }
            if (r + 8 < M) {
                float2 o = make_float2(dm[mt][nt][2] + dc[mt][nt][2] + bz.x,
                                       dm[mt][nt][3] + dc[mt][nt][3] + bz.y);
                *(float2*)&C[(size_t)(r + 8) * ldc + c] = o;
            }
        }
    }
}

// ---------------- GEMM, A split inline (for FC layers) ----------------
#define G_BS2 (32 * GBPAD)
#define GSTAGE (128 * GAPAD + 2 * G_BS2)
#define GSMEM_BYTES (2 * GSTAGE * 4)

__global__ __launch_bounds__(512) void gemm_tc2(
    const float* __restrict__ A0, const float* __restrict__ A1,
    const float* __restrict__ Bh0, const float* __restrict__ Bl0,
    const float* __restrict__ Bh1, const float* __restrict__ Bl1,
    const float* __restrict__ bias0, const float* __restrict__ bias1,
    float* __restrict__ C0, float* __restrict__ C1,
    int M, int N, int K, int lda, int ldb, int ldc)
{
    extern __shared__ float gsm[];

    const int z = blockIdx.z;
    const float* A    = z ? A1 : A0;
    const float* Bh_g = z ? Bh1 : Bh0;
    const float* Bl_g = z ? Bl1 : Bl0;
    const float* bias = z ? bias1 : bias0;
    float* C          = z ? C1 : C0;

    const int tid = threadIdx.x;
    const int wid = tid >> 5;
    const int lane = tid & 31;
    const int g = lane >> 2;
    const int t = lane & 3;
    const int wm = wid & 3;
    const int wn = wid >> 2;
    const int row0 = blockIdx.y * 128;
    const int col0 = blockIdx.x * 128;

    float d[2][4][4];
    #pragma unroll
    for (int mt = 0; mt < 2; mt++)
        #pragma unroll
        for (int nt = 0; nt < 4; nt++)
            #pragma unroll
            for (int j = 0; j < 4; j++) d[mt][nt][j] = 0.f;

    const int ktiles = K >> 5;

    {
        float* As  = gsm;
        float* Bhs = gsm + 128 * GAPAD;
        float* Bls = Bhs + G_BS2;
        #pragma unroll
        for (int i = 0; i < 2; i++) {
            int id = tid + 512 * i;
            int ar = id >> 3, ac = id & 7;
            int r = row0 + ar;
            int rc = r < M ? r : (M - 1);
            cp_async16((uint32_t)__cvta_generic_to_shared(&As[ar * GAPAD + ac * 4]),
                       &A[(size_t)rc * lda + ac * 4], r < M ? 16 : 0);
            int br = id >> 5, bc = id & 31;
            cp_async16((uint32_t)__cvta_generic_to_shared(&Bhs[br * GBPAD + bc * 4]),
                       &Bh_g[(size_t)br * ldb + col0 + bc * 4], 16);
            cp_async16((uint32_t)__cvta_generic_to_shared(&Bls[br * GBPAD + bc * 4]),
                       &Bl_g[(size_t)br * ldb + col0 + bc * 4], 16);
        }
        cp_commit();
    }

    for (int kt = 0; kt < ktiles; kt++) {
        if (kt + 1 < ktiles) {
            float* As  = gsm + ((kt + 1) & 1) * GSTAGE;
            float* Bhs = As + 128 * GAPAD;
            float* Bls = Bhs + G_BS2;
            int k0 = (kt + 1) << 5;
            #pragma unroll
            for (int i = 0; i < 2; i++) {
                int id = tid + 512 * i;
                int ar = id >> 3, ac = id & 7;
                int r = row0 + ar;
                int rc = r < M ? r : (M - 1);
                cp_async16((uint32_t)__cvta_generic_to_shared(&As[ar * GAPAD + ac * 4]),
                           &A[(size_t)rc * lda + k0 + ac * 4], r < M ? 16 : 0);
                int br = id >> 5, bc = id & 31;
                cp_async16((uint32_t)__cvta_generic_to_shared(&Bhs[br * GBPAD + bc * 4]),
                           &Bh_g[(size_t)(k0 + br) * ldb + col0 + bc * 4], 16);
                cp_async16((uint32_t)__cvta_generic_to_shared(&Bls[br * GBPAD + bc * 4]),
                           &Bl_g[(size_t)(k0 + br) * ldb + col0 + bc * 4], 16);
            }
            cp_commit();
            cp_wait<1>();
        } else {
            cp_wait<0>();
        }
        __syncthreads();

        const float* As  = gsm + (kt & 1) * GSTAGE;
        const float* Bhs = As + 128 * GAPAD;
        const float* Bls = Bhs + G_BS2;

        #pragma unroll
        for (int ks = 0; ks < 4; ks++) {
            const int k = ks * 8;
            uint32_t ah[2][4], al[2][4];
            #pragma unroll
            for (int mt = 0; mt < 2; mt++) {
                int r0 = wm * 32 + mt * 16 + g;
                float x0 = As[r0 * GAPAD + k + t];
                float x1 = As[(r0 + 8) * GAPAD + k + t];
                float x2 = As[r0 * GAPAD + k + t + 4];
                float x3 = As[(r0 + 8) * GAPAD + k + t + 4];
                split_tf32(x0, ah[mt][0], al[mt][0]);
                split_tf32(x1, ah[mt][1], al[mt][1]);
                split_tf32(x2, ah[mt][2], al[mt][2]);
                split_tf32(x3, ah[mt][3], al[mt][3]);
            }
            #pragma unroll
            for (int nt = 0; nt < 4; nt++) {
                int c = wn * 32 + nt * 8 + g;
                uint32_t bh0 = __float_as_uint(Bhs[(k + t) * GBPAD + c]);
                uint32_t bh1 = __float_as_uint(Bhs[(k + t + 4) * GBPAD + c]);
                uint32_t bl0 = __float_as_uint(Bls[(k + t) * GBPAD + c]);
                uint32_t bl1 = __float_as_uint(Bls[(k + t + 4) * GBPAD + c]);
                #pragma unroll
                for (int mt = 0; mt < 2; mt++) {
                    mma_tf32(d[mt][nt], ah[mt][0], ah[mt][1], ah[mt][2], ah[mt][3], bh0, bh1);
                    mma_tf32(d[mt][nt], ah[mt][0], ah[mt][1], ah[mt][2], ah[mt][3], bl0, bl1);
                    mma_tf32(d[mt][nt], al[mt][0], al[mt][1], al[mt][2], al[mt][3], bh0, bh1);
                }
            }
        }
        __syncthreads();
    }

    #pragma unroll
    for (int mt = 0; mt < 2; mt++) {
        #pragma unroll
        for (int nt = 0; nt < 4; nt++) {
            int r = row0 + wm * 32 + mt * 16 + g;
            int c = col0 + wn * 32 + nt * 8 + 2 * t;
            float2 bz = *(const float2*)&bias[c];
            if (r < M) {
                float2 o = make_float2(d[mt][nt][0] + bz.x, d[mt][nt][1] + bz.y);
                *(float2*)&C[(size_t)r * ldc + c] = o;
            }
            if (r + 8 < M) {
                float2 o = make_float2(d[mt][nt][2] + bz.x, d[mt][nt][3] + bz.y);
                *(float2*)&C[(size_t)(r + 8) * ldc + c] = o;
            }
        }
    }
}

// ---------------- sentence-level graph attention ----------------
__global__ __launch_bounds__(256) void sent_attn(
    const float* __restrict__ qs, const float* __restrict__ ksn,
    const float* __restrict__ vsn, const float* __restrict__ bias_s,
    const float* __restrict__ gab,
    float* __restrict__ attns_out, float* __restrict__ ctxs_out)
{
    const int h = blockIdx.x, b = blockIdx.y;
    const int q = threadIdx.x;

    __shared__ float Ks[NSd][DKd + 1];
    __shared__ float Vs[NSd][DKd + 1];
    __shared__ float G[NSd][NSd + 1];

    for (int idx = q; idx < NSd * DKd; idx += 256) {
        int s = idx >> 6, k = idx & 63;
        Ks[s][k] = ksn[(size_t)(b * NSd + s) * Dd + h * DKd + k];
        Vs[s][k] = vsn[(size_t)(b * NSd + s) * Dd + h * DKd + k];
    }
    for (int idx = q; idx < NSd * NSd; idx += 256) {
        int s = idx / NSd, tt = idx % NSd;
        G[s][tt] = gab[((size_t)(b * Hd + h) * NSd + s) * NSd + tt];
    }
    __syncthreads();

    float qreg[DKd];
    const float* qrow = qs + (size_t)(b * LQd + q) * Dd + h * DKd;
    #pragma unroll
    for (int k = 0; k < DKd; k++) qreg[k] = qrow[k] * 0.125f;

    float a[NSd];
    const float* bsrow = bias_s + ((size_t)(b * Hd + h) * LQd + q) * NSd;
    #pragma unroll
    for (int s = 0; s < NSd; s++) {
        float dd = 0.f;
        #pragma unroll
        for (int k = 0; k < DKd; k++) dd += qreg[k] * Ks[s][k];
        a[s] = dd + bsrow[s];
    }

    float m = -1e30f;
    #pragma unroll
    for (int s = 0; s < NSd; s++) m = fmaxf(m, a[s]);
    float smx[NSd]; float sum = 0.f;
    #pragma unroll
    for (int s = 0; s < NSd; s++) { smx[s] = __expf(a[s] - m); sum += smx[s]; }
    float inv = 1.f / sum;

    float gg[NSd];
    #pragma unroll
    for (int tt = 0; tt < NSd; tt++) {
        float dd = 0.f;
        #pragma unroll
        for (int s = 0; s < NSd; s++) dd += smx[s] * G[s][tt];
        gg[tt] = dd * inv;
    }
    #pragma unroll
    for (int s = 0; s < NSd; s++) a[s] -= 0.5f * gg[s] * gg[s];

    m = -1e30f;
    #pragma unroll
    for (int s = 0; s < NSd; s++) m = fmaxf(m, a[s]);
    sum = 0.f;
    #pragma unroll
    for (int s = 0; s < NSd; s++) { a[s] = __expf(a[s] - m); sum += a[s]; }
    inv = 1.f / sum;

    float* arow = attns_out + ((size_t)(b * Hd + h) * LQd + q) * NSd;
    #pragma unroll
    for (int s = 0; s < NSd; s++) { a[s] *= inv; arow[s] = a[s]; }

    float* crow = ctxs_out + (size_t)(b * LQd + q) * Dd + h * DKd;
    #pragma unroll
    for (int dd = 0; dd < DKd; dd++) {
        float acc = 0.f;
        #pragma unroll
        for (int s = 0; s < NSd; s++) acc += a[s] * Vs[s][dd];
        crow[dd] = acc;
    }
}

// ---------------- word-level attention, 64-query tiles ----------------
// grid (LQ/64, H, B) = (4,8,4), 256 threads (8 warps 2x4).
// QK: warp tile 32x32 of P=64x128. PV: warp tile 32x16 of O=64x64.
#define WQPAD 68
#define WKPAD 68
#define WPPAD 132
#define W_QH 0
#define W_QL (64 * WQPAD)
#define W_K  (2 * 64 * WQPAD)
#define W_V  (W_K + 128 * WKPAD)
#define W_P  (W_V + 128 * WKPAD)
#define WSMEM_WORDS (W_P + 64 * WPPAD)   // 34560 floats = 138240 B

__global__ __launch_bounds__(256) void word_attn64(
    const float* __restrict__ qw, const float* __restrict__ kw,
    const float* __restrict__ vw, const float* __restrict__ bias_w,
    const float* __restrict__ attns, float* __restrict__ ctxw)
{
    extern __shared__ float wsm[];
    uint32_t* Qh = (uint32_t*)(wsm + W_QH);
    uint32_t* Ql = (uint32_t*)(wsm + W_QL);
    float* Ks = wsm + W_K;
    float* Vs = wsm + W_V;
    float* Ps = wsm + W_P;

    const int tid = threadIdx.x;
    const int wid = tid >> 5;
    const int lane = tid & 31;
    const int g = lane >> 2;
    const int t = lane & 3;
    const int wm = wid & 1;     // 2 row groups of 32
    const int wn = wid >> 1;    // 4 col groups
    const int q0 = blockIdx.x * 64;
    const int h  = blockIdx.y;
    const int b  = blockIdx.z;

    // load Q (scaled), split hi/lo
    #pragma unroll
    for (int i = 0; i < 4; i++) {
        int id = tid + 256 * i;
        int qr = id >> 4, qc = id & 15;
        float4 v = *(const float4*)(qw + (size_t)(b * LQd + q0 + qr) * Dd + h * DKd + qc * 4);
        float vv[4] = {v.x * 0.125f, v.y * 0.125f, v.z * 0.125f, v.w * 0.125f};
        #pragma unroll
        for (int j = 0; j < 4; j++) {
            uint32_t hi, lo;
            split_tf32(vv[j], hi, lo);
            Qh[qr * WQPAD + qc * 4 + j] = hi;
            Ql[qr * WQPAD + qc * 4 + j] = lo;
        }
    }

    float oacc[2][2][4];
    #pragma unroll
    for (int mt = 0; mt < 2; mt++)
        #pragma unroll
        for (int nt = 0; nt < 2; nt++)
            #pragma unroll
            for (int j = 0; j < 4; j++) oacc[mt][nt][j] = 0.f;

    for (int s = 0; s < NSd; s++) {
        __syncthreads();
        const float* kb = kw + (size_t)(b * NSd + s) * NTd * Dd + h * DKd;
        const float* vb = vw + (size_t)(b * NSd + s) * NTd * Dd + h * DKd;
        #pragma unroll
        for (int i = 0; i < 8; i++) {
            int id = tid + 256 * i;
            int kr = id >> 4, kc = id & 15;
            float4 kv = *(const float4*)(kb + (size_t)kr * Dd + kc * 4);
            *(float4*)&Ks[kr * WKPAD + kc * 4] = kv;
            float4 vv = *(const float4*)(vb + (size_t)kr * Dd + kc * 4);
            *(float4*)&Vs[kr * WKPAD + kc * 4] = vv;
        }
        __syncthreads();

        // ---- P = Q @ K^T (warp tile 32x32) ----
        float pacc[2][4][4];
        #pragma unroll
        for (int mt = 0; mt < 2; mt++)
            #pragma unroll
            for (int nt = 0; nt < 4; nt++)
                #pragma unroll
                for (int j = 0; j < 4; j++) pacc[mt][nt][j] = 0.f;

        #pragma unroll
        for (int ks = 0; ks < 8; ks++) {
            const int k = ks * 8;
            uint32_t ah[2][4], al[2][4];
            #pragma unroll
            for (int mt = 0; mt < 2; mt++) {
                int r0 = wm * 32 + mt * 16 + g;
                ah[mt][0] = Qh[r0 * WQPAD + k + t];
                ah[mt][1] = Qh[(r0 + 8) * WQPAD + k + t];
                ah[mt][2] = Qh[r0 * WQPAD + k + t + 4];
                ah[mt][3] = Qh[(r0 + 8) * WQPAD + k + t + 4];
                al[mt][0] = Ql[r0 * WQPAD + k + t];
                al[mt][1] = Ql[(r0 + 8) * WQPAD + k + t];
                al[mt][2] = Ql[r0 * WQPAD + k + t + 4];
                al[mt][3] = Ql[(r0 + 8) * WQPAD + k + t + 4];
            }
            #pragma unroll
            for (int nt = 0; nt < 4; nt++) {
                int c = wn * 32 + nt * 8 + g;
                float y0 = Ks[c * WKPAD + k + t];
                float y1 = Ks[c * WKPAD + k + t + 4];
                uint32_t bh0, bl0, bh1, bl1;
                split_tf32(y0, bh0, bl0);
                split_tf32(y1, bh1, bl1);
                #pragma unroll
                for (int mt = 0; mt < 2; mt++) {
                    mma_tf32(pacc[mt][nt], ah[mt][0], ah[mt][1], ah[mt][2], ah[mt][3], bh0, bh1);
                    mma_tf32(pacc[mt][nt], ah[mt][0], ah[mt][1], ah[mt][2], ah[mt][3], bl0, bl1);
                    mma_tf32(pacc[mt][nt], al[mt][0], al[mt][1], al[mt][2], al[mt][3], bh0, bh1);
                }
            }
        }
        #pragma unroll
        for (int mt = 0; mt < 2; mt++)
            #pragma unroll
            for (int nt = 0; nt < 4; nt++) {
                int r = wm * 32 + mt * 16 + g;
                int c = wn * 32 + nt * 8 + 2 * t;
                *(float2*)&Ps[r * WPPAD + c] = make_float2(pacc[mt][nt][0], pacc[mt][nt][1]);
                *(float2*)&Ps[(r + 8) * WPPAD + c] = make_float2(pacc[mt][nt][2], pacc[mt][nt][3]);
            }
        __syncthreads();

        // ---- softmax rows (warp wid owns rows wid*8..wid*8+7) ----
        const float* bb = bias_w + ((size_t)((b * NSd + s) * Hd + h) * LQd + q0) * NTd;
        #pragma unroll
        for (int rr = 0; rr < 8; rr++) {
            int r = wid * 8 + rr;
            float x0 = Ps[r * WPPAD + lane]       + bb[r * NTd + lane];
            float x1 = Ps[r * WPPAD + lane + 32]  + bb[r * NTd + lane + 32];
            float x2 = Ps[r * WPPAD + lane + 64]  + bb[r * NTd + lane + 64];
            float x3 = Ps[r * WPPAD + lane + 96]  + bb[r * NTd + lane + 96];
            float mx = fmaxf(fmaxf(x0, x1), fmaxf(x2, x3));
            #pragma unroll
            for (int o = 16; o; o >>= 1) mx = fmaxf(mx, __shfl_xor_sync(0xffffffffu, mx, o));
            x0 = __expf(x0 - mx); x1 = __expf(x1 - mx);
            x2 = __expf(x2 - mx); x3 = __expf(x3 - mx);
            float su = x0 + x1 + x2 + x3;
            #pragma unroll
            for (int o = 16; o; o >>= 1) su += __shfl_xor_sync(0xffffffffu, su, o);
            float wsc = attns[((size_t)(b * Hd + h) * LQd + q0 + r) * NSd + s] / su;
            Ps[r * WPPAD + lane]      = x0 * wsc;
            Ps[r * WPPAD + lane + 32] = x1 * wsc;
            Ps[r * WPPAD + lane + 64] = x2 * wsc;
            Ps[r * WPPAD + lane + 96] = x3 * wsc;
        }
        __syncthreads();

        // ---- O += P @ V (warp tile 32x16) ----
        #pragma unroll
        for (int ks = 0; ks < 16; ks++) {
            const int k = ks * 8;
            uint32_t ph[2][4], pl[2][4];
            #pragma unroll
            for (int mt = 0; mt < 2; mt++) {
                int r0 = wm * 32 + mt * 16 + g;
                float p0 = Ps[r0 * WPPAD + k + t];
                float p1 = Ps[(r0 + 8) * WPPAD + k + t];
                float p2 = Ps[r0 * WPPAD + k + t + 4];
                float p3 = Ps[(r0 + 8) * WPPAD + k + t + 4];
                split_tf32(p0, ph[mt][0], pl[mt][0]);
                split_tf32(p1, ph[mt][1], pl[mt][1]);
                split_tf32(p2, ph[mt][2], pl[mt][2]);
                split_tf32(p3, ph[mt][3], pl[mt][3]);
            }
            #pragma unroll
            for (int nt = 0; nt < 2; nt++) {
                int c = wn * 16 + nt * 8 + g;
                float y0 = Vs[(k + t) * WKPAD + c];
                float y1 = Vs[(k + t + 4) * WKPAD + c];
                uint32_t bh0, bl0, bh1, bl1;
                split_tf32(y0, bh0, bl0);
                split_tf32(y1, bh1, bl1);
                #pragma unroll
                for (int mt = 0; mt < 2; mt++) {
                    mma_tf32(oacc[mt][nt], ph[mt][0], ph[mt][1], ph[mt][2], ph[mt][3], bh0, bh1);
                    mma_tf32(oacc[mt][nt], ph[mt][0], ph[mt][1], ph[mt][2], ph[mt][3], bl0, bl1);
                    mma_tf32(oacc[mt][nt], pl[mt][0], pl[mt][1], pl[mt][2], pl[mt][3], bh0, bh1);
                }
            }
        }
    }

    #pragma unroll
    for (int mt = 0; mt < 2; mt++)
        #pragma unroll
        for (int nt = 0; nt < 2; nt++) {
            int r = q0 + wm * 32 + mt * 16 + g;
            int c = h * DKd + wn * 16 + nt * 8 + 2 * t;
            *(float2*)&ctxw[(size_t)(b * LQd + r) * Dd + c] =
                make_float2(oacc[mt][nt][0], oacc[mt][nt][1]);
            *(float2*)&ctxw[(size_t)(b * LQd + r + 8) * Dd + c] =
                make_float2(oacc[mt][nt][2], oacc[mt][nt][3]);
        }
}

// ---------------- host ----------------
extern "C" void kernel_launch(void* const* d_in, const int* in_sizes, int n_in,
                              void* d_out, int out_size)
{
    const float* q      = (const float*)d_in[0];
    const float* k_s    = (const float*)d_in[1];
    const float* v_s    = (const float*)d_in[2];
    const float* k_w    = (const float*)d_in[3];
    const float* v_w    = (const float*)d_in[4];
    const float* bias_w = (const float*)d_in[5];
    const float* bias_s = (const float*)d_in[6];
    const float* gab    = (const float*)d_in[7];

    const float *wq_s, *bq_s, *wk_s, *bk_s, *wv_s, *bv_s;
    const float *wq_w, *bq_w, *wk_w, *bk_w, *wv_w, *bv_w;
    const float *fcs_w, *fcs_b, *fcw_w, *fcw_b, *fco_w, *fco_b;

    if (in_sizes[9] == 512) {
        wq_s = (const float*)d_in[8];  bq_s = (const float*)d_in[9];
        wk_s = (const float*)d_in[10]; bk_s = (const float*)d_in[11];
        wv_s = (const float*)d_in[12]; bv_s = (const float*)d_in[13];
        wq_w = (const float*)d_in[14]; bq_w = (const float*)d_in[15];
        wk_w = (const float*)d_in[16]; bk_w = (const float*)d_in[17];
        wv_w = (const float*)d_in[18]; bv_w = (const float*)d_in[19];
        fcs_w = (const float*)d_in[20]; fcs_b = (const float*)d_in[21];
        fcw_w = (const float*)d_in[22]; fcw_b = (const float*)d_in[23];
        fco_w = (const float*)d_in[24]; fco_b = (const float*)d_in[25];
    } else {
        wq_s = (const float*)d_in[8];  wk_s = (const float*)d_in[9];
        wv_s = (const float*)d_in[10]; wq_w = (const float*)d_in[11];
        wk_w = (const float*)d_in[12]; wv_w = (const float*)d_in[13];
        fcs_w = (const float*)d_in[14]; fcw_w = (const float*)d_in[15];
        bq_s = (const float*)d_in[16]; bk_s = (const float*)d_in[17];
        bv_s = (const float*)d_in[18]; bq_w = (const float*)d_in[19];
        bk_w = (const float*)d_in[20]; bv_w = (const float*)d_in[21];
        fcs_b = (const float*)d_in[22]; fcw_b = (const float*)d_in[23];
        fco_w = (const float*)d_in[24]; fco_b = (const float*)d_in[25];
    }

    float* scratch = nullptr;
    cudaGetSymbolAddress((void**)&scratch, g_scratch);
    float* s_qs   = scratch + OFF_QS;
    float* s_qw   = scratch + OFF_QW;
    float* s_ks   = scratch + OFF_KS;
    float* s_vs   = scratch + OFF_VS;
    float* s_kw   = scratch + OFF_KW;
    float* s_vw   = scratch + OFF_VW;
    float* s_att  = scratch + OFF_ATT;
    float* s_ctxs = scratch + OFF_CTXS;
    float* s_ctxw = scratch + OFF_CTXW;
    float* s_cat  = scratch + OFF_CAT;
    float* wh     = scratch + OFF_WH;
    float* wl     = scratch + OFF_WL;
    float* ah     = scratch + OFF_AH;
    float* al     = scratch + OFF_AL;

    cudaFuncSetAttribute(gemm_presplit, cudaFuncAttributeMaxDynamicSharedMemorySize, PSMEM_BYTES);
    cudaFuncSetAttribute(gemm_tc2, cudaFuncAttributeMaxDynamicSharedMemorySize, GSMEM_BYTES);
    cudaFuncSetAttribute(word_attn64, cudaFuncAttributeMaxDynamicSharedMemorySize,
                         WSMEM_WORDS * (int)sizeof(float));

    // prep: split 9 weights + 5 activations
    PrepArgs2 pa;
    const float* wsrc[9] = {wq_s, wk_s, wv_s, wq_w, wk_w, wv_w, fcs_w, fcw_w, fco_w};
    for (int i = 0; i < 9; i++) {
        pa.src[i]  = wsrc[i];
        pa.dsth[i] = wh + WOFF(i);
        pa.dstl[i] = wl + WOFF(i);
        pa.n[i]    = (i < 8) ? 262144 : 524288;
    }
    const float* asrc[5] = {q, k_s, v_s, k_w, v_w};
    const int aoff[5] = {AQ, AKS, AVS, AKW, AVW};
    const int alen[5] = {524288, 49152, 49152, 6291456, 6291456};
    for (int i = 0; i < 5; i++) {
        pa.src[9 + i]  = asrc[i];
        pa.dsth[9 + i] = ah + aoff[i];
        pa.dstl[9 + i] = al + aoff[i];
        pa.n[9 + i]    = alen[i];
    }
    prep_split2<<<dim3(256, 14), 256>>>(pa);

    #define WHp(i) (wh + WOFF(i))
    #define WLp(i) (wl + WOFF(i))

    dim3 blk(512);

    // q projections (A = split q)
    gemm_presplit<<<dim3(4, 8, 2), blk, PSMEM_BYTES>>>(
        ah + AQ, al + AQ, ah + AQ, al + AQ,
        WHp(0), WLp(0), WHp(3), WLp(3), bq_s, bq_w, s_qs, s_qw,
        1024, 512, 512, 512, 512, 512);
    // sentence k/v projections
    gemm_presplit<<<dim3(4, 1, 2), blk, PSMEM_BYTES>>>(
        ah + AKS, al + AKS, ah + AVS, al + AVS,
        WHp(1), WLp(1), WHp(2), WLp(2), bk_s, bv_s, s_ks, s_vs,
        96, 512, 512, 512, 512, 512);
    // word k/v projections (big)
    gemm_presplit<<<dim3(4, 96, 2), blk, PSMEM_BYTES>>>(
        ah + AKW, al + AKW, ah + AVW, al + AVW,
        WHp(4), WLp(4), WHp(5), WLp(5), bk_w, bv_w, s_kw, s_vw,
        12288, 512, 512, 512, 512, 512);

    sent_attn<<<dim3(Hd, BB), 256>>>(s_qs, s_ks, s_vs, bias_s, gab, s_att, s_ctxs);

    word_attn64<<<dim3(LQd / 64, Hd, BB), 256, WSMEM_WORDS * sizeof(float)>>>(
        s_qw, s_kw, s_vw, bias_w, s_att, s_ctxw);

    // fcs / fcw into cat (inline-split A)
    gemm_tc2<<<dim3(4, 8, 2), blk, GSMEM_BYTES>>>(
        s_ctxs, s_ctxw, WHp(6), WLp(6), WHp(7), WLp(7), fcs_b, fcw_b,
        s_cat, s_cat + 512,
        1024, 512, 512, 512, 512, 1024);
    // final fco
    gemm_tc2<<<dim3(4, 8, 1), blk, GSMEM_BYTES>>>(
        s_cat, s_cat, WHp(8), WLp(8), WHp(8), WLp(8), fco_b, fco_b,
        (float*)d_out, (float*)d_out,
        1024, 512, 1024, 1024, 512, 512);
}

// round 6
// speedup vs baseline: 1.2286x; 1.2286x over previous
#include <cuda_runtime.h>
#include <cuda_fp16.h>
#include <math.h>
#include <stdint.h>

// Problem constants
#define BB   4
#define LQd  256
#define NSd  24
#define NTd  128
#define Dd   512
#define Hd   8
#define DKd  64

// ---------------- scratch (floats) ----------------
#define OFF_QS    0
#define OFF_QW    524288
#define OFF_KS    1048576
#define OFF_VS    1097728
#define OFF_KW    1146880
#define OFF_VW    7438336
#define OFF_ATT   13729792
#define OFF_ACTH  13926400
#define OFF_ACTL  20529152
#define OFF_WTH   27131904
#define OFF_WTL   28442624
#define OFF_CTXSH 29753344
#define OFF_CTXSL 30015488
#define OFF_CTXWH 30277632
#define OFF_CTXWL 30539776
#define OFF_CATH  30801920
#define OFF_CATL  31326208
#define SCRATCH_TOTAL 31850496
__device__ float g_scratch[SCRATCH_TOTAL];

// half-offsets inside ACT buffers
#define AQ   0
#define AKS  524288
#define AVS  573440
#define AKW  622592
#define AVW  6914048
// half-offsets inside WT buffers (transposed [N][K]); fco at 8 has 524288
#define WOFF(i) ((i) * 262144)

// ---------------- helpers ----------------
__device__ __forceinline__ void split_h(float x, __half& hi, __half& lo) {
    hi = __float2half_rn(x);
    lo = __float2half_rn(x - __half2float(hi));
}
__device__ __forceinline__ uint32_t pack_h2(__half a, __half b) {
    return (uint32_t)__half_as_ushort(a) | ((uint32_t)__half_as_ushort(b) << 16);
}
__device__ __forceinline__ void mma_f16(float d[4],
                                        uint32_t a0, uint32_t a1, uint32_t a2, uint32_t a3,
                                        uint32_t b0, uint32_t b1) {
    asm volatile(
        "mma.sync.aligned.m16n8k16.row.col.f32.f16.f16.f32 "
        "{%0,%1,%2,%3},{%4,%5,%6,%7},{%8,%9},{%0,%1,%2,%3};"
        : "+f"(d[0]), "+f"(d[1]), "+f"(d[2]), "+f"(d[3])
        : "r"(a0), "r"(a1), "r"(a2), "r"(a3), "r"(b0), "r"(b1));
}
__device__ __forceinline__ void cp_async16(uint32_t smem_addr, const void* gptr, int src_bytes) {
    asm volatile("cp.async.cg.shared.global [%0], [%1], 16, %2;"
                 :: "r"(smem_addr), "l"(gptr), "r"(src_bytes) : "memory");
}
__device__ __forceinline__ void cp_commit() { asm volatile("cp.async.commit_group;" ::: "memory"); }
template <int N>
__device__ __forceinline__ void cp_wait() { asm volatile("cp.async.wait_group %0;" :: "n"(N) : "memory"); }

// ---------------- prep: split activations to half hi/lo ----------------
struct ASplitArgs { const float* src[5]; };
__constant__ int c_alen[5] = {524288, 49152, 49152, 6291456, 6291456};
__constant__ int c_aoff[5] = {AQ, AKS, AVS, AKW, AVW};

__global__ __launch_bounds__(256) void act_split(ASplitArgs args, __half* acth, __half* actl)
{
    int z = blockIdx.y;
    int n = c_alen[z];
    const float* s = args.src[z];
    __half* dh = acth + c_aoff[z];
    __half* dl = actl + c_aoff[z];
    for (int i = blockIdx.x * 256 + threadIdx.x; i < n; i += gridDim.x * 256) {
        __half hi, lo;
        split_h(s[i], hi, lo);
        dh[i] = hi;
        dl[i] = lo;
    }
}

// ---------------- prep: transpose+split weights [K][512] -> [512][K] half ----------------
struct WSplitArgs { const float* src[9]; };
__constant__ int c_wK[9] = {512, 512, 512, 512, 512, 512, 512, 512, 1024};
__constant__ int c_woff[9] = {WOFF(0), WOFF(1), WOFF(2), WOFF(3), WOFF(4),
                              WOFF(5), WOFF(6), WOFF(7), WOFF(8)};

__global__ void w_transplit(WSplitArgs args, __half* wth, __half* wtl)
{
    int z = blockIdx.z;
    int Kw = c_wK[z];
    int k0 = blockIdx.y * 32;
    if (k0 >= Kw) return;
    int n0 = blockIdx.x * 32;
    const float* W = args.src[z];
    __half* th = wth + c_woff[z];
    __half* tl = wtl + c_woff[z];

    __shared__ float ts[32][33];
    int tx = threadIdx.x, ty = threadIdx.y;
    #pragma unroll
    for (int r = 0; r < 4; r++)
        ts[ty + 8 * r][tx] = W[(size_t)(k0 + ty + 8 * r) * 512 + n0 + tx];
    __syncthreads();
    #pragma unroll
    for (int r = 0; r < 4; r++) {
        int n = n0 + ty + 8 * r;
        int k = k0 + tx;
        __half hi, lo;
        split_h(ts[tx][ty + 8 * r], hi, lo);
        th[(size_t)n * Kw + k] = hi;
        tl[(size_t)n * Kw + k] = lo;
    }
}

// ---------------- split-FP16 GEMM ----------------
// C[M,N] = A[M,K] @ W[K,N] (+bias), W pre-transposed as BT[N][K] half hi/lo.
// 128x128 tile, BK=32, 512 threads (16 warps 4x4, warp tile 32x32), double buffer.
#define HAS 40                        // half stride of A/B smem rows (32 + 8 pad)
#define HSTAGE (4 * 128 * HAS)        // 20480 halves per stage (Ah,Al,Bh,Bl)
#define HSMEM_BYTES (2 * HSTAGE * 2)  // 81920 B

__global__ __launch_bounds__(512) void gemm_h(
    const __half* __restrict__ Ah0, const __half* __restrict__ Al0,
    const __half* __restrict__ Ah1, const __half* __restrict__ Al1,
    const __half* __restrict__ Bh0, const __half* __restrict__ Bl0,
    const __half* __restrict__ Bh1, const __half* __restrict__ Bl1,
    const float* __restrict__ bias0, const float* __restrict__ bias1,
    float* __restrict__ Cf0, float* __restrict__ Cf1,
    __half* __restrict__ Ch0, __half* __restrict__ Cl0,
    __half* __restrict__ Ch1, __half* __restrict__ Cl1,
    int M, int K, int lda, int ldc, int mode)
{
    extern __shared__ __half hsm[];

    const int z = blockIdx.z;
    const __half* Ah_g = z ? Ah1 : Ah0;
    const __half* Al_g = z ? Al1 : Al0;
    const __half* Bh_g = z ? Bh1 : Bh0;
    const __half* Bl_g = z ? Bl1 : Bl0;
    const float* bias  = z ? bias1 : bias0;
    float* Cf          = z ? Cf1 : Cf0;
    __half* Ch         = z ? Ch1 : Ch0;
    __half* Cl         = z ? Cl1 : Cl0;

    const int tid = threadIdx.x;
    const int wid = tid >> 5;
    const int lane = tid & 31;
    const int g = lane >> 2;
    const int t = lane & 3;
    const int wm = wid & 3;
    const int wn = wid >> 2;
    const int row0 = blockIdx.y * 128;
    const int col0 = blockIdx.x * 128;

    float dm[2][4][4], dc[2][4][4];
    #pragma unroll
    for (int mt = 0; mt < 2; mt++)
        #pragma unroll
        for (int nt = 0; nt < 4; nt++)
            #pragma unroll
            for (int j = 0; j < 4; j++) { dm[mt][nt][j] = 0.f; dc[mt][nt][j] = 0.f; }

    const int ktiles = K >> 5;
    const int lrow = tid >> 2;        // 0..127
    const int lch  = tid & 3;         // 0..3 (16B = 8-half chunks)

    // stage fill
    {
        __half* Ahs = hsm;
        __half* Als = Ahs + 128 * HAS;
        __half* Bhs = Als + 128 * HAS;
        __half* Bls = Bhs + 128 * HAS;
        int r = row0 + lrow;
        int rc = r < M ? r : (M - 1);
        int pb = r < M ? 16 : 0;
        cp_async16((uint32_t)__cvta_generic_to_shared(&Ahs[lrow * HAS + lch * 8]),
                   &Ah_g[(size_t)rc * lda + lch * 8], pb);
        cp_async16((uint32_t)__cvta_generic_to_shared(&Als[lrow * HAS + lch * 8]),
                   &Al_g[(size_t)rc * lda + lch * 8], pb);
        cp_async16((uint32_t)__cvta_generic_to_shared(&Bhs[lrow * HAS + lch * 8]),
                   &Bh_g[(size_t)(col0 + lrow) * K + lch * 8], 16);
        cp_async16((uint32_t)__cvta_generic_to_shared(&Bls[lrow * HAS + lch * 8]),
                   &Bl_g[(size_t)(col0 + lrow) * K + lch * 8], 16);
        cp_commit();
    }

    for (int kt = 0; kt < ktiles; kt++) {
        if (kt + 1 < ktiles) {
            __half* Ahs = hsm + ((kt + 1) & 1) * HSTAGE;
            __half* Als = Ahs + 128 * HAS;
            __half* Bhs = Als + 128 * HAS;
            __half* Bls = Bhs + 128 * HAS;
            int k0 = (kt + 1) << 5;
            int r = row0 + lrow;
            int rc = r < M ? r : (M - 1);
            int pb = r < M ? 16 : 0;
            cp_async16((uint32_t)__cvta_generic_to_shared(&Ahs[lrow * HAS + lch * 8]),
                       &Ah_g[(size_t)rc * lda + k0 + lch * 8], pb);
            cp_async16((uint32_t)__cvta_generic_to_shared(&Als[lrow * HAS + lch * 8]),
                       &Al_g[(size_t)rc * lda + k0 + lch * 8], pb);
            cp_async16((uint32_t)__cvta_generic_to_shared(&Bhs[lrow * HAS + lch * 8]),
                       &Bh_g[(size_t)(col0 + lrow) * K + k0 + lch * 8], 16);
            cp_async16((uint32_t)__cvta_generic_to_shared(&Bls[lrow * HAS + lch * 8]),
                       &Bl_g[(size_t)(col0 + lrow) * K + k0 + lch * 8], 16);
            cp_commit();
            cp_wait<1>();
        } else {
            cp_wait<0>();
        }
        __syncthreads();

        const __half* Ahs = hsm + (kt & 1) * HSTAGE;
        const __half* Als = Ahs + 128 * HAS;
        const __half* Bhs = Als + 128 * HAS;
        const __half* Bls = Bhs + 128 * HAS;

        #pragma unroll
        for (int ks = 0; ks < 2; ks++) {
            const int kb = ks * 16;
            uint32_t ah[2][4], al[2][4];
            #pragma unroll
            for (int mt = 0; mt < 2; mt++) {
                int r0 = wm * 32 + mt * 16 + g;
                ah[mt][0] = *(const uint32_t*)&Ahs[r0 * HAS + kb + 2 * t];
                ah[mt][1] = *(const uint32_t*)&Ahs[(r0 + 8) * HAS + kb + 2 * t];
                ah[mt][2] = *(const uint32_t*)&Ahs[r0 * HAS + kb + 2 * t + 8];
                ah[mt][3] = *(const uint32_t*)&Ahs[(r0 + 8) * HAS + kb + 2 * t + 8];
                al[mt][0] = *(const uint32_t*)&Als[r0 * HAS + kb + 2 * t];
                al[mt][1] = *(const uint32_t*)&Als[(r0 + 8) * HAS + kb + 2 * t];
                al[mt][2] = *(const uint32_t*)&Als[r0 * HAS + kb + 2 * t + 8];
                al[mt][3] = *(const uint32_t*)&Als[(r0 + 8) * HAS + kb + 2 * t + 8];
            }
            #pragma unroll
            for (int nt = 0; nt < 4; nt++) {
                int c = wn * 32 + nt * 8 + g;
                uint32_t bh0 = *(const uint32_t*)&Bhs[c * HAS + kb + 2 * t];
                uint32_t bh1 = *(const uint32_t*)&Bhs[c * HAS + kb + 2 * t + 8];
                uint32_t bl0 = *(const uint32_t*)&Bls[c * HAS + kb + 2 * t];
                uint32_t bl1 = *(const uint32_t*)&Bls[c * HAS + kb + 2 * t + 8];
                #pragma unroll
                for (int mt = 0; mt < 2; mt++) {
                    mma_f16(dm[mt][nt], ah[mt][0], ah[mt][1], ah[mt][2], ah[mt][3], bh0, bh1);
                    mma_f16(dc[mt][nt], ah[mt][0], ah[mt][1], ah[mt][2], ah[mt][3], bl0, bl1);
                    mma_f16(dc[mt][nt], al[mt][0], al[mt][1], al[mt][2], al[mt][3], bh0, bh1);
                }
            }
        }
        __syncthreads();
    }

    #pragma unroll
    for (int mt = 0; mt < 2; mt++) {
        #pragma unroll
        for (int nt = 0; nt < 4; nt++) {
            int r = row0 + wm * 32 + mt * 16 + g;
            int c = col0 + wn * 32 + nt * 8 + 2 * t;
            float2 bz = *(const float2*)&bias[c];
            float o0 = dm[mt][nt][0] + dc[mt][nt][0] + bz.x;
            float o1 = dm[mt][nt][1] + dc[mt][nt][1] + bz.y;
            float o2 = dm[mt][nt][2] + dc[mt][nt][2] + bz.x;
            float o3 = dm[mt][nt][3] + dc[mt][nt][3] + bz.y;
            if (mode == 0) {
                if (r < M)     *(float2*)&Cf[(size_t)r * ldc + c] = make_float2(o0, o1);
                if (r + 8 < M) *(float2*)&Cf[(size_t)(r + 8) * ldc + c] = make_float2(o2, o3);
            } else {
                __half h0, l0, h1, l1;
                if (r < M) {
                    split_h(o0, h0, l0); split_h(o1, h1, l1);
                    *(__half2*)&Ch[(size_t)r * ldc + c] = __halves2half2(h0, h1);
                    *(__half2*)&Cl[(size_t)r * ldc + c] = __halves2half2(l0, l1);
                }
                if (r + 8 < M) {
                    split_h(o2, h0, l0); split_h(o3, h1, l1);
                    *(__half2*)&Ch[(size_t)(r + 8) * ldc + c] = __halves2half2(h0, h1);
                    *(__half2*)&Cl[(size_t)(r + 8) * ldc + c] = __halves2half2(l0, l1);
                }
            }
        }
    }
}

// ---------------- sentence-level graph attention ----------------
__global__ __launch_bounds__(256) void sent_attn(
    const float* __restrict__ qs, const float* __restrict__ ksn,
    const float* __restrict__ vsn, const float* __restrict__ bias_s,
    const float* __restrict__ gab,
    float* __restrict__ attns_out,
    __half* __restrict__ csh, __half* __restrict__ csl)
{
    const int h = blockIdx.x, b = blockIdx.y;
    const int q = threadIdx.x;

    __shared__ float Ks[NSd][DKd + 1];
    __shared__ float Vs[NSd][DKd + 1];
    __shared__ float G[NSd][NSd + 1];

    for (int idx = q; idx < NSd * DKd; idx += 256) {
        int s = idx >> 6, k = idx & 63;
        Ks[s][k] = ksn[(size_t)(b * NSd + s) * Dd + h * DKd + k];
        Vs[s][k] = vsn[(size_t)(b * NSd + s) * Dd + h * DKd + k];
    }
    for (int idx = q; idx < NSd * NSd; idx += 256) {
        int s = idx / NSd, tt = idx % NSd;
        G[s][tt] = gab[((size_t)(b * Hd + h) * NSd + s) * NSd + tt];
    }
    __syncthreads();

    float qreg[DKd];
    const float* qrow = qs + (size_t)(b * LQd + q) * Dd + h * DKd;
    #pragma unroll
    for (int k = 0; k < DKd; k++) qreg[k] = qrow[k] * 0.125f;

    float a[NSd];
    const float* bsrow = bias_s + ((size_t)(b * Hd + h) * LQd + q) * NSd;
    #pragma unroll
    for (int s = 0; s < NSd; s++) {
        float dd = 0.f;
        #pragma unroll
        for (int k = 0; k < DKd; k++) dd += qreg[k] * Ks[s][k];
        a[s] = dd + bsrow[s];
    }

    float m = -1e30f;
    #pragma unroll
    for (int s = 0; s < NSd; s++) m = fmaxf(m, a[s]);
    float smx[NSd]; float sum = 0.f;
    #pragma unroll
    for (int s = 0; s < NSd; s++) { smx[s] = __expf(a[s] - m); sum += smx[s]; }
    float inv = 1.f / sum;

    float gg[NSd];
    #pragma unroll
    for (int tt = 0; tt < NSd; tt++) {
        float dd = 0.f;
        #pragma unroll
        for (int s = 0; s < NSd; s++) dd += smx[s] * G[s][tt];
        gg[tt] = dd * inv;
    }
    #pragma unroll
    for (int s = 0; s < NSd; s++) a[s] -= 0.5f * gg[s] * gg[s];

    m = -1e30f;
    #pragma unroll
    for (int s = 0; s < NSd; s++) m = fmaxf(m, a[s]);
    sum = 0.f;
    #pragma unroll
    for (int s = 0; s < NSd; s++) { a[s] = __expf(a[s] - m); sum += a[s]; }
    inv = 1.f / sum;

    float* arow = attns_out + ((size_t)(b * Hd + h) * LQd + q) * NSd;
    #pragma unroll
    for (int s = 0; s < NSd; s++) { a[s] *= inv; arow[s] = a[s]; }

    size_t cbase = (size_t)(b * LQd + q) * Dd + h * DKd;
    #pragma unroll
    for (int dd = 0; dd < DKd; dd++) {
        float acc = 0.f;
        #pragma unroll
        for (int s = 0; s < NSd; s++) acc += a[s] * Vs[s][dd];
        __half hi, lo;
        split_h(acc, hi, lo);
        csh[cbase + dd] = hi;
        csl[cbase + dd] = lo;
    }
}

// ---------------- word-level attention (split-FP16) ----------------
// grid (8, 8, 4), 256 threads (8 warps). QK warp tile 16x32, PV 16x16.
// smem halves: QH[32][72] QL | KH[128][72] KL | VH[128][72] VL | PH[32][136] PL
// + PsF fp32 [32][132]
#define HQS 72
#define HPS 136
#define O_QH 0
#define O_QL (32 * HQS)
#define O_KH (2 * 32 * HQS)
#define O_KL (O_KH + 128 * HQS)
#define O_VH (O_KL + 128 * HQS)
#define O_VL (O_VH + 128 * HQS)
#define O_PH (O_VL + 128 * HQS)
#define O_PL (O_PH + 32 * HPS)
#define O_PSF (O_PL + 32 * HPS)          // halves offset; fp32 region starts here
#define WPPAD 132
#define WSMEM_BYTES (O_PSF * 2 + 32 * WPPAD * 4)   // 100352 + 16896 = 117248

__global__ __launch_bounds__(256) void word_attn_h(
    const float* __restrict__ qw, const float* __restrict__ kw,
    const float* __restrict__ vw, const float* __restrict__ bias_w,
    const float* __restrict__ attns,
    __half* __restrict__ cwh, __half* __restrict__ cwl)
{
    extern __shared__ __half hsm[];
    __half* QH = hsm + O_QH;
    __half* QL = hsm + O_QL;
    __half* KH = hsm + O_KH;
    __half* KL = hsm + O_KL;
    __half* VH = hsm + O_VH;
    __half* VL = hsm + O_VL;
    __half* PH = hsm + O_PH;
    __half* PL = hsm + O_PL;
    float* Ps  = (float*)(hsm + O_PSF);

    const int tid = threadIdx.x;
    const int wid = tid >> 5;
    const int lane = tid & 31;
    const int g = lane >> 2;
    const int t = lane & 3;
    const int wm = wid & 1;
    const int wn = wid >> 1;
    const int q0 = blockIdx.x * 32;
    const int h  = blockIdx.y;
    const int b  = blockIdx.z;

    // load + split Q (scaled)
    #pragma unroll
    for (int i = 0; i < 2; i++) {
        int id = tid + 256 * i;
        int qr = id >> 4, qc = id & 15;
        float4 v = *(const float4*)(qw + (size_t)(b * LQd + q0 + qr) * Dd + h * DKd + qc * 4);
        float vv[4] = {v.x * 0.125f, v.y * 0.125f, v.z * 0.125f, v.w * 0.125f};
        __half hi[4], lo[4];
        #pragma unroll
        for (int j = 0; j < 4; j++) split_h(vv[j], hi[j], lo[j]);
        __half2* dh = (__half2*)&QH[qr * HQS + qc * 4];
        dh[0] = __halves2half2(hi[0], hi[1]);
        dh[1] = __halves2half2(hi[2], hi[3]);
        __half2* dl = (__half2*)&QL[qr * HQS + qc * 4];
        dl[0] = __halves2half2(lo[0], lo[1]);
        dl[1] = __halves2half2(lo[2], lo[3]);
    }

    float om[2][4], oc[2][4];
    #pragma unroll
    for (int nt = 0; nt < 2; nt++)
        #pragma unroll
        for (int j = 0; j < 4; j++) { om[nt][j] = 0.f; oc[nt][j] = 0.f; }

    for (int s = 0; s < NSd; s++) {
        __syncthreads();
        const float* kb_p = kw + (size_t)(b * NSd + s) * NTd * Dd + h * DKd;
        const float* vb_p = vw + (size_t)(b * NSd + s) * NTd * Dd + h * DKd;
        #pragma unroll
        for (int i = 0; i < 8; i++) {
            int id = tid + 256 * i;
            int kr = id >> 4, kc = id & 15;
            float4 kv = *(const float4*)(kb_p + (size_t)kr * Dd + kc * 4);
            __half hi[4], lo[4];
            split_h(kv.x, hi[0], lo[0]); split_h(kv.y, hi[1], lo[1]);
            split_h(kv.z, hi[2], lo[2]); split_h(kv.w, hi[3], lo[3]);
            __half2* dh = (__half2*)&KH[kr * HQS + kc * 4];
            dh[0] = __halves2half2(hi[0], hi[1]); dh[1] = __halves2half2(hi[2], hi[3]);
            __half2* dl = (__half2*)&KL[kr * HQS + kc * 4];
            dl[0] = __halves2half2(lo[0], lo[1]); dl[1] = __halves2half2(lo[2], lo[3]);
            float4 vv = *(const float4*)(vb_p + (size_t)kr * Dd + kc * 4);
            split_h(vv.x, hi[0], lo[0]); split_h(vv.y, hi[1], lo[1]);
            split_h(vv.z, hi[2], lo[2]); split_h(vv.w, hi[3], lo[3]);
            __half2* eh = (__half2*)&VH[kr * HQS + kc * 4];
            eh[0] = __halves2half2(hi[0], hi[1]); eh[1] = __halves2half2(hi[2], hi[3]);
            __half2* el = (__half2*)&VL[kr * HQS + kc * 4];
            el[0] = __halves2half2(lo[0], lo[1]); el[1] = __halves2half2(lo[2], lo[3]);
        }
        __syncthreads();

        // ---- P = Q @ K^T (warp tile 16x32), split-fp16 3-term ----
        float pm[4][4], pc[4][4];
        #pragma unroll
        for (int nt = 0; nt < 4; nt++)
            #pragma unroll
            for (int j = 0; j < 4; j++) { pm[nt][j] = 0.f; pc[nt][j] = 0.f; }

        #pragma unroll
        for (int ks = 0; ks < 4; ks++) {
            const int kb = ks * 16;
            int r0 = wm * 16 + g;
            uint32_t ah0 = *(const uint32_t*)&QH[r0 * HQS + kb + 2 * t];
            uint32_t ah1 = *(const uint32_t*)&QH[(r0 + 8) * HQS + kb + 2 * t];
            uint32_t ah2 = *(const uint32_t*)&QH[r0 * HQS + kb + 2 * t + 8];
            uint32_t ah3 = *(const uint32_t*)&QH[(r0 + 8) * HQS + kb + 2 * t + 8];
            uint32_t al0 = *(const uint32_t*)&QL[r0 * HQS + kb + 2 * t];
            uint32_t al1 = *(const uint32_t*)&QL[(r0 + 8) * HQS + kb + 2 * t];
            uint32_t al2 = *(const uint32_t*)&QL[r0 * HQS + kb + 2 * t + 8];
            uint32_t al3 = *(const uint32_t*)&QL[(r0 + 8) * HQS + kb + 2 * t + 8];
            #pragma unroll
            for (int nt = 0; nt < 4; nt++) {
                int c = wn * 32 + nt * 8 + g;
                uint32_t bh0 = *(const uint32_t*)&KH[c * HQS + kb + 2 * t];
                uint32_t bh1 = *(const uint32_t*)&KH[c * HQS + kb + 2 * t + 8];
                uint32_t bl0 = *(const uint32_t*)&KL[c * HQS + kb + 2 * t];
                uint32_t bl1 = *(const uint32_t*)&KL[c * HQS + kb + 2 * t + 8];
                mma_f16(pm[nt], ah0, ah1, ah2, ah3, bh0, bh1);
                mma_f16(pc[nt], ah0, ah1, ah2, ah3, bl0, bl1);
                mma_f16(pc[nt], al0, al1, al2, al3, bh0, bh1);
            }
        }
        #pragma unroll
        for (int nt = 0; nt < 4; nt++) {
            int r = wm * 16 + g;
            int c = wn * 32 + nt * 8 + 2 * t;
            *(float2*)&Ps[r * WPPAD + c] = make_float2(pm[nt][0] + pc[nt][0], pm[nt][1] + pc[nt][1]);
            *(float2*)&Ps[(r + 8) * WPPAD + c] = make_float2(pm[nt][2] + pc[nt][2], pm[nt][3] + pc[nt][3]);
        }
        __syncthreads();

        // ---- softmax + bias + attns scale; write split-fp16 P ----
        const float* bb = bias_w + ((size_t)((b * NSd + s) * Hd + h) * LQd + q0) * NTd;
        #pragma unroll
        for (int rr = 0; rr < 4; rr++) {
            int r = wid * 4 + rr;
            float x0 = Ps[r * WPPAD + lane]       + bb[r * NTd + lane];
            float x1 = Ps[r * WPPAD + lane + 32]  + bb[r * NTd + lane + 32];
            float x2 = Ps[r * WPPAD + lane + 64]  + bb[r * NTd + lane + 64];
            float x3 = Ps[r * WPPAD + lane + 96]  + bb[r * NTd + lane + 96];
            float mx = fmaxf(fmaxf(x0, x1), fmaxf(x2, x3));
            #pragma unroll
            for (int o = 16; o; o >>= 1) mx = fmaxf(mx, __shfl_xor_sync(0xffffffffu, mx, o));
            x0 = __expf(x0 - mx); x1 = __expf(x1 - mx);
            x2 = __expf(x2 - mx); x3 = __expf(x3 - mx);
            float su = x0 + x1 + x2 + x3;
            #pragma unroll
            for (int o = 16; o; o >>= 1) su += __shfl_xor_sync(0xffffffffu, su, o);
            float wsc = attns[((size_t)(b * Hd + h) * LQd + q0 + r) * NSd + s] / su;
            __half hi, lo;
            split_h(x0 * wsc, hi, lo); PH[r * HPS + lane] = hi;       PL[r * HPS + lane] = lo;
            split_h(x1 * wsc, hi, lo); PH[r * HPS + lane + 32] = hi;  PL[r * HPS + lane + 32] = lo;
            split_h(x2 * wsc, hi, lo); PH[r * HPS + lane + 64] = hi;  PL[r * HPS + lane + 64] = lo;
            split_h(x3 * wsc, hi, lo); PH[r * HPS + lane + 96] = hi;  PL[r * HPS + lane + 96] = lo;
        }
        __syncthreads();

        // ---- O += P @ V (warp tile 16x16) ----
        #pragma unroll
        for (int ks = 0; ks < 8; ks++) {
            const int kb = ks * 16;
            int r0 = wm * 16 + g;
            uint32_t ph0 = *(const uint32_t*)&PH[r0 * HPS + kb + 2 * t];
            uint32_t ph1 = *(const uint32_t*)&PH[(r0 + 8) * HPS + kb + 2 * t];
            uint32_t ph2 = *(const uint32_t*)&PH[r0 * HPS + kb + 2 * t + 8];
            uint32_t ph3 = *(const uint32_t*)&PH[(r0 + 8) * HPS + kb + 2 * t + 8];
            uint32_t pl0 = *(const uint32_t*)&PL[r0 * HPS + kb + 2 * t];
            uint32_t pl1 = *(const uint32_t*)&PL[(r0 + 8) * HPS + kb + 2 * t];
            uint32_t pl2 = *(const uint32_t*)&PL[r0 * HPS + kb + 2 * t + 8];
            uint32_t pl3 = *(const uint32_t*)&PL[(r0 + 8) * HPS + kb + 2 * t + 8];
            #pragma unroll
            for (int nt = 0; nt < 2; nt++) {
                int c = wn * 16 + nt * 8 + g;
                int k0r = kb + 2 * t;
                uint32_t bh0 = pack_h2(VH[k0r * HQS + c],        VH[(k0r + 1) * HQS + c]);
                uint32_t bh1 = pack_h2(VH[(k0r + 8) * HQS + c],  VH[(k0r + 9) * HQS + c]);
                uint32_t bl0 = pack_h2(VL[k0r * HQS + c],        VL[(k0r + 1) * HQS + c]);
                uint32_t bl1 = pack_h2(VL[(k0r + 8) * HQS + c],  VL[(k0r + 9) * HQS + c]);
                mma_f16(om[nt], ph0, ph1, ph2, ph3, bh0, bh1);
                mma_f16(oc[nt], ph0, ph1, ph2, ph3, bl0, bl1);
                mma_f16(oc[nt], pl0, pl1, pl2, pl3, bh0, bh1);
            }
        }
    }

    #pragma unroll
    for (int nt = 0; nt < 2; nt++) {
        int r = q0 + wm * 16 + g;
        int c = h * DKd + wn * 16 + nt * 8 + 2 * t;
        float v0 = om[nt][0] + oc[nt][0], v1 = om[nt][1] + oc[nt][1];
        float v2 = om[nt][2] + oc[nt][2], v3 = om[nt][3] + oc[nt][3];
        __half h0, l0, h1, l1;
        split_h(v0, h0, l0); split_h(v1, h1, l1);
        *(__half2*)&cwh[(size_t)(b * LQd + r) * Dd + c] = __halves2half2(h0, h1);
        *(__half2*)&cwl[(size_t)(b * LQd + r) * Dd + c] = __halves2half2(l0, l1);
        split_h(v2, h0, l0); split_h(v3, h1, l1);
        *(__half2*)&cwh[(size_t)(b * LQd + r + 8) * Dd + c] = __halves2half2(h0, h1);
        *(__half2*)&cwl[(size_t)(b * LQd + r + 8) * Dd + c] = __halves2half2(l0, l1);
    }
}

// ---------------- host ----------------
extern "C" void kernel_launch(void* const* d_in, const int* in_sizes, int n_in,
                              void* d_out, int out_size)
{
    const float* q      = (const float*)d_in[0];
    const float* k_s    = (const float*)d_in[1];
    const float* v_s    = (const float*)d_in[2];
    const float* k_w    = (const float*)d_in[3];
    const float* v_w    = (const float*)d_in[4];
    const float* bias_w = (const float*)d_in[5];
    const float* bias_s = (const float*)d_in[6];
    const float* gab    = (const float*)d_in[7];

    const float *wq_s, *bq_s, *wk_s, *bk_s, *wv_s, *bv_s;
    const float *wq_w, *bq_w, *wk_w, *bk_w, *wv_w, *bv_w;
    const float *fcs_w, *fcs_b, *fcw_w, *fcw_b, *fco_w, *fco_b;

    if (in_sizes[9] == 512) {
        wq_s = (const float*)d_in[8];  bq_s = (const float*)d_in[9];
        wk_s = (const float*)d_in[10]; bk_s = (const float*)d_in[11];
        wv_s = (const float*)d_in[12]; bv_s = (const float*)d_in[13];
        wq_w = (const float*)d_in[14]; bq_w = (const float*)d_in[15];
        wk_w = (const float*)d_in[16]; bk_w = (const float*)d_in[17];
        wv_w = (const float*)d_in[18]; bv_w = (const float*)d_in[19];
        fcs_w = (const float*)d_in[20]; fcs_b = (const float*)d_in[21];
        fcw_w = (const float*)d_in[22]; fcw_b = (const float*)d_in[23];
        fco_w = (const float*)d_in[24]; fco_b = (const float*)d_in[25];
    } else {
        wq_s = (const float*)d_in[8];  wk_s = (const float*)d_in[9];
        wv_s = (const float*)d_in[10]; wq_w = (const float*)d_in[11];
        wk_w = (const float*)d_in[12]; wv_w = (const float*)d_in[13];
        fcs_w = (const float*)d_in[14]; fcw_w = (const float*)d_in[15];
        bq_s = (const float*)d_in[16]; bk_s = (const float*)d_in[17];
        bv_s = (const float*)d_in[18]; bq_w = (const float*)d_in[19];
        bk_w = (const float*)d_in[20]; bv_w = (const float*)d_in[21];
        fcs_b = (const float*)d_in[22]; fcw_b = (const float*)d_in[23];
        fco_w = (const float*)d_in[24]; fco_b = (const float*)d_in[25];
    }

    float* scratch = nullptr;
    cudaGetSymbolAddress((void**)&scratch, g_scratch);
    float* s_qs  = scratch + OFF_QS;
    float* s_qw  = scratch + OFF_QW;
    float* s_ks  = scratch + OFF_KS;
    float* s_vs  = scratch + OFF_VS;
    float* s_kw  = scratch + OFF_KW;
    float* s_vw  = scratch + OFF_VW;
    float* s_att = scratch + OFF_ATT;
    __half* acth = (__half*)(scratch + OFF_ACTH);
    __half* actl = (__half*)(scratch + OFF_ACTL);
    __half* wth  = (__half*)(scratch + OFF_WTH);
    __half* wtl  = (__half*)(scratch + OFF_WTL);
    __half* csh  = (__half*)(scratch + OFF_CTXSH);
    __half* csl  = (__half*)(scratch + OFF_CTXSL);
    __half* cwh  = (__half*)(scratch + OFF_CTXWH);
    __half* cwl  = (__half*)(scratch + OFF_CTXWL);
    __half* cath = (__half*)(scratch + OFF_CATH);
    __half* catl = (__half*)(scratch + OFF_CATL);

    cudaFuncSetAttribute(gemm_h, cudaFuncAttributeMaxDynamicSharedMemorySize, HSMEM_BYTES);
    cudaFuncSetAttribute(word_attn_h, cudaFuncAttributeMaxDynamicSharedMemorySize, WSMEM_BYTES);

    // prep
    ASplitArgs aa;
    aa.src[0] = q; aa.src[1] = k_s; aa.src[2] = v_s; aa.src[3] = k_w; aa.src[4] = v_w;
    act_split<<<dim3(256, 5), 256>>>(aa, acth, actl);
    WSplitArgs wa;
    wa.src[0] = wq_s; wa.src[1] = wk_s; wa.src[2] = wv_s;
    wa.src[3] = wq_w; wa.src[4] = wk_w; wa.src[5] = wv_w;
    wa.src[6] = fcs_w; wa.src[7] = fcw_w; wa.src[8] = fco_w;
    w_transplit<<<dim3(16, 32, 9), dim3(32, 8)>>>(wa, wth, wtl);

    #define WTH_(i) (wth + WOFF(i))
    #define WTL_(i) (wtl + WOFF(i))

    dim3 blk(512);

    // q projections -> fp32 qs/qw
    gemm_h<<<dim3(4, 8, 2), blk, HSMEM_BYTES>>>(
        acth + AQ, actl + AQ, acth + AQ, actl + AQ,
        WTH_(0), WTL_(0), WTH_(3), WTL_(3), bq_s, bq_w,
        s_qs, s_qw, nullptr, nullptr, nullptr, nullptr,
        1024, 512, 512, 512, 0);
    // sentence k/v projections -> fp32
    gemm_h<<<dim3(4, 1, 2), blk, HSMEM_BYTES>>>(
        acth + AKS, actl + AKS, acth + AVS, actl + AVS,
        WTH_(1), WTL_(1), WTH_(2), WTL_(2), bk_s, bv_s,
        s_ks, s_vs, nullptr, nullptr, nullptr, nullptr,
        96, 512, 512, 512, 0);
    // word k/v projections -> fp32
    gemm_h<<<dim3(4, 96, 2), blk, HSMEM_BYTES>>>(
        acth + AKW, actl + AKW, acth + AVW, actl + AVW,
        WTH_(4), WTL_(4), WTH_(5), WTL_(5), bk_w, bv_w,
        s_kw, s_vw, nullptr, nullptr, nullptr, nullptr,
        12288, 512, 512, 512, 0);

    sent_attn<<<dim3(Hd, BB), 256>>>(s_qs, s_ks, s_vs, bias_s, gab, s_att, csh, csl);

    word_attn_h<<<dim3(8, Hd, BB), 256, WSMEM_BYTES>>>(
        s_qw, s_kw, s_vw, bias_w, s_att, cwh, cwl);

    // fcs / fcw -> split cat (mode 1)
    gemm_h<<<dim3(4, 8, 2), blk, HSMEM_BYTES>>>(
        csh, csl, cwh, cwl,
        WTH_(6), WTL_(6), WTH_(7), WTL_(7), fcs_b, fcw_b,
        nullptr, nullptr, cath, catl, cath + 512, catl + 512,
        1024, 512, 512, 1024, 1);
    // final fco -> fp32 d_out
    gemm_h<<<dim3(4, 8, 1), blk, HSMEM_BYTES>>>(
        cath, catl, cath, catl,
        WTH_(8), WTL_(8), WTH_(8), WTL_(8), fco_b, fco_b,
        (float*)d_out, (float*)d_out, nullptr, nullptr, nullptr, nullptr,
        1024, 1024, 1024, 512, 0);
}

// round 7
// speedup vs baseline: 1.3133x; 1.0690x over previous
#include <cuda_runtime.h>
#include <cuda_fp16.h>
#include <math.h>
#include <stdint.h>

// Problem constants
#define BB   4
#define LQd  256
#define NSd  24
#define NTd  128
#define Dd   512
#define Hd   8
#define DKd  64

// ---------------- scratch layout ----------------
// fp32 region
#define OFF_QS   0
#define OFF_KS   524288
#define OFF_VS   573440
#define OFF_ATT  622592
#define OFF_HALF 819200
// half region offsets (units: halves), base = (half*)(scratch + OFF_HALF)
#define H_ACTH 0
#define H_ACTL 13205504
#define H_WTH  26411008
#define H_WTL  29032448
#define H_QWH  31653888
#define H_QWL  32178176
#define H_KWH  32702464
#define H_KWL  38993920
#define H_VWH  45285376
#define H_VWL  51576832
#define H_CSH  57868288
#define H_CSL  58392576
#define H_CWH  58916864
#define H_CWL  59441152
#define H_CATH 59965440
#define H_CATL 61014016
#define H_TOTAL 62062592
#define SCRATCH_TOTAL (OFF_HALF + H_TOTAL / 2)
__device__ float g_scratch[SCRATCH_TOTAL];

// act-split sub-offsets (halves)
#define AQ   0
#define AKS  524288
#define AVS  573440
#define AKW  622592
#define AVW  6914048
// weight sub-offsets (halves), transposed [N][K]
#define WOFF(i) ((i) * 262144)

// ---------------- helpers ----------------
__device__ __forceinline__ void split_h(float x, __half& hi, __half& lo) {
    hi = __float2half_rn(x);
    lo = __float2half_rn(x - __half2float(hi));
}
__device__ __forceinline__ uint32_t pack_h2(__half a, __half b) {
    return (uint32_t)__half_as_ushort(a) | ((uint32_t)__half_as_ushort(b) << 16);
}
__device__ __forceinline__ void mma_f16(float d[4],
                                        uint32_t a0, uint32_t a1, uint32_t a2, uint32_t a3,
                                        uint32_t b0, uint32_t b1) {
    asm volatile(
        "mma.sync.aligned.m16n8k16.row.col.f32.f16.f16.f32 "
        "{%0,%1,%2,%3},{%4,%5,%6,%7},{%8,%9},{%0,%1,%2,%3};"
        : "+f"(d[0]), "+f"(d[1]), "+f"(d[2]), "+f"(d[3])
        : "r"(a0), "r"(a1), "r"(a2), "r"(a3), "r"(b0), "r"(b1));
}
__device__ __forceinline__ void cp_async16(uint32_t smem_addr, const void* gptr, int src_bytes) {
    asm volatile("cp.async.cg.shared.global [%0], [%1], 16, %2;"
                 :: "r"(smem_addr), "l"(gptr), "r"(src_bytes) : "memory");
}
__device__ __forceinline__ void cp_commit() { asm volatile("cp.async.commit_group;" ::: "memory"); }
template <int N>
__device__ __forceinline__ void cp_wait() { asm volatile("cp.async.wait_group %0;" :: "n"(N) : "memory"); }

// ---------------- prep: split activations ----------------
struct ASplitArgs { const float* src[5]; };
__constant__ int c_alen[5] = {524288, 49152, 49152, 6291456, 6291456};
__constant__ int c_aoff[5] = {AQ, AKS, AVS, AKW, AVW};

__global__ __launch_bounds__(256) void act_split(ASplitArgs args, __half* acth, __half* actl)
{
    int z = blockIdx.y;
    int n = c_alen[z];
    const float* s = args.src[z];
    __half* dh = acth + c_aoff[z];
    __half* dl = actl + c_aoff[z];
    for (int i = blockIdx.x * 256 + threadIdx.x; i < n; i += gridDim.x * 256) {
        __half hi, lo;
        split_h(s[i], hi, lo);
        dh[i] = hi;
        dl[i] = lo;
    }
}

// ---------------- prep: transpose+split weights (with optional scale) ----------------
struct WSplitArgs { const float* src[9]; };
__constant__ int c_wK[9] = {512, 512, 512, 512, 512, 512, 512, 512, 1024};
__constant__ int c_woff[9] = {WOFF(0), WOFF(1), WOFF(2), WOFF(3), WOFF(4),
                              WOFF(5), WOFF(6), WOFF(7), WOFF(8)};
__constant__ float c_wscale[9] = {1.f, 1.f, 1.f, 0.125f, 1.f, 1.f, 1.f, 1.f, 1.f};

__global__ void w_transplit(WSplitArgs args, __half* wth, __half* wtl)
{
    int z = blockIdx.z;
    int Kw = c_wK[z];
    int k0 = blockIdx.y * 32;
    if (k0 >= Kw) return;
    int n0 = blockIdx.x * 32;
    const float* W = args.src[z];
    float sc = c_wscale[z];
    __half* th = wth + c_woff[z];
    __half* tl = wtl + c_woff[z];

    __shared__ float ts[32][33];
    int tx = threadIdx.x, ty = threadIdx.y;
    #pragma unroll
    for (int r = 0; r < 4; r++)
        ts[ty + 8 * r][tx] = W[(size_t)(k0 + ty + 8 * r) * 512 + n0 + tx];
    __syncthreads();
    #pragma unroll
    for (int r = 0; r < 4; r++) {
        int n = n0 + ty + 8 * r;
        int k = k0 + tx;
        __half hi, lo;
        split_h(sc * ts[tx][ty + 8 * r], hi, lo);
        th[(size_t)n * Kw + k] = hi;
        tl[(size_t)n * Kw + k] = lo;
    }
}

// ---------------- split-FP16 GEMM with per-z config ----------------
#define HAS 40
#define HSTAGE (4 * 128 * HAS)
#define HSMEM_BYTES (2 * HSTAGE * 2)

struct GemmCfg {
    const __half* Ah[4]; const __half* Al[4];
    const __half* Bh[4]; const __half* Bl[4];
    const float* bias[4];
    float* Cf[4];
    __half* Ch[4]; __half* Cl[4];
    int M[4]; int mode[4]; float bscale[4];
    int K; int ldc;
};

__global__ __launch_bounds__(512) void gemm_cfg(GemmCfg cfg)
{
    extern __shared__ __half hsm[];

    const int z = blockIdx.z;
    const int M = cfg.M[z];
    const int row0 = blockIdx.y * 128;
    if (row0 >= M) return;

    const __half* Ah_g = cfg.Ah[z];
    const __half* Al_g = cfg.Al[z];
    const __half* Bh_g = cfg.Bh[z];
    const __half* Bl_g = cfg.Bl[z];
    const float* bias  = cfg.bias[z];
    const int mode     = cfg.mode[z];
    const float bsc    = cfg.bscale[z];
    const int K        = cfg.K;
    const int ldc      = cfg.ldc;

    const int tid = threadIdx.x;
    const int wid = tid >> 5;
    const int lane = tid & 31;
    const int g = lane >> 2;
    const int t = lane & 3;
    const int wm = wid & 3;
    const int wn = wid >> 2;
    const int col0 = blockIdx.x * 128;

    float dm[2][4][4], dc[2][4][4];
    #pragma unroll
    for (int mt = 0; mt < 2; mt++)
        #pragma unroll
        for (int nt = 0; nt < 4; nt++)
            #pragma unroll
            for (int j = 0; j < 4; j++) { dm[mt][nt][j] = 0.f; dc[mt][nt][j] = 0.f; }

    const int ktiles = K >> 5;
    const int lrow = tid >> 2;
    const int lch  = tid & 3;

    {
        __half* Ahs = hsm;
        __half* Als = Ahs + 128 * HAS;
        __half* Bhs = Als + 128 * HAS;
        __half* Bls = Bhs + 128 * HAS;
        int r = row0 + lrow;
        int rc = r < M ? r : (M - 1);
        int pb = r < M ? 16 : 0;
        cp_async16((uint32_t)__cvta_generic_to_shared(&Ahs[lrow * HAS + lch * 8]),
                   &Ah_g[(size_t)rc * K + lch * 8], pb);
        cp_async16((uint32_t)__cvta_generic_to_shared(&Als[lrow * HAS + lch * 8]),
                   &Al_g[(size_t)rc * K + lch * 8], pb);
        cp_async16((uint32_t)__cvta_generic_to_shared(&Bhs[lrow * HAS + lch * 8]),
                   &Bh_g[(size_t)(col0 + lrow) * K + lch * 8], 16);
        cp_async16((uint32_t)__cvta_generic_to_shared(&Bls[lrow * HAS + lch * 8]),
                   &Bl_g[(size_t)(col0 + lrow) * K + lch * 8], 16);
        cp_commit();
    }

    for (int kt = 0; kt < ktiles; kt++) {
        if (kt + 1 < ktiles) {
            __half* Ahs = hsm + ((kt + 1) & 1) * HSTAGE;
            __half* Als = Ahs + 128 * HAS;
            __half* Bhs = Als + 128 * HAS;
            __half* Bls = Bhs + 128 * HAS;
            int k0 = (kt + 1) << 5;
            int r = row0 + lrow;
            int rc = r < M ? r : (M - 1);
            int pb = r < M ? 16 : 0;
            cp_async16((uint32_t)__cvta_generic_to_shared(&Ahs[lrow * HAS + lch * 8]),
                       &Ah_g[(size_t)rc * K + k0 + lch * 8], pb);
            cp_async16((uint32_t)__cvta_generic_to_shared(&Als[lrow * HAS + lch * 8]),
                       &Al_g[(size_t)rc * K + k0 + lch * 8], pb);
            cp_async16((uint32_t)__cvta_generic_to_shared(&Bhs[lrow * HAS + lch * 8]),
                       &Bh_g[(size_t)(col0 + lrow) * K + k0 + lch * 8], 16);
            cp_async16((uint32_t)__cvta_generic_to_shared(&Bls[lrow * HAS + lch * 8]),
                       &Bl_g[(size_t)(col0 + lrow) * K + k0 + lch * 8], 16);
            cp_commit();
            cp_wait<1>();
        } else {
            cp_wait<0>();
        }
        __syncthreads();

        const __half* Ahs = hsm + (kt & 1) * HSTAGE;
        const __half* Als = Ahs + 128 * HAS;
        const __half* Bhs = Als + 128 * HAS;
        const __half* Bls = Bhs + 128 * HAS;

        #pragma unroll
        for (int ks = 0; ks < 2; ks++) {
            const int kb = ks * 16;
            uint32_t ah[2][4], al[2][4];
            #pragma unroll
            for (int mt = 0; mt < 2; mt++) {
                int r0 = wm * 32 + mt * 16 + g;
                ah[mt][0] = *(const uint32_t*)&Ahs[r0 * HAS + kb + 2 * t];
                ah[mt][1] = *(const uint32_t*)&Ahs[(r0 + 8) * HAS + kb + 2 * t];
                ah[mt][2] = *(const uint32_t*)&Ahs[r0 * HAS + kb + 2 * t + 8];
                ah[mt][3] = *(const uint32_t*)&Ahs[(r0 + 8) * HAS + kb + 2 * t + 8];
                al[mt][0] = *(const uint32_t*)&Als[r0 * HAS + kb + 2 * t];
                al[mt][1] = *(const uint32_t*)&Als[(r0 + 8) * HAS + kb + 2 * t];
                al[mt][2] = *(const uint32_t*)&Als[r0 * HAS + kb + 2 * t + 8];
                al[mt][3] = *(const uint32_t*)&Als[(r0 + 8) * HAS + kb + 2 * t + 8];
            }
            #pragma unroll
            for (int nt = 0; nt < 4; nt++) {
                int c = wn * 32 + nt * 8 + g;
                uint32_t bh0 = *(const uint32_t*)&Bhs[c * HAS + kb + 2 * t];
                uint32_t bh1 = *(const uint32_t*)&Bhs[c * HAS + kb + 2 * t + 8];
                uint32_t bl0 = *(const uint32_t*)&Bls[c * HAS + kb + 2 * t];
                uint32_t bl1 = *(const uint32_t*)&Bls[c * HAS + kb + 2 * t + 8];
                #pragma unroll
                for (int mt = 0; mt < 2; mt++) {
                    mma_f16(dm[mt][nt], ah[mt][0], ah[mt][1], ah[mt][2], ah[mt][3], bh0, bh1);
                    mma_f16(dc[mt][nt], ah[mt][0], ah[mt][1], ah[mt][2], ah[mt][3], bl0, bl1);
                    mma_f16(dc[mt][nt], al[mt][0], al[mt][1], al[mt][2], al[mt][3], bh0, bh1);
                }
            }
        }
        __syncthreads();
    }

    #pragma unroll
    for (int mt = 0; mt < 2; mt++) {
        #pragma unroll
        for (int nt = 0; nt < 4; nt++) {
            int r = row0 + wm * 32 + mt * 16 + g;
            int c = col0 + wn * 32 + nt * 8 + 2 * t;
            float2 bz = *(const float2*)&bias[c];
            float o0 = dm[mt][nt][0] + dc[mt][nt][0] + bsc * bz.x;
            float o1 = dm[mt][nt][1] + dc[mt][nt][1] + bsc * bz.y;
            float o2 = dm[mt][nt][2] + dc[mt][nt][2] + bsc * bz.x;
            float o3 = dm[mt][nt][3] + dc[mt][nt][3] + bsc * bz.y;
            if (mode == 0) {
                float* Cf = cfg.Cf[z];
                if (r < M)     *(float2*)&Cf[(size_t)r * ldc + c] = make_float2(o0, o1);
                if (r + 8 < M) *(float2*)&Cf[(size_t)(r + 8) * ldc + c] = make_float2(o2, o3);
            } else {
                __half* Ch = cfg.Ch[z];
                __half* Cl = cfg.Cl[z];
                __half h0, l0, h1, l1;
                if (r < M) {
                    split_h(o0, h0, l0); split_h(o1, h1, l1);
                    *(__half2*)&Ch[(size_t)r * ldc + c] = __halves2half2(h0, h1);
                    *(__half2*)&Cl[(size_t)r * ldc + c] = __halves2half2(l0, l1);
                }
                if (r + 8 < M) {
                    split_h(o2, h0, l0); split_h(o3, h1, l1);
                    *(__half2*)&Ch[(size_t)(r + 8) * ldc + c] = __halves2half2(h0, h1);
                    *(__half2*)&Cl[(size_t)(r + 8) * ldc + c] = __halves2half2(l0, l1);
                }
            }
        }
    }
}

// ---------------- sentence-level graph attention ----------------
__global__ __launch_bounds__(256) void sent_attn(
    const float* __restrict__ qs, const float* __restrict__ ksn,
    const float* __restrict__ vsn, const float* __restrict__ bias_s,
    const float* __restrict__ gab,
    float* __restrict__ attns_out,
    __half* __restrict__ csh, __half* __restrict__ csl)
{
    const int h = blockIdx.x, b = blockIdx.y;
    const int q = threadIdx.x;

    __shared__ float Ks[NSd][DKd + 1];
    __shared__ float Vs[NSd][DKd + 1];
    __shared__ float G[NSd][NSd + 1];

    for (int idx = q; idx < NSd * DKd; idx += 256) {
        int s = idx >> 6, k = idx & 63;
        Ks[s][k] = ksn[(size_t)(b * NSd + s) * Dd + h * DKd + k];
        Vs[s][k] = vsn[(size_t)(b * NSd + s) * Dd + h * DKd + k];
    }
    for (int idx = q; idx < NSd * NSd; idx += 256) {
        int s = idx / NSd, tt = idx % NSd;
        G[s][tt] = gab[((size_t)(b * Hd + h) * NSd + s) * NSd + tt];
    }
    __syncthreads();

    float qreg[DKd];
    const float* qrow = qs + (size_t)(b * LQd + q) * Dd + h * DKd;
    #pragma unroll
    for (int k = 0; k < DKd; k++) qreg[k] = qrow[k] * 0.125f;

    float a[NSd];
    const float* bsrow = bias_s + ((size_t)(b * Hd + h) * LQd + q) * NSd;
    #pragma unroll
    for (int s = 0; s < NSd; s++) {
        float dd = 0.f;
        #pragma unroll
        for (int k = 0; k < DKd; k++) dd += qreg[k] * Ks[s][k];
        a[s] = dd + bsrow[s];
    }

    float m = -1e30f;
    #pragma unroll
    for (int s = 0; s < NSd; s++) m = fmaxf(m, a[s]);
    float smx[NSd]; float sum = 0.f;
    #pragma unroll
    for (int s = 0; s < NSd; s++) { smx[s] = __expf(a[s] - m); sum += smx[s]; }
    float inv = 1.f / sum;

    float gg[NSd];
    #pragma unroll
    for (int tt = 0; tt < NSd; tt++) {
        float dd = 0.f;
        #pragma unroll
        for (int s = 0; s < NSd; s++) dd += smx[s] * G[s][tt];
        gg[tt] = dd * inv;
    }
    #pragma unroll
    for (int s = 0; s < NSd; s++) a[s] -= 0.5f * gg[s] * gg[s];

    m = -1e30f;
    #pragma unroll
    for (int s = 0; s < NSd; s++) m = fmaxf(m, a[s]);
    sum = 0.f;
    #pragma unroll
    for (int s = 0; s < NSd; s++) { a[s] = __expf(a[s] - m); sum += a[s]; }
    inv = 1.f / sum;

    float* arow = attns_out + ((size_t)(b * Hd + h) * LQd + q) * NSd;
    #pragma unroll
    for (int s = 0; s < NSd; s++) { a[s] *= inv; arow[s] = a[s]; }

    size_t cbase = (size_t)(b * LQd + q) * Dd + h * DKd;
    #pragma unroll
    for (int dd = 0; dd < DKd; dd++) {
        float acc = 0.f;
        #pragma unroll
        for (int s = 0; s < NSd; s++) acc += a[s] * Vs[s][dd];
        __half hi, lo;
        split_h(acc, hi, lo);
        csh[cbase + dd] = hi;
        csl[cbase + dd] = lo;
    }
}

// ---------------- word-level attention (split-FP16, cp.async double-buffered) ----------------
#define HQS 72
#define HPS 136
#define W_QH 0
#define W_QL (32 * HQS)
#define W_K0 (2 * 32 * HQS)                 // start of K/V stage area
#define W_ARR (128 * HQS)                   // 9216 halves per array
#define W_STG (4 * W_ARR)                   // 36864 halves per stage
#define W_PH (W_K0 + 2 * W_STG)
#define W_PL (W_PH + 32 * HPS)
#define W_PSF (W_PL + 32 * HPS)             // fp32 region starts here (half offset)
#define WPPAD 132
#define WSMEM_BYTES (W_PSF * 2 + 32 * WPPAD * 4)   // 174080 + 16896 = 190976

__global__ __launch_bounds__(256) void word_attn_h2(
    const __half* __restrict__ qwh, const __half* __restrict__ qwl,
    const __half* __restrict__ kwh, const __half* __restrict__ kwl,
    const __half* __restrict__ vwh, const __half* __restrict__ vwl,
    const float* __restrict__ bias_w, const float* __restrict__ attns,
    __half* __restrict__ cwh, __half* __restrict__ cwl)
{
    extern __shared__ __half hsm[];
    float* Ps = (float*)(hsm + W_PSF);
    __half* PH = hsm + W_PH;
    __half* PL = hsm + W_PL;

    const int tid = threadIdx.x;
    const int wid = tid >> 5;
    const int lane = tid & 31;
    const int g = lane >> 2;
    const int t = lane & 3;
    const int wm = wid & 1;
    const int wn = wid >> 1;
    const int q0 = blockIdx.x * 32;
    const int h  = blockIdx.y;
    const int b  = blockIdx.z;

    const size_t kvbase0 = (size_t)(b * NSd) * NTd * Dd + h * DKd;

    // issue Q loads + stage 0 K/V loads, one commit group
    {
        #pragma unroll
        for (int i = 0; i < 2; i++) {
            int id = tid + 256 * i;
            int arr = id >> 8, rem = id & 255;
            int row = rem >> 3, ch = rem & 7;
            const __half* src = (arr == 0 ? qwh : qwl) + (size_t)(b * LQd + q0 + row) * Dd + h * DKd + ch * 8;
            uint32_t dst = (uint32_t)__cvta_generic_to_shared(
                &hsm[(arr == 0 ? W_QH : W_QL) + row * HQS + ch * 8]);
            cp_async16(dst, src, 16);
        }
        const __half* srcs[4] = {kwh, kwl, vwh, vwl};
        #pragma unroll
        for (int i = 0; i < 16; i++) {
            int id = tid + 256 * i;
            int arr = id >> 10, rem = id & 1023;
            int row = rem >> 3, ch = rem & 7;
            const __half* src = srcs[arr] + kvbase0 + (size_t)row * Dd + ch * 8;
            uint32_t dst = (uint32_t)__cvta_generic_to_shared(
                &hsm[W_K0 + arr * W_ARR + row * HQS + ch * 8]);
            cp_async16(dst, src, 16);
        }
        cp_commit();
    }

    float om[2][4], oc[2][4];
    #pragma unroll
    for (int nt = 0; nt < 2; nt++)
        #pragma unroll
        for (int j = 0; j < 4; j++) { om[nt][j] = 0.f; oc[nt][j] = 0.f; }

    for (int s = 0; s < NSd; s++) {
        // prefetch next stage
        if (s + 1 < NSd) {
            const size_t kvb = (size_t)(b * NSd + s + 1) * NTd * Dd + h * DKd;
            int stb = W_K0 + ((s + 1) & 1) * W_STG;
            const __half* srcs[4] = {kwh, kwl, vwh, vwl};
            #pragma unroll
            for (int i = 0; i < 16; i++) {
                int id = tid + 256 * i;
                int arr = id >> 10, rem = id & 1023;
                int row = rem >> 3, ch = rem & 7;
                const __half* src = srcs[arr] + kvb + (size_t)row * Dd + ch * 8;
                uint32_t dst = (uint32_t)__cvta_generic_to_shared(
                    &hsm[stb + arr * W_ARR + row * HQS + ch * 8]);
                cp_async16(dst, src, 16);
            }
            cp_commit();
            cp_wait<1>();
        } else {
            cp_wait<0>();
        }
        __syncthreads();

        const __half* QH = hsm + W_QH;
        const __half* QL = hsm + W_QL;
        const int stb = W_K0 + (s & 1) * W_STG;
        const __half* KH = hsm + stb;
        const __half* KL = hsm + stb + W_ARR;
        const __half* VH = hsm + stb + 2 * W_ARR;
        const __half* VL = hsm + stb + 3 * W_ARR;

        // ---- P = Q @ K^T (warp tile 16x32) ----
        float pm[4][4], pc[4][4];
        #pragma unroll
        for (int nt = 0; nt < 4; nt++)
            #pragma unroll
            for (int j = 0; j < 4; j++) { pm[nt][j] = 0.f; pc[nt][j] = 0.f; }

        #pragma unroll
        for (int ks = 0; ks < 4; ks++) {
            const int kb = ks * 16;
            int r0 = wm * 16 + g;
            uint32_t ah0 = *(const uint32_t*)&QH[r0 * HQS + kb + 2 * t];
            uint32_t ah1 = *(const uint32_t*)&QH[(r0 + 8) * HQS + kb + 2 * t];
            uint32_t ah2 = *(const uint32_t*)&QH[r0 * HQS + kb + 2 * t + 8];
            uint32_t ah3 = *(const uint32_t*)&QH[(r0 + 8) * HQS + kb + 2 * t + 8];
            uint32_t al0 = *(const uint32_t*)&QL[r0 * HQS + kb + 2 * t];
            uint32_t al1 = *(const uint32_t*)&QL[(r0 + 8) * HQS + kb + 2 * t];
            uint32_t al2 = *(const uint32_t*)&QL[r0 * HQS + kb + 2 * t + 8];
            uint32_t al3 = *(const uint32_t*)&QL[(r0 + 8) * HQS + kb + 2 * t + 8];
            #pragma unroll
            for (int nt = 0; nt < 4; nt++) {
                int c = wn * 32 + nt * 8 + g;
                uint32_t bh0 = *(const uint32_t*)&KH[c * HQS + kb + 2 * t];
                uint32_t bh1 = *(const uint32_t*)&KH[c * HQS + kb + 2 * t + 8];
                uint32_t bl0 = *(const uint32_t*)&KL[c * HQS + kb + 2 * t];
                uint32_t bl1 = *(const uint32_t*)&KL[c * HQS + kb + 2 * t + 8];
                mma_f16(pm[nt], ah0, ah1, ah2, ah3, bh0, bh1);
                mma_f16(pc[nt], ah0, ah1, ah2, ah3, bl0, bl1);
                mma_f16(pc[nt], al0, al1, al2, al3, bh0, bh1);
            }
        }
        #pragma unroll
        for (int nt = 0; nt < 4; nt++) {
            int r = wm * 16 + g;
            int c = wn * 32 + nt * 8 + 2 * t;
            *(float2*)&Ps[r * WPPAD + c] = make_float2(pm[nt][0] + pc[nt][0], pm[nt][1] + pc[nt][1]);
            *(float2*)&Ps[(r + 8) * WPPAD + c] = make_float2(pm[nt][2] + pc[nt][2], pm[nt][3] + pc[nt][3]);
        }
        __syncthreads();

        // ---- softmax + bias + attns scale; write split-fp16 P ----
        const float* bb = bias_w + ((size_t)((b * NSd + s) * Hd + h) * LQd + q0) * NTd;
        #pragma unroll
        for (int rr = 0; rr < 4; rr++) {
            int r = wid * 4 + rr;
            float x0 = Ps[r * WPPAD + lane]       + bb[r * NTd + lane];
            float x1 = Ps[r * WPPAD + lane + 32]  + bb[r * NTd + lane + 32];
            float x2 = Ps[r * WPPAD + lane + 64]  + bb[r * NTd + lane + 64];
            float x3 = Ps[r * WPPAD + lane + 96]  + bb[r * NTd + lane + 96];
            float mx = fmaxf(fmaxf(x0, x1), fmaxf(x2, x3));
            #pragma unroll
            for (int o = 16; o; o >>= 1) mx = fmaxf(mx, __shfl_xor_sync(0xffffffffu, mx, o));
            x0 = __expf(x0 - mx); x1 = __expf(x1 - mx);
            x2 = __expf(x2 - mx); x3 = __expf(x3 - mx);
            float su = x0 + x1 + x2 + x3;
            #pragma unroll
            for (int o = 16; o; o >>= 1) su += __shfl_xor_sync(0xffffffffu, su, o);
            float wsc = attns[((size_t)(b * Hd + h) * LQd + q0 + r) * NSd + s] / su;
            __half hi, lo;
            split_h(x0 * wsc, hi, lo); PH[r * HPS + lane] = hi;       PL[r * HPS + lane] = lo;
            split_h(x1 * wsc, hi, lo); PH[r * HPS + lane + 32] = hi;  PL[r * HPS + lane + 32] = lo;
            split_h(x2 * wsc, hi, lo); PH[r * HPS + lane + 64] = hi;  PL[r * HPS + lane + 64] = lo;
            split_h(x3 * wsc, hi, lo); PH[r * HPS + lane + 96] = hi;  PL[r * HPS + lane + 96] = lo;
        }
        __syncthreads();

        // ---- O += P @ V (warp tile 16x16) ----
        #pragma unroll
        for (int ks = 0; ks < 8; ks++) {
            const int kb = ks * 16;
            int r0 = wm * 16 + g;
            uint32_t ph0 = *(const uint32_t*)&PH[r0 * HPS + kb + 2 * t];
            uint32_t ph1 = *(const uint32_t*)&PH[(r0 + 8) * HPS + kb + 2 * t];
            uint32_t ph2 = *(const uint32_t*)&PH[r0 * HPS + kb + 2 * t + 8];
            uint32_t ph3 = *(const uint32_t*)&PH[(r0 + 8) * HPS + kb + 2 * t + 8];
            uint32_t pl0 = *(const uint32_t*)&PL[r0 * HPS + kb + 2 * t];
            uint32_t pl1 = *(const uint32_t*)&PL[(r0 + 8) * HPS + kb + 2 * t];
            uint32_t pl2 = *(const uint32_t*)&PL[r0 * HPS + kb + 2 * t + 8];
            uint32_t pl3 = *(const uint32_t*)&PL[(r0 + 8) * HPS + kb + 2 * t + 8];
            #pragma unroll
            for (int nt = 0; nt < 2; nt++) {
                int c = wn * 16 + nt * 8 + g;
                int k0r = kb + 2 * t;
                uint32_t bh0 = pack_h2(VH[k0r * HQS + c],        VH[(k0r + 1) * HQS + c]);
                uint32_t bh1 = pack_h2(VH[(k0r + 8) * HQS + c],  VH[(k0r + 9) * HQS + c]);
                uint32_t bl0 = pack_h2(VL[k0r * HQS + c],        VL[(k0r + 1) * HQS + c]);
                uint32_t bl1 = pack_h2(VL[(k0r + 8) * HQS + c],  VL[(k0r + 9) * HQS + c]);
                mma_f16(om[nt], ph0, ph1, ph2, ph3, bh0, bh1);
                mma_f16(oc[nt], ph0, ph1, ph2, ph3, bl0, bl1);
                mma_f16(oc[nt], pl0, pl1, pl2, pl3, bh0, bh1);
            }
        }
        __syncthreads();   // all threads done with stage s before it's overwritten
    }

    #pragma unroll
    for (int nt = 0; nt < 2; nt++) {
        int r = q0 + wm * 16 + g;
        int c = h * DKd + wn * 16 + nt * 8 + 2 * t;
        float v0 = om[nt][0] + oc[nt][0], v1 = om[nt][1] + oc[nt][1];
        float v2 = om[nt][2] + oc[nt][2], v3 = om[nt][3] + oc[nt][3];
        __half h0, l0, h1, l1;
        split_h(v0, h0, l0); split_h(v1, h1, l1);
        *(__half2*)&cwh[(size_t)(b * LQd + r) * Dd + c] = __halves2half2(h0, h1);
        *(__half2*)&cwl[(size_t)(b * LQd + r) * Dd + c] = __halves2half2(l0, l1);
        split_h(v2, h0, l0); split_h(v3, h1, l1);
        *(__half2*)&cwh[(size_t)(b * LQd + r + 8) * Dd + c] = __halves2half2(h0, h1);
        *(__half2*)&cwl[(size_t)(b * LQd + r + 8) * Dd + c] = __halves2half2(l0, l1);
    }
}

// ---------------- host ----------------
extern "C" void kernel_launch(void* const* d_in, const int* in_sizes, int n_in,
                              void* d_out, int out_size)
{
    const float* q      = (const float*)d_in[0];
    const float* k_s    = (const float*)d_in[1];
    const float* v_s    = (const float*)d_in[2];
    const float* k_w    = (const float*)d_in[3];
    const float* v_w    = (const float*)d_in[4];
    const float* bias_w = (const float*)d_in[5];
    const float* bias_s = (const float*)d_in[6];
    const float* gab    = (const float*)d_in[7];

    const float *wq_s, *bq_s, *wk_s, *bk_s, *wv_s, *bv_s;
    const float *wq_w, *bq_w, *wk_w, *bk_w, *wv_w, *bv_w;
    const float *fcs_w, *fcs_b, *fcw_w, *fcw_b, *fco_w, *fco_b;

    if (in_sizes[9] == 512) {
        wq_s = (const float*)d_in[8];  bq_s = (const float*)d_in[9];
        wk_s = (const float*)d_in[10]; bk_s = (const float*)d_in[11];
        wv_s = (const float*)d_in[12]; bv_s = (const float*)d_in[13];
        wq_w = (const float*)d_in[14]; bq_w = (const float*)d_in[15];
        wk_w = (const float*)d_in[16]; bk_w = (const float*)d_in[17];
        wv_w = (const float*)d_in[18]; bv_w = (const float*)d_in[19];
        fcs_w = (const float*)d_in[20]; fcs_b = (const float*)d_in[21];
        fcw_w = (const float*)d_in[22]; fcw_b = (const float*)d_in[23];
        fco_w = (const float*)d_in[24]; fco_b = (const float*)d_in[25];
    } else {
        wq_s = (const float*)d_in[8];  wk_s = (const float*)d_in[9];
        wv_s = (const float*)d_in[10]; wq_w = (const float*)d_in[11];
        wk_w = (const float*)d_in[12]; wv_w = (const float*)d_in[13];
        fcs_w = (const float*)d_in[14]; fcw_w = (const float*)d_in[15];
        bq_s = (const float*)d_in[16]; bk_s = (const float*)d_in[17];
        bv_s = (const float*)d_in[18]; bq_w = (const float*)d_in[19];
        bk_w = (const float*)d_in[20]; bv_w = (const float*)d_in[21];
        fcs_b = (const float*)d_in[22]; fcw_b = (const float*)d_in[23];
        fco_w = (const float*)d_in[24]; fco_b = (const float*)d_in[25];
    }

    float* scratch = nullptr;
    cudaGetSymbolAddress((void**)&scratch, g_scratch);
    float* s_qs  = scratch + OFF_QS;
    float* s_ks  = scratch + OFF_KS;
    float* s_vs  = scratch + OFF_VS;
    float* s_att = scratch + OFF_ATT;
    __half* hb = (__half*)(scratch + OFF_HALF);
    __half* acth = hb + H_ACTH;
    __half* actl = hb + H_ACTL;
    __half* wth  = hb + H_WTH;
    __half* wtl  = hb + H_WTL;
    __half* qwh  = hb + H_QWH;
    __half* qwl  = hb + H_QWL;
    __half* kwh  = hb + H_KWH;
    __half* kwl  = hb + H_KWL;
    __half* vwh  = hb + H_VWH;
    __half* vwl  = hb + H_VWL;
    __half* csh  = hb + H_CSH;
    __half* csl  = hb + H_CSL;
    __half* cwh  = hb + H_CWH;
    __half* cwl  = hb + H_CWL;
    __half* cath = hb + H_CATH;
    __half* catl = hb + H_CATL;

    cudaFuncSetAttribute(gemm_cfg, cudaFuncAttributeMaxDynamicSharedMemorySize, HSMEM_BYTES);
    cudaFuncSetAttribute(word_attn_h2, cudaFuncAttributeMaxDynamicSharedMemorySize, WSMEM_BYTES);

    // prep
    ASplitArgs aa;
    aa.src[0] = q; aa.src[1] = k_s; aa.src[2] = v_s; aa.src[3] = k_w; aa.src[4] = v_w;
    act_split<<<dim3(256, 5), 256>>>(aa, acth, actl);
    WSplitArgs wa;
    wa.src[0] = wq_s; wa.src[1] = wk_s; wa.src[2] = wv_s;
    wa.src[3] = wq_w; wa.src[4] = wk_w; wa.src[5] = wv_w;
    wa.src[6] = fcs_w; wa.src[7] = fcw_w; wa.src[8] = fco_w;
    w_transplit<<<dim3(16, 32, 9), dim3(32, 8)>>>(wa, wth, wtl);

    // merged projections A: z0 qs(f32), z1 qw(split, 0.125 folded), z2 ks(f32), z3 vs(f32)
    {
        GemmCfg c = {};
        c.K = 512; c.ldc = 512;
        c.Ah[0] = acth + AQ;  c.Al[0] = actl + AQ;
        c.Ah[1] = acth + AQ;  c.Al[1] = actl + AQ;
        c.Ah[2] = acth + AKS; c.Al[2] = actl + AKS;
        c.Ah[3] = acth + AVS; c.Al[3] = actl + AVS;
        c.Bh[0] = wth + WOFF(0); c.Bl[0] = wtl + WOFF(0);
        c.Bh[1] = wth + WOFF(3); c.Bl[1] = wtl + WOFF(3);
        c.Bh[2] = wth + WOFF(1); c.Bl[2] = wtl + WOFF(1);
        c.Bh[3] = wth + WOFF(2); c.Bl[3] = wtl + WOFF(2);
        c.bias[0] = bq_s; c.bias[1] = bq_w; c.bias[2] = bk_s; c.bias[3] = bv_s;
        c.bscale[0] = 1.f; c.bscale[1] = 0.125f; c.bscale[2] = 1.f; c.bscale[3] = 1.f;
        c.M[0] = 1024; c.M[1] = 1024; c.M[2] = 96; c.M[3] = 96;
        c.mode[0] = 0; c.mode[1] = 1; c.mode[2] = 0; c.mode[3] = 0;
        c.Cf[0] = s_qs; c.Cf[2] = s_ks; c.Cf[3] = s_vs;
        c.Ch[1] = qwh;  c.Cl[1] = qwl;
        gemm_cfg<<<dim3(4, 8, 4), 512, HSMEM_BYTES>>>(c);
    }
    // big word projections: z0 kw, z1 vw (both split output)
    {
        GemmCfg c = {};
        c.K = 512; c.ldc = 512;
        c.Ah[0] = acth + AKW; c.Al[0] = actl + AKW;
        c.Ah[1] = acth + AVW; c.Al[1] = actl + AVW;
        c.Bh[0] = wth + WOFF(4); c.Bl[0] = wtl + WOFF(4);
        c.Bh[1] = wth + WOFF(5); c.Bl[1] = wtl + WOFF(5);
        c.bias[0] = bk_w; c.bias[1] = bv_w;
        c.bscale[0] = 1.f; c.bscale[1] = 1.f;
        c.M[0] = 12288; c.M[1] = 12288;
        c.mode[0] = 1; c.mode[1] = 1;
        c.Ch[0] = kwh; c.Cl[0] = kwl;
        c.Ch[1] = vwh; c.Cl[1] = vwl;
        gemm_cfg<<<dim3(4, 96, 2), 512, HSMEM_BYTES>>>(c);
    }

    sent_attn<<<dim3(Hd, BB), 256>>>(s_qs, s_ks, s_vs, bias_s, gab, s_att, csh, csl);

    word_attn_h2<<<dim3(8, Hd, BB), 256, WSMEM_BYTES>>>(
        qwh, qwl, kwh, kwl, vwh, vwl, bias_w, s_att, cwh, cwl);

    // fcs / fcw -> split cat
    {
        GemmCfg c = {};
        c.K = 512; c.ldc = 1024;
        c.Ah[0] = csh; c.Al[0] = csl;
        c.Ah[1] = cwh; c.Al[1] = cwl;
        c.Bh[0] = wth + WOFF(6); c.Bl[0] = wtl + WOFF(6);
        c.Bh[1] = wth + WOFF(7); c.Bl[1] = wtl + WOFF(7);
        c.bias[0] = fcs_b; c.bias[1] = fcw_b;
        c.bscale[0] = 1.f; c.bscale[1] = 1.f;
        c.M[0] = 1024; c.M[1] = 1024;
        c.mode[0] = 1; c.mode[1] = 1;
        c.Ch[0] = cath;       c.Cl[0] = catl;
        c.Ch[1] = cath + 512; c.Cl[1] = catl + 512;
        gemm_cfg<<<dim3(4, 8, 2), 512, HSMEM_BYTES>>>(c);
    }
    // final fco -> fp32 out
    {
        GemmCfg c = {};
        c.K = 1024; c.ldc = 512;
        c.Ah[0] = cath; c.Al[0] = catl;
        c.Bh[0] = wth + WOFF(8); c.Bl[0] = wtl + WOFF(8);
        c.bias[0] = fco_b;
        c.bscale[0] = 1.f;
        c.M[0] = 1024;
        c.mode[0] = 0;
        c.Cf[0] = (float*)d_out;
        gemm_cfg<<<dim3(4, 8, 1), 512, HSMEM_BYTES>>>(c);
    }
}

// round 8
// speedup vs baseline: 1.5594x; 1.1874x over previous
#include <cuda_runtime.h>
#include <cuda_fp16.h>
#include <math.h>
#include <stdint.h>

// Problem constants
#define BB   4
#define LQd  256
#define NSd  24
#define NTd  128
#define Dd   512
#define Hd   8
#define DKd  64

// ---------------- scratch layout ----------------
#define OFF_QS   0
#define OFF_KS   524288
#define OFF_VS   573440
#define OFF_ATT  622592
#define OFF_HALF 819200
#define H_ACTH 0
#define H_ACTL 13205504
#define H_WTH  26411008
#define H_WTL  29032448
#define H_QWH  31653888
#define H_QWL  32178176
#define H_KWH  32702464
#define H_KWL  38993920
#define H_VWH  45285376
#define H_VWL  51576832
#define H_CSH  57868288
#define H_CSL  58392576
#define H_CWH  58916864
#define H_CWL  59441152
#define H_CATH 59965440
#define H_CATL 61014016
#define H_TOTAL 62062592
#define SCRATCH_TOTAL (OFF_HALF + H_TOTAL / 2)
__device__ float g_scratch[SCRATCH_TOTAL];

#define AQ   0
#define AKS  524288
#define AVS  573440
#define AKW  622592
#define AVW  6914048
#define WOFF(i) ((i) * 262144)

// ---------------- helpers ----------------
__device__ __forceinline__ void split_h(float x, __half& hi, __half& lo) {
    hi = __float2half_rn(x);
    lo = __float2half_rn(x - __half2float(hi));
}
__device__ __forceinline__ uint32_t pack_h2(__half a, __half b) {
    return (uint32_t)__half_as_ushort(a) | ((uint32_t)__half_as_ushort(b) << 16);
}
__device__ __forceinline__ void mma_f16(float d[4],
                                        uint32_t a0, uint32_t a1, uint32_t a2, uint32_t a3,
                                        uint32_t b0, uint32_t b1) {
    asm volatile(
        "mma.sync.aligned.m16n8k16.row.col.f32.f16.f16.f32 "
        "{%0,%1,%2,%3},{%4,%5,%6,%7},{%8,%9},{%0,%1,%2,%3};"
        : "+f"(d[0]), "+f"(d[1]), "+f"(d[2]), "+f"(d[3])
        : "r"(a0), "r"(a1), "r"(a2), "r"(a3), "r"(b0), "r"(b1));
}
__device__ __forceinline__ void cp_async16(uint32_t smem_addr, const void* gptr, int src_bytes) {
    asm volatile("cp.async.cg.shared.global [%0], [%1], 16, %2;"
                 :: "r"(smem_addr), "l"(gptr), "r"(src_bytes) : "memory");
}
__device__ __forceinline__ void cp_commit() { asm volatile("cp.async.commit_group;" ::: "memory"); }
template <int N>
__device__ __forceinline__ void cp_wait() { asm volatile("cp.async.wait_group %0;" :: "n"(N) : "memory"); }

// ---------------- prep: split activations ----------------
struct ASplitArgs { const float* src[5]; };
__constant__ int c_alen[5] = {524288, 49152, 49152, 6291456, 6291456};
__constant__ int c_aoff[5] = {AQ, AKS, AVS, AKW, AVW};

__global__ __launch_bounds__(256) void act_split(ASplitArgs args, __half* acth, __half* actl)
{
    int z = blockIdx.y;
    int n = c_alen[z];
    const float* s = args.src[z];
    __half* dh = acth + c_aoff[z];
    __half* dl = actl + c_aoff[z];
    for (int i = blockIdx.x * 256 + threadIdx.x; i < n; i += gridDim.x * 256) {
        __half hi, lo;
        split_h(s[i], hi, lo);
        dh[i] = hi;
        dl[i] = lo;
    }
}

// ---------------- prep: transpose+split weights ----------------
struct WSplitArgs { const float* src[9]; };
__constant__ int c_wK[9] = {512, 512, 512, 512, 512, 512, 512, 512, 1024};
__constant__ int c_woff[9] = {WOFF(0), WOFF(1), WOFF(2), WOFF(3), WOFF(4),
                              WOFF(5), WOFF(6), WOFF(7), WOFF(8)};
__constant__ float c_wscale[9] = {1.f, 1.f, 1.f, 0.125f, 1.f, 1.f, 1.f, 1.f, 1.f};

__global__ void w_transplit(WSplitArgs args, __half* wth, __half* wtl)
{
    int z = blockIdx.z;
    int Kw = c_wK[z];
    int k0 = blockIdx.y * 32;
    if (k0 >= Kw) return;
    int n0 = blockIdx.x * 32;
    const float* W = args.src[z];
    float sc = c_wscale[z];
    __half* th = wth + c_woff[z];
    __half* tl = wtl + c_woff[z];

    __shared__ float ts[32][33];
    int tx = threadIdx.x, ty = threadIdx.y;
    #pragma unroll
    for (int r = 0; r < 4; r++)
        ts[ty + 8 * r][tx] = W[(size_t)(k0 + ty + 8 * r) * 512 + n0 + tx];
    __syncthreads();
    #pragma unroll
    for (int r = 0; r < 4; r++) {
        int n = n0 + ty + 8 * r;
        int k = k0 + tx;
        __half hi, lo;
        split_h(sc * ts[tx][ty + 8 * r], hi, lo);
        th[(size_t)n * Kw + k] = hi;
        tl[(size_t)n * Kw + k] = lo;
    }
}

// ---------------- split-FP16 GEMM: 128x64 tile, 256 threads, 2 CTAs/SM ----------------
#define HAS 40
#define G_A 128   // A rows per tile
#define G_B 64    // B rows (N cols) per tile
#define HSTAGE ((2 * G_A + 2 * G_B) * HAS)   // 15360 halves
#define HSMEM_BYTES (2 * HSTAGE * 2)         // 61440

struct GemmCfg {
    const __half* Ah[4]; const __half* Al[4];
    const __half* Bh[4]; const __half* Bl[4];
    const float* bias[4];
    float* Cf[4];
    __half* Ch[4]; __half* Cl[4];
    int M[4]; int mode[4]; float bscale[4];
    int K; int ldc;
};

__global__ __launch_bounds__(256, 2) void gemm_cfg(GemmCfg cfg)
{
    extern __shared__ __half hsm[];

    const int z = blockIdx.z;
    const int M = cfg.M[z];
    const int row0 = blockIdx.y * 128;
    if (row0 >= M) return;

    const __half* Ah_g = cfg.Ah[z];
    const __half* Al_g = cfg.Al[z];
    const __half* Bh_g = cfg.Bh[z];
    const __half* Bl_g = cfg.Bl[z];
    const float* bias  = cfg.bias[z];
    const int mode     = cfg.mode[z];
    const float bsc    = cfg.bscale[z];
    const int K        = cfg.K;
    const int ldc      = cfg.ldc;

    const int tid = threadIdx.x;
    const int wid = tid >> 5;
    const int lane = tid & 31;
    const int g = lane >> 2;
    const int t = lane & 3;
    const int wm = wid & 3;       // 4 row groups of 32
    const int wn = wid >> 2;      // 2 col groups of 32
    const int col0 = blockIdx.x * 64;

    float dm[2][4][4], dc[2][4][4];
    #pragma unroll
    for (int mt = 0; mt < 2; mt++)
        #pragma unroll
        for (int nt = 0; nt < 4; nt++)
            #pragma unroll
            for (int j = 0; j < 4; j++) { dm[mt][nt][j] = 0.f; dc[mt][nt][j] = 0.f; }

    const int ktiles = K >> 5;

    // load helper indices: A = 2 arrays x 128 rows x 4 chunks (1024 slots),
    // B = 2 arrays x 64 rows x 4 chunks (512 slots)
    {
        __half* Ahs = hsm;
        __half* Als = Ahs + G_A * HAS;
        __half* Bhs = Als + G_A * HAS;
        __half* Bls = Bhs + G_B * HAS;
        #pragma unroll
        for (int i = 0; i < 4; i++) {
            int id = tid + 256 * i;
            int arr = id >> 9, rem = id & 511;
            int row = rem >> 2, ch = rem & 3;
            int r = row0 + row;
            int rc = r < M ? r : (M - 1);
            int pb = r < M ? 16 : 0;
            const __half* src = (arr ? Al_g : Ah_g) + (size_t)rc * K + ch * 8;
            __half* dst = (arr ? Als : Ahs) + row * HAS + ch * 8;
            cp_async16((uint32_t)__cvta_generic_to_shared(dst), src, pb);
        }
        #pragma unroll
        for (int i = 0; i < 2; i++) {
            int id = tid + 256 * i;
            int arr = id >> 8, rem = id & 255;
            int row = rem >> 2, ch = rem & 3;
            const __half* src = (arr ? Bl_g : Bh_g) + (size_t)(col0 + row) * K + ch * 8;
            __half* dst = (arr ? Bls : Bhs) + row * HAS + ch * 8;
            cp_async16((uint32_t)__cvta_generic_to_shared(dst), src, 16);
        }
        cp_commit();
    }

    for (int kt = 0; kt < ktiles; kt++) {
        if (kt + 1 < ktiles) {
            __half* Ahs = hsm + ((kt + 1) & 1) * HSTAGE;
            __half* Als = Ahs + G_A * HAS;
            __half* Bhs = Als + G_A * HAS;
            __half* Bls = Bhs + G_B * HAS;
            int k0 = (kt + 1) << 5;
            #pragma unroll
            for (int i = 0; i < 4; i++) {
                int id = tid + 256 * i;
                int arr = id >> 9, rem = id & 511;
                int row = rem >> 2, ch = rem & 3;
                int r = row0 + row;
                int rc = r < M ? r : (M - 1);
                int pb = r < M ? 16 : 0;
                const __half* src = (arr ? Al_g : Ah_g) + (size_t)rc * K + k0 + ch * 8;
                __half* dst = (arr ? Als : Ahs) + row * HAS + ch * 8;
                cp_async16((uint32_t)__cvta_generic_to_shared(dst), src, pb);
            }
            #pragma unroll
            for (int i = 0; i < 2; i++) {
                int id = tid + 256 * i;
                int arr = id >> 8, rem = id & 255;
                int row = rem >> 2, ch = rem & 3;
                const __half* src = (arr ? Bl_g : Bh_g) + (size_t)(col0 + row) * K + k0 + ch * 8;
                __half* dst = (arr ? Bls : Bhs) + row * HAS + ch * 8;
                cp_async16((uint32_t)__cvta_generic_to_shared(dst), src, 16);
            }
            cp_commit();
            cp_wait<1>();
        } else {
            cp_wait<0>();
        }
        __syncthreads();

        const __half* Ahs = hsm + (kt & 1) * HSTAGE;
        const __half* Als = Ahs + G_A * HAS;
        const __half* Bhs = Als + G_A * HAS;
        const __half* Bls = Bhs + G_B * HAS;

        #pragma unroll
        for (int ks = 0; ks < 2; ks++) {
            const int kb = ks * 16;
            uint32_t ah[2][4], al[2][4];
            #pragma unroll
            for (int mt = 0; mt < 2; mt++) {
                int r0 = wm * 32 + mt * 16 + g;
                ah[mt][0] = *(const uint32_t*)&Ahs[r0 * HAS + kb + 2 * t];
                ah[mt][1] = *(const uint32_t*)&Ahs[(r0 + 8) * HAS + kb + 2 * t];
                ah[mt][2] = *(const uint32_t*)&Ahs[r0 * HAS + kb + 2 * t + 8];
                ah[mt][3] = *(const uint32_t*)&Ahs[(r0 + 8) * HAS + kb + 2 * t + 8];
                al[mt][0] = *(const uint32_t*)&Als[r0 * HAS + kb + 2 * t];
                al[mt][1] = *(const uint32_t*)&Als[(r0 + 8) * HAS + kb + 2 * t];
                al[mt][2] = *(const uint32_t*)&Als[r0 * HAS + kb + 2 * t + 8];
                al[mt][3] = *(const uint32_t*)&Als[(r0 + 8) * HAS + kb + 2 * t + 8];
            }
            #pragma unroll
            for (int nt = 0; nt < 4; nt++) {
                int c = wn * 32 + nt * 8 + g;
                uint32_t bh0 = *(const uint32_t*)&Bhs[c * HAS + kb + 2 * t];
                uint32_t bh1 = *(const uint32_t*)&Bhs[c * HAS + kb + 2 * t + 8];
                uint32_t bl0 = *(const uint32_t*)&Bls[c * HAS + kb + 2 * t];
                uint32_t bl1 = *(const uint32_t*)&Bls[c * HAS + kb + 2 * t + 8];
                #pragma unroll
                for (int mt = 0; mt < 2; mt++) {
                    mma_f16(dm[mt][nt], ah[mt][0], ah[mt][1], ah[mt][2], ah[mt][3], bh0, bh1);
                    mma_f16(dc[mt][nt], ah[mt][0], ah[mt][1], ah[mt][2], ah[mt][3], bl0, bl1);
                    mma_f16(dc[mt][nt], al[mt][0], al[mt][1], al[mt][2], al[mt][3], bh0, bh1);
                }
            }
        }
        __syncthreads();
    }

    #pragma unroll
    for (int mt = 0; mt < 2; mt++) {
        #pragma unroll
        for (int nt = 0; nt < 4; nt++) {
            int r = row0 + wm * 32 + mt * 16 + g;
            int c = col0 + wn * 32 + nt * 8 + 2 * t;
            float2 bz = *(const float2*)&bias[c];
            float o0 = dm[mt][nt][0] + dc[mt][nt][0] + bsc * bz.x;
            float o1 = dm[mt][nt][1] + dc[mt][nt][1] + bsc * bz.y;
            float o2 = dm[mt][nt][2] + dc[mt][nt][2] + bsc * bz.x;
            float o3 = dm[mt][nt][3] + dc[mt][nt][3] + bsc * bz.y;
            if (mode == 0) {
                float* Cf = cfg.Cf[z];
                if (r < M)     *(float2*)&Cf[(size_t)r * ldc + c] = make_float2(o0, o1);
                if (r + 8 < M) *(float2*)&Cf[(size_t)(r + 8) * ldc + c] = make_float2(o2, o3);
            } else {
                __half* Ch = cfg.Ch[z];
                __half* Cl = cfg.Cl[z];
                __half h0, l0, h1, l1;
                if (r < M) {
                    split_h(o0, h0, l0); split_h(o1, h1, l1);
                    *(__half2*)&Ch[(size_t)r * ldc + c] = __halves2half2(h0, h1);
                    *(__half2*)&Cl[(size_t)r * ldc + c] = __halves2half2(l0, l1);
                }
                if (r + 8 < M) {
                    split_h(o2, h0, l0); split_h(o3, h1, l1);
                    *(__half2*)&Ch[(size_t)(r + 8) * ldc + c] = __halves2half2(h0, h1);
                    *(__half2*)&Cl[(size_t)(r + 8) * ldc + c] = __halves2half2(l0, l1);
                }
            }
        }
    }
}

// ---------------- sentence-level graph attention ----------------
__global__ __launch_bounds__(256) void sent_attn(
    const float* __restrict__ qs, const float* __restrict__ ksn,
    const float* __restrict__ vsn, const float* __restrict__ bias_s,
    const float* __restrict__ gab,
    float* __restrict__ attns_out,
    __half* __restrict__ csh, __half* __restrict__ csl)
{
    const int h = blockIdx.x, b = blockIdx.y;
    const int q = threadIdx.x;

    __shared__ float Ks[NSd][DKd + 1];
    __shared__ float Vs[NSd][DKd + 1];
    __shared__ float G[NSd][NSd + 1];

    for (int idx = q; idx < NSd * DKd; idx += 256) {
        int s = idx >> 6, k = idx & 63;
        Ks[s][k] = ksn[(size_t)(b * NSd + s) * Dd + h * DKd + k];
        Vs[s][k] = vsn[(size_t)(b * NSd + s) * Dd + h * DKd + k];
    }
    for (int idx = q; idx < NSd * NSd; idx += 256) {
        int s = idx / NSd, tt = idx % NSd;
        G[s][tt] = gab[((size_t)(b * Hd + h) * NSd + s) * NSd + tt];
    }
    __syncthreads();

    float qreg[DKd];
    const float* qrow = qs + (size_t)(b * LQd + q) * Dd + h * DKd;
    #pragma unroll
    for (int k = 0; k < DKd; k++) qreg[k] = qrow[k] * 0.125f;

    float a[NSd];
    const float* bsrow = bias_s + ((size_t)(b * Hd + h) * LQd + q) * NSd;
    #pragma unroll
    for (int s = 0; s < NSd; s++) {
        float dd = 0.f;
        #pragma unroll
        for (int k = 0; k < DKd; k++) dd += qreg[k] * Ks[s][k];
        a[s] = dd + bsrow[s];
    }

    float m = -1e30f;
    #pragma unroll
    for (int s = 0; s < NSd; s++) m = fmaxf(m, a[s]);
    float smx[NSd]; float sum = 0.f;
    #pragma unroll
    for (int s = 0; s < NSd; s++) { smx[s] = __expf(a[s] - m); sum += smx[s]; }
    float inv = 1.f / sum;

    float gg[NSd];
    #pragma unroll
    for (int tt = 0; tt < NSd; tt++) {
        float dd = 0.f;
        #pragma unroll
        for (int s = 0; s < NSd; s++) dd += smx[s] * G[s][tt];
        gg[tt] = dd * inv;
    }
    #pragma unroll
    for (int s = 0; s < NSd; s++) a[s] -= 0.5f * gg[s] * gg[s];

    m = -1e30f;
    #pragma unroll
    for (int s = 0; s < NSd; s++) m = fmaxf(m, a[s]);
    sum = 0.f;
    #pragma unroll
    for (int s = 0; s < NSd; s++) { a[s] = __expf(a[s] - m); sum += a[s]; }
    inv = 1.f / sum;

    float* arow = attns_out + ((size_t)(b * Hd + h) * LQd + q) * NSd;
    #pragma unroll
    for (int s = 0; s < NSd; s++) { a[s] *= inv; arow[s] = a[s]; }

    size_t cbase = (size_t)(b * LQd + q) * Dd + h * DKd;
    #pragma unroll
    for (int dd = 0; dd < DKd; dd++) {
        float acc = 0.f;
        #pragma unroll
        for (int s = 0; s < NSd; s++) acc += a[s] * Vs[s][dd];
        __half hi, lo;
        split_h(acc, hi, lo);
        csh[cbase + dd] = hi;
        csl[cbase + dd] = lo;
    }
}

// ---------------- word-level attention (split-FP16, 512 threads) ----------------
#define HQS 72
#define HPS 136
#define W_QH 0
#define W_QL (32 * HQS)
#define W_K0 (2 * 32 * HQS)
#define W_ARR (128 * HQS)
#define W_STG (4 * W_ARR)
#define W_PH (W_K0 + 2 * W_STG)
#define W_PL (W_PH + 32 * HPS)
#define W_PSF (W_PL + 32 * HPS)
#define WPPAD 132
#define WSMEM_BYTES (W_PSF * 2 + 32 * WPPAD * 4)

__global__ __launch_bounds__(512) void word_attn_h2(
    const __half* __restrict__ qwh, const __half* __restrict__ qwl,
    const __half* __restrict__ kwh, const __half* __restrict__ kwl,
    const __half* __restrict__ vwh, const __half* __restrict__ vwl,
    const float* __restrict__ bias_w, const float* __restrict__ attns,
    __half* __restrict__ cwh, __half* __restrict__ cwl)
{
    extern __shared__ __half hsm[];
    float* Ps = (float*)(hsm + W_PSF);
    __half* PH = hsm + W_PH;
    __half* PL = hsm + W_PL;

    const int tid = threadIdx.x;
    const int wid = tid >> 5;
    const int lane = tid & 31;
    const int g = lane >> 2;
    const int t = lane & 3;
    const int wm = wid & 1;      // 2 row groups of 16
    const int wn = wid >> 1;     // 8 col groups
    const int q0 = blockIdx.x * 32;
    const int h  = blockIdx.y;
    const int b  = blockIdx.z;

    const size_t kvbase0 = (size_t)(b * NSd) * NTd * Dd + h * DKd;

    // Q loads (512 slots) + stage 0 K/V (4096 slots)
    {
        {
            int arr = tid >> 8, rem = tid & 255;
            int row = rem >> 3, ch = rem & 7;
            const __half* src = (arr == 0 ? qwh : qwl) + (size_t)(b * LQd + q0 + row) * Dd + h * DKd + ch * 8;
            uint32_t dst = (uint32_t)__cvta_generic_to_shared(
                &hsm[(arr == 0 ? W_QH : W_QL) + row * HQS + ch * 8]);
            cp_async16(dst, src, 16);
        }
        const __half* srcs[4] = {kwh, kwl, vwh, vwl};
        #pragma unroll
        for (int i = 0; i < 8; i++) {
            int id = tid + 512 * i;
            int arr = id >> 10, rem = id & 1023;
            int row = rem >> 3, ch = rem & 7;
            const __half* src = srcs[arr] + kvbase0 + (size_t)row * Dd + ch * 8;
            uint32_t dst = (uint32_t)__cvta_generic_to_shared(
                &hsm[W_K0 + arr * W_ARR + row * HQS + ch * 8]);
            cp_async16(dst, src, 16);
        }
        cp_commit();
    }

    float om[4], oc[4];
    #pragma unroll
    for (int j = 0; j < 4; j++) { om[j] = 0.f; oc[j] = 0.f; }

    for (int s = 0; s < NSd; s++) {
        if (s + 1 < NSd) {
            const size_t kvb = (size_t)(b * NSd + s + 1) * NTd * Dd + h * DKd;
            int stb = W_K0 + ((s + 1) & 1) * W_STG;
            const __half* srcs[4] = {kwh, kwl, vwh, vwl};
            #pragma unroll
            for (int i = 0; i < 8; i++) {
                int id = tid + 512 * i;
                int arr = id >> 10, rem = id & 1023;
                int row = rem >> 3, ch = rem & 7;
                const __half* src = srcs[arr] + kvb + (size_t)row * Dd + ch * 8;
                uint32_t dst = (uint32_t)__cvta_generic_to_shared(
                    &hsm[stb + arr * W_ARR + row * HQS + ch * 8]);
                cp_async16(dst, src, 16);
            }
            cp_commit();
            cp_wait<1>();
        } else {
            cp_wait<0>();
        }
        __syncthreads();

        const __half* QH = hsm + W_QH;
        const __half* QL = hsm + W_QL;
        const int stb = W_K0 + (s & 1) * W_STG;
        const __half* KH = hsm + stb;
        const __half* KL = hsm + stb + W_ARR;
        const __half* VH = hsm + stb + 2 * W_ARR;
        const __half* VL = hsm + stb + 3 * W_ARR;

        // ---- P = Q @ K^T (warp tile 16x16, wn covers 8 col groups of 16) ----
        float pm[2][4], pc[2][4];
        #pragma unroll
        for (int nt = 0; nt < 2; nt++)
            #pragma unroll
            for (int j = 0; j < 4; j++) { pm[nt][j] = 0.f; pc[nt][j] = 0.f; }

        #pragma unroll
        for (int ks = 0; ks < 4; ks++) {
            const int kb = ks * 16;
            int r0 = wm * 16 + g;
            uint32_t ah0 = *(const uint32_t*)&QH[r0 * HQS + kb + 2 * t];
            uint32_t ah1 = *(const uint32_t*)&QH[(r0 + 8) * HQS + kb + 2 * t];
            uint32_t ah2 = *(const uint32_t*)&QH[r0 * HQS + kb + 2 * t + 8];
            uint32_t ah3 = *(const uint32_t*)&QH[(r0 + 8) * HQS + kb + 2 * t + 8];
            uint32_t al0 = *(const uint32_t*)&QL[r0 * HQS + kb + 2 * t];
            uint32_t al1 = *(const uint32_t*)&QL[(r0 + 8) * HQS + kb + 2 * t];
            uint32_t al2 = *(const uint32_t*)&QL[r0 * HQS + kb + 2 * t + 8];
            uint32_t al3 = *(const uint32_t*)&QL[(r0 + 8) * HQS + kb + 2 * t + 8];
            #pragma unroll
            for (int nt = 0; nt < 2; nt++) {
                int c = wn * 16 + nt * 8 + g;
                uint32_t bh0 = *(const uint32_t*)&KH[c * HQS + kb + 2 * t];
                uint32_t bh1 = *(const uint32_t*)&KH[c * HQS + kb + 2 * t + 8];
                uint32_t bl0 = *(const uint32_t*)&KL[c * HQS + kb + 2 * t];
                uint32_t bl1 = *(const uint32_t*)&KL[c * HQS + kb + 2 * t + 8];
                mma_f16(pm[nt], ah0, ah1, ah2, ah3, bh0, bh1);
                mma_f16(pc[nt], ah0, ah1, ah2, ah3, bl0, bl1);
                mma_f16(pc[nt], al0, al1, al2, al3, bh0, bh1);
            }
        }
        #pragma unroll
        for (int nt = 0; nt < 2; nt++) {
            int r = wm * 16 + g;
            int c = wn * 16 + nt * 8 + 2 * t;
            *(float2*)&Ps[r * WPPAD + c] = make_float2(pm[nt][0] + pc[nt][0], pm[nt][1] + pc[nt][1]);
            *(float2*)&Ps[(r + 8) * WPPAD + c] = make_float2(pm[nt][2] + pc[nt][2], pm[nt][3] + pc[nt][3]);
        }
        __syncthreads();

        // ---- softmax + bias + attns scale (2 rows per warp) ----
        const float* bb = bias_w + ((size_t)((b * NSd + s) * Hd + h) * LQd + q0) * NTd;
        #pragma unroll
        for (int rr = 0; rr < 2; rr++) {
            int r = wid * 2 + rr;
            float x0 = Ps[r * WPPAD + lane]       + bb[r * NTd + lane];
            float x1 = Ps[r * WPPAD + lane + 32]  + bb[r * NTd + lane + 32];
            float x2 = Ps[r * WPPAD + lane + 64]  + bb[r * NTd + lane + 64];
            float x3 = Ps[r * WPPAD + lane + 96]  + bb[r * NTd + lane + 96];
            float mx = fmaxf(fmaxf(x0, x1), fmaxf(x2, x3));
            #pragma unroll
            for (int o = 16; o; o >>= 1) mx = fmaxf(mx, __shfl_xor_sync(0xffffffffu, mx, o));
            x0 = __expf(x0 - mx); x1 = __expf(x1 - mx);
            x2 = __expf(x2 - mx); x3 = __expf(x3 - mx);
            float su = x0 + x1 + x2 + x3;
            #pragma unroll
            for (int o = 16; o; o >>= 1) su += __shfl_xor_sync(0xffffffffu, su, o);
            float wsc = attns[((size_t)(b * Hd + h) * LQd + q0 + r) * NSd + s] / su;
            __half hi, lo;
            split_h(x0 * wsc, hi, lo); PH[r * HPS + lane] = hi;       PL[r * HPS + lane] = lo;
            split_h(x1 * wsc, hi, lo); PH[r * HPS + lane + 32] = hi;  PL[r * HPS + lane + 32] = lo;
            split_h(x2 * wsc, hi, lo); PH[r * HPS + lane + 64] = hi;  PL[r * HPS + lane + 64] = lo;
            split_h(x3 * wsc, hi, lo); PH[r * HPS + lane + 96] = hi;  PL[r * HPS + lane + 96] = lo;
        }
        __syncthreads();

        // ---- O += P @ V (warp tile 16x8) ----
        #pragma unroll
        for (int ks = 0; ks < 8; ks++) {
            const int kb = ks * 16;
            int r0 = wm * 16 + g;
            uint32_t ph0 = *(const uint32_t*)&PH[r0 * HPS + kb + 2 * t];
            uint32_t ph1 = *(const uint32_t*)&PH[(r0 + 8) * HPS + kb + 2 * t];
            uint32_t ph2 = *(const uint32_t*)&PH[r0 * HPS + kb + 2 * t + 8];
            uint32_t ph3 = *(const uint32_t*)&PH[(r0 + 8) * HPS + kb + 2 * t + 8];
            uint32_t pl0 = *(const uint32_t*)&PL[r0 * HPS + kb + 2 * t];
            uint32_t pl1 = *(const uint32_t*)&PL[(r0 + 8) * HPS + kb + 2 * t];
            uint32_t pl2 = *(const uint32_t*)&PL[r0 * HPS + kb + 2 * t + 8];
            uint32_t pl3 = *(const uint32_t*)&PL[(r0 + 8) * HPS + kb + 2 * t + 8];
            int c = wn * 8 + g;
            int k0r = kb + 2 * t;
            uint32_t bh0 = pack_h2(VH[k0r * HQS + c],        VH[(k0r + 1) * HQS + c]);
            uint32_t bh1 = pack_h2(VH[(k0r + 8) * HQS + c],  VH[(k0r + 9) * HQS + c]);
            uint32_t bl0 = pack_h2(VL[k0r * HQS + c],        VL[(k0r + 1) * HQS + c]);
            uint32_t bl1 = pack_h2(VL[(k0r + 8) * HQS + c],  VL[(k0r + 9) * HQS + c]);
            mma_f16(om, ph0, ph1, ph2, ph3, bh0, bh1);
            mma_f16(oc, ph0, ph1, ph2, ph3, bl0, bl1);
            mma_f16(oc, pl0, pl1, pl2, pl3, bh0, bh1);
        }
        __syncthreads();
    }

    {
        int r = q0 + wm * 16 + g;
        int c = h * DKd + wn * 8 + 2 * t;
        float v0 = om[0] + oc[0], v1 = om[1] + oc[1];
        float v2 = om[2] + oc[2], v3 = om[3] + oc[3];
        __half h0, l0, h1, l1;
        split_h(v0, h0, l0); split_h(v1, h1, l1);
        *(__half2*)&cwh[(size_t)(b * LQd + r) * Dd + c] = __halves2half2(h0, h1);
        *(__half2*)&cwl[(size_t)(b * LQd + r) * Dd + c] = __halves2half2(l0, l1);
        split_h(v2, h0, l0); split_h(v3, h1, l1);
        *(__half2*)&cwh[(size_t)(b * LQd + r + 8) * Dd + c] = __halves2half2(h0, h1);
        *(__half2*)&cwl[(size_t)(b * LQd + r + 8) * Dd + c] = __halves2half2(l0, l1);
    }
}

// ---------------- host ----------------
extern "C" void kernel_launch(void* const* d_in, const int* in_sizes, int n_in,
                              void* d_out, int out_size)
{
    const float* q      = (const float*)d_in[0];
    const float* k_s    = (const float*)d_in[1];
    const float* v_s    = (const float*)d_in[2];
    const float* k_w    = (const float*)d_in[3];
    const float* v_w    = (const float*)d_in[4];
    const float* bias_w = (const float*)d_in[5];
    const float* bias_s = (const float*)d_in[6];
    const float* gab    = (const float*)d_in[7];

    const float *wq_s, *bq_s, *wk_s, *bk_s, *wv_s, *bv_s;
    const float *wq_w, *bq_w, *wk_w, *bk_w, *wv_w, *bv_w;
    const float *fcs_w, *fcs_b, *fcw_w, *fcw_b, *fco_w, *fco_b;

    if (in_sizes[9] == 512) {
        wq_s = (const float*)d_in[8];  bq_s = (const float*)d_in[9];
        wk_s = (const float*)d_in[10]; bk_s = (const float*)d_in[11];
        wv_s = (const float*)d_in[12]; bv_s = (const float*)d_in[13];
        wq_w = (const float*)d_in[14]; bq_w = (const float*)d_in[15];
        wk_w = (const float*)d_in[16]; bk_w = (const float*)d_in[17];
        wv_w = (const float*)d_in[18]; bv_w = (const float*)d_in[19];
        fcs_w = (const float*)d_in[20]; fcs_b = (const float*)d_in[21];
        fcw_w = (const float*)d_in[22]; fcw_b = (const float*)d_in[23];
        fco_w = (const float*)d_in[24]; fco_b = (const float*)d_in[25];
    } else {
        wq_s = (const float*)d_in[8];  wk_s = (const float*)d_in[9];
        wv_s = (const float*)d_in[10]; wq_w = (const float*)d_in[11];
        wk_w = (const float*)d_in[12]; wv_w = (const float*)d_in[13];
        fcs_w = (const float*)d_in[14]; fcw_w = (const float*)d_in[15];
        bq_s = (const float*)d_in[16]; bk_s = (const float*)d_in[17];
        bv_s = (const float*)d_in[18]; bq_w = (const float*)d_in[19];
        bk_w = (const float*)d_in[20]; bv_w = (const float*)d_in[21];
        fcs_b = (const float*)d_in[22]; fcw_b = (const float*)d_in[23];
        fco_w = (const float*)d_in[24]; fco_b = (const float*)d_in[25];
    }

    float* scratch = nullptr;
    cudaGetSymbolAddress((void**)&scratch, g_scratch);
    float* s_qs  = scratch + OFF_QS;
    float* s_ks  = scratch + OFF_KS;
    float* s_vs  = scratch + OFF_VS;
    float* s_att = scratch + OFF_ATT;
    __half* hb = (__half*)(scratch + OFF_HALF);
    __half* acth = hb + H_ACTH;
    __half* actl = hb + H_ACTL;
    __half* wth  = hb + H_WTH;
    __half* wtl  = hb + H_WTL;
    __half* qwh  = hb + H_QWH;
    __half* qwl  = hb + H_QWL;
    __half* kwh  = hb + H_KWH;
    __half* kwl  = hb + H_KWL;
    __half* vwh  = hb + H_VWH;
    __half* vwl  = hb + H_VWL;
    __half* csh  = hb + H_CSH;
    __half* csl  = hb + H_CSL;
    __half* cwh  = hb + H_CWH;
    __half* cwl  = hb + H_CWL;
    __half* cath = hb + H_CATH;
    __half* catl = hb + H_CATL;

    cudaFuncSetAttribute(gemm_cfg, cudaFuncAttributeMaxDynamicSharedMemorySize, HSMEM_BYTES);
    cudaFuncSetAttribute(word_attn_h2, cudaFuncAttributeMaxDynamicSharedMemorySize, WSMEM_BYTES);

    // prep
    ASplitArgs aa;
    aa.src[0] = q; aa.src[1] = k_s; aa.src[2] = v_s; aa.src[3] = k_w; aa.src[4] = v_w;
    act_split<<<dim3(256, 5), 256>>>(aa, acth, actl);
    WSplitArgs wa;
    wa.src[0] = wq_s; wa.src[1] = wk_s; wa.src[2] = wv_s;
    wa.src[3] = wq_w; wa.src[4] = wk_w; wa.src[5] = wv_w;
    wa.src[6] = fcs_w; wa.src[7] = fcw_w; wa.src[8] = fco_w;
    w_transplit<<<dim3(16, 32, 9), dim3(32, 8)>>>(wa, wth, wtl);

    // merged projections
    {
        GemmCfg c = {};
        c.K = 512; c.ldc = 512;
        c.Ah[0] = acth + AQ;  c.Al[0] = actl + AQ;
        c.Ah[1] = acth + AQ;  c.Al[1] = actl + AQ;
        c.Ah[2] = acth + AKS; c.Al[2] = actl + AKS;
        c.Ah[3] = acth + AVS; c.Al[3] = actl + AVS;
        c.Bh[0] = wth + WOFF(0); c.Bl[0] = wtl + WOFF(0);
        c.Bh[1] = wth + WOFF(3); c.Bl[1] = wtl + WOFF(3);
        c.Bh[2] = wth + WOFF(1); c.Bl[2] = wtl + WOFF(1);
        c.Bh[3] = wth + WOFF(2); c.Bl[3] = wtl + WOFF(2);
        c.bias[0] = bq_s; c.bias[1] = bq_w; c.bias[2] = bk_s; c.bias[3] = bv_s;
        c.bscale[0] = 1.f; c.bscale[1] = 0.125f; c.bscale[2] = 1.f; c.bscale[3] = 1.f;
        c.M[0] = 1024; c.M[1] = 1024; c.M[2] = 96; c.M[3] = 96;
        c.mode[0] = 0; c.mode[1] = 1; c.mode[2] = 0; c.mode[3] = 0;
        c.Cf[0] = s_qs; c.Cf[2] = s_ks; c.Cf[3] = s_vs;
        c.Ch[1] = qwh;  c.Cl[1] = qwl;
        gemm_cfg<<<dim3(8, 8, 4), 256, HSMEM_BYTES>>>(c);
    }
    // big word projections
    {
        GemmCfg c = {};
        c.K = 512; c.ldc = 512;
        c.Ah[0] = acth + AKW; c.Al[0] = actl + AKW;
        c.Ah[1] = acth + AVW; c.Al[1] = actl + AVW;
        c.Bh[0] = wth + WOFF(4); c.Bl[0] = wtl + WOFF(4);
        c.Bh[1] = wth + WOFF(5); c.Bl[1] = wtl + WOFF(5);
        c.bias[0] = bk_w; c.bias[1] = bv_w;
        c.bscale[0] = 1.f; c.bscale[1] = 1.f;
        c.M[0] = 12288; c.M[1] = 12288;
        c.mode[0] = 1; c.mode[1] = 1;
        c.Ch[0] = kwh; c.Cl[0] = kwl;
        c.Ch[1] = vwh; c.Cl[1] = vwl;
        gemm_cfg<<<dim3(8, 96, 2), 256, HSMEM_BYTES>>>(c);
    }

    sent_attn<<<dim3(Hd, BB), 256>>>(s_qs, s_ks, s_vs, bias_s, gab, s_att, csh, csl);

    word_attn_h2<<<dim3(8, Hd, BB), 512, WSMEM_BYTES>>>(
        qwh, qwl, kwh, kwl, vwh, vwl, bias_w, s_att, cwh, cwl);

    // fcs / fcw -> split cat
    {
        GemmCfg c = {};
        c.K = 512; c.ldc = 1024;
        c.Ah[0] = csh; c.Al[0] = csl;
        c.Ah[1] = cwh; c.Al[1] = cwl;
        c.Bh[0] = wth + WOFF(6); c.Bl[0] = wtl + WOFF(6);
        c.Bh[1] = wth + WOFF(7); c.Bl[1] = wtl + WOFF(7);
        c.bias[0] = fcs_b; c.bias[1] = fcw_b;
        c.bscale[0] = 1.f; c.bscale[1] = 1.f;
        c.M[0] = 1024; c.M[1] = 1024;
        c.mode[0] = 1; c.mode[1] = 1;
        c.Ch[0] = cath;       c.Cl[0] = catl;
        c.Ch[1] = cath + 512; c.Cl[1] = catl + 512;
        gemm_cfg<<<dim3(8, 8, 2), 256, HSMEM_BYTES>>>(c);
    }
    // final fco -> fp32 out
    {
        GemmCfg c = {};
        c.K = 1024; c.ldc = 512;
        c.Ah[0] = cath; c.Al[0] = catl;
        c.Bh[0] = wth + WOFF(8); c.Bl[0] = wtl + WOFF(8);
        c.bias[0] = fco_b;
        c.bscale[0] = 1.f;
        c.M[0] = 1024;
        c.mode[0] = 0;
        c.Cf[0] = (float*)d_out;
        gemm_cfg<<<dim3(8, 8, 1), 256, HSMEM_BYTES>>>(c);
    }
}

// round 9
// speedup vs baseline: 1.6665x; 1.0687x over previous
#include <cuda_runtime.h>
#include <cuda_fp16.h>
#include <math.h>
#include <stdint.h>

// Problem constants
#define BB   4
#define LQd  256
#define NSd  24
#define NTd  128
#define Dd   512
#define Hd   8
#define DKd  64

// ---------------- scratch layout ----------------
#define OFF_QS   0
#define OFF_KS   524288
#define OFF_VS   573440
#define OFF_ATT  622592
#define OFF_HALF 819200
#define H_ACTH 0
#define H_ACTL 13205504
#define H_WTH  26411008
#define H_WTL  29032448
#define H_QWH  31653888
#define H_QWL  32178176
#define H_KWH  32702464
#define H_KWL  38993920
#define H_VWH  45285376
#define H_VWL  51576832
#define H_CSH  57868288
#define H_CSL  58392576
#define H_CWH  58916864
#define H_CWL  59441152
#define H_CATH 59965440
#define H_CATL 61014016
#define H_TOTAL 62062592
#define SCRATCH_TOTAL (OFF_HALF + H_TOTAL / 2)
__device__ float g_scratch[SCRATCH_TOTAL];

#define AQ   0
#define AKS  524288
#define AVS  573440
#define AKW  622592
#define AVW  6914048
#define WOFF(i) ((i) * 262144)

// ---------------- helpers ----------------
__device__ __forceinline__ void split_h(float x, __half& hi, __half& lo) {
    hi = __float2half_rn(x);
    lo = __float2half_rn(x - __half2float(hi));
}
__device__ __forceinline__ uint32_t pack_h2(__half a, __half b) {
    return (uint32_t)__half_as_ushort(a) | ((uint32_t)__half_as_ushort(b) << 16);
}
__device__ __forceinline__ void mma_f16(float d[4],
                                        uint32_t a0, uint32_t a1, uint32_t a2, uint32_t a3,
                                        uint32_t b0, uint32_t b1) {
    asm volatile(
        "mma.sync.aligned.m16n8k16.row.col.f32.f16.f16.f32 "
        "{%0,%1,%2,%3},{%4,%5,%6,%7},{%8,%9},{%0,%1,%2,%3};"
        : "+f"(d[0]), "+f"(d[1]), "+f"(d[2]), "+f"(d[3])
        : "r"(a0), "r"(a1), "r"(a2), "r"(a3), "r"(b0), "r"(b1));
}
__device__ __forceinline__ void cp_async16(uint32_t smem_addr, const void* gptr, int src_bytes) {
    asm volatile("cp.async.cg.shared.global [%0], [%1], 16, %2;"
                 :: "r"(smem_addr), "l"(gptr), "r"(src_bytes) : "memory");
}
__device__ __forceinline__ void cp_commit() { asm volatile("cp.async.commit_group;" ::: "memory"); }
template <int N>
__device__ __forceinline__ void cp_wait() { asm volatile("cp.async.wait_group %0;" :: "n"(N) : "memory"); }

// ---------------- prep: split activations ----------------
struct ASplitArgs { const float* src[5]; };
__constant__ int c_alen[5] = {524288, 49152, 49152, 6291456, 6291456};
__constant__ int c_aoff[5] = {AQ, AKS, AVS, AKW, AVW};

__global__ __launch_bounds__(256) void act_split(ASplitArgs args, __half* acth, __half* actl)
{
    int z = blockIdx.y;
    int n = c_alen[z];
    const float* s = args.src[z];
    __half* dh = acth + c_aoff[z];
    __half* dl = actl + c_aoff[z];
    for (int i = blockIdx.x * 256 + threadIdx.x; i < n; i += gridDim.x * 256) {
        __half hi, lo;
        split_h(s[i], hi, lo);
        dh[i] = hi;
        dl[i] = lo;
    }
}

// ---------------- prep: transpose+split weights ----------------
struct WSplitArgs { const float* src[9]; };
__constant__ int c_wK[9] = {512, 512, 512, 512, 512, 512, 512, 512, 1024};
__constant__ int c_woff[9] = {WOFF(0), WOFF(1), WOFF(2), WOFF(3), WOFF(4),
                              WOFF(5), WOFF(6), WOFF(7), WOFF(8)};
__constant__ float c_wscale[9] = {1.f, 1.f, 1.f, 0.125f, 1.f, 1.f, 1.f, 1.f, 1.f};

__global__ void w_transplit(WSplitArgs args, __half* wth, __half* wtl)
{
    int z = blockIdx.z;
    int Kw = c_wK[z];
    int k0 = blockIdx.y * 32;
    if (k0 >= Kw) return;
    int n0 = blockIdx.x * 32;
    const float* W = args.src[z];
    float sc = c_wscale[z];
    __half* th = wth + c_woff[z];
    __half* tl = wtl + c_woff[z];

    __shared__ float ts[32][33];
    int tx = threadIdx.x, ty = threadIdx.y;
    #pragma unroll
    for (int r = 0; r < 4; r++)
        ts[ty + 8 * r][tx] = W[(size_t)(k0 + ty + 8 * r) * 512 + n0 + tx];
    __syncthreads();
    #pragma unroll
    for (int r = 0; r < 4; r++) {
        int n = n0 + ty + 8 * r;
        int k = k0 + tx;
        __half hi, lo;
        split_h(sc * ts[tx][ty + 8 * r], hi, lo);
        th[(size_t)n * Kw + k] = hi;
        tl[(size_t)n * Kw + k] = lo;
    }
}

// ---------------- split-FP16 GEMM: 128x64 tile, 256 threads, 2 CTAs/SM ----------------
#define HAS 40
#define G_A 128
#define G_B 64
#define HSTAGE ((2 * G_A + 2 * G_B) * HAS)
#define HSMEM_BYTES (2 * HSTAGE * 2)

struct GemmCfg {
    const __half* Ah[4]; const __half* Al[4];
    const __half* Bh[4]; const __half* Bl[4];
    const float* bias[4];
    float* Cf[4];
    __half* Ch[4]; __half* Cl[4];
    int M[4]; int mode[4]; float bscale[4];
    int K; int ldc;
};

__global__ __launch_bounds__(256, 2) void gemm_cfg(GemmCfg cfg)
{
    extern __shared__ __half hsm[];

    const int z = blockIdx.z;
    const int M = cfg.M[z];
    const int row0 = blockIdx.y * 128;
    if (row0 >= M) return;

    const __half* Ah_g = cfg.Ah[z];
    const __half* Al_g = cfg.Al[z];
    const __half* Bh_g = cfg.Bh[z];
    const __half* Bl_g = cfg.Bl[z];
    const float* bias  = cfg.bias[z];
    const int mode     = cfg.mode[z];
    const float bsc    = cfg.bscale[z];
    const int K        = cfg.K;
    const int ldc      = cfg.ldc;

    const int tid = threadIdx.x;
    const int wid = tid >> 5;
    const int lane = tid & 31;
    const int g = lane >> 2;
    const int t = lane & 3;
    const int wm = wid & 3;
    const int wn = wid >> 2;
    const int col0 = blockIdx.x * 64;

    float dm[2][4][4], dc[2][4][4];
    #pragma unroll
    for (int mt = 0; mt < 2; mt++)
        #pragma unroll
        for (int nt = 0; nt < 4; nt++)
            #pragma unroll
            for (int j = 0; j < 4; j++) { dm[mt][nt][j] = 0.f; dc[mt][nt][j] = 0.f; }

    const int ktiles = K >> 5;

    {
        __half* Ahs = hsm;
        __half* Als = Ahs + G_A * HAS;
        __half* Bhs = Als + G_A * HAS;
        __half* Bls = Bhs + G_B * HAS;
        #pragma unroll
        for (int i = 0; i < 4; i++) {
            int id = tid + 256 * i;
            int arr = id >> 9, rem = id & 511;
            int row = rem >> 2, ch = rem & 3;
            int r = row0 + row;
            int rc = r < M ? r : (M - 1);
            int pb = r < M ? 16 : 0;
            const __half* src = (arr ? Al_g : Ah_g) + (size_t)rc * K + ch * 8;
            __half* dst = (arr ? Als : Ahs) + row * HAS + ch * 8;
            cp_async16((uint32_t)__cvta_generic_to_shared(dst), src, pb);
        }
        #pragma unroll
        for (int i = 0; i < 2; i++) {
            int id = tid + 256 * i;
            int arr = id >> 8, rem = id & 255;
            int row = rem >> 2, ch = rem & 3;
            const __half* src = (arr ? Bl_g : Bh_g) + (size_t)(col0 + row) * K + ch * 8;
            __half* dst = (arr ? Bls : Bhs) + row * HAS + ch * 8;
            cp_async16((uint32_t)__cvta_generic_to_shared(dst), src, 16);
        }
        cp_commit();
    }

    for (int kt = 0; kt < ktiles; kt++) {
        if (kt + 1 < ktiles) {
            __half* Ahs = hsm + ((kt + 1) & 1) * HSTAGE;
            __half* Als = Ahs + G_A * HAS;
            __half* Bhs = Als + G_A * HAS;
            __half* Bls = Bhs + G_B * HAS;
            int k0 = (kt + 1) << 5;
            #pragma unroll
            for (int i = 0; i < 4; i++) {
                int id = tid + 256 * i;
                int arr = id >> 9, rem = id & 511;
                int row = rem >> 2, ch = rem & 3;
                int r = row0 + row;
                int rc = r < M ? r : (M - 1);
                int pb = r < M ? 16 : 0;
                const __half* src = (arr ? Al_g : Ah_g) + (size_t)rc * K + k0 + ch * 8;
                __half* dst = (arr ? Als : Ahs) + row * HAS + ch * 8;
                cp_async16((uint32_t)__cvta_generic_to_shared(dst), src, pb);
            }
            #pragma unroll
            for (int i = 0; i < 2; i++) {
                int id = tid + 256 * i;
                int arr = id >> 8, rem = id & 255;
                int row = rem >> 2, ch = rem & 3;
                const __half* src = (arr ? Bl_g : Bh_g) + (size_t)(col0 + row) * K + k0 + ch * 8;
                __half* dst = (arr ? Bls : Bhs) + row * HAS + ch * 8;
                cp_async16((uint32_t)__cvta_generic_to_shared(dst), src, 16);
            }
            cp_commit();
            cp_wait<1>();
        } else {
            cp_wait<0>();
        }
        __syncthreads();

        const __half* Ahs = hsm + (kt & 1) * HSTAGE;
        const __half* Als = Ahs + G_A * HAS;
        const __half* Bhs = Als + G_A * HAS;
        const __half* Bls = Bhs + G_B * HAS;

        #pragma unroll
        for (int ks = 0; ks < 2; ks++) {
            const int kb = ks * 16;
            uint32_t ah[2][4], al[2][4];
            #pragma unroll
            for (int mt = 0; mt < 2; mt++) {
                int r0 = wm * 32 + mt * 16 + g;
                ah[mt][0] = *(const uint32_t*)&Ahs[r0 * HAS + kb + 2 * t];
                ah[mt][1] = *(const uint32_t*)&Ahs[(r0 + 8) * HAS + kb + 2 * t];
                ah[mt][2] = *(const uint32_t*)&Ahs[r0 * HAS + kb + 2 * t + 8];
                ah[mt][3] = *(const uint32_t*)&Ahs[(r0 + 8) * HAS + kb + 2 * t + 8];
                al[mt][0] = *(const uint32_t*)&Als[r0 * HAS + kb + 2 * t];
                al[mt][1] = *(const uint32_t*)&Als[(r0 + 8) * HAS + kb + 2 * t];
                al[mt][2] = *(const uint32_t*)&Als[r0 * HAS + kb + 2 * t + 8];
                al[mt][3] = *(const uint32_t*)&Als[(r0 + 8) * HAS + kb + 2 * t + 8];
            }
            #pragma unroll
            for (int nt = 0; nt < 4; nt++) {
                int c = wn * 32 + nt * 8 + g;
                uint32_t bh0 = *(const uint32_t*)&Bhs[c * HAS + kb + 2 * t];
                uint32_t bh1 = *(const uint32_t*)&Bhs[c * HAS + kb + 2 * t + 8];
                uint32_t bl0 = *(const uint32_t*)&Bls[c * HAS + kb + 2 * t];
                uint32_t bl1 = *(const uint32_t*)&Bls[c * HAS + kb + 2 * t + 8];
                #pragma unroll
                for (int mt = 0; mt < 2; mt++) {
                    mma_f16(dm[mt][nt], ah[mt][0], ah[mt][1], ah[mt][2], ah[mt][3], bh0, bh1);
                    mma_f16(dc[mt][nt], ah[mt][0], ah[mt][1], ah[mt][2], ah[mt][3], bl0, bl1);
                    mma_f16(dc[mt][nt], al[mt][0], al[mt][1], al[mt][2], al[mt][3], bh0, bh1);
                }
            }
        }
        __syncthreads();
    }

    #pragma unroll
    for (int mt = 0; mt < 2; mt++) {
        #pragma unroll
        for (int nt = 0; nt < 4; nt++) {
            int r = row0 + wm * 32 + mt * 16 + g;
            int c = col0 + wn * 32 + nt * 8 + 2 * t;
            float2 bz = *(const float2*)&bias[c];
            float o0 = dm[mt][nt][0] + dc[mt][nt][0] + bsc * bz.x;
            float o1 = dm[mt][nt][1] + dc[mt][nt][1] + bsc * bz.y;
            float o2 = dm[mt][nt][2] + dc[mt][nt][2] + bsc * bz.x;
            float o3 = dm[mt][nt][3] + dc[mt][nt][3] + bsc * bz.y;
            if (mode == 0) {
                float* Cf = cfg.Cf[z];
                if (r < M)     *(float2*)&Cf[(size_t)r * ldc + c] = make_float2(o0, o1);
                if (r + 8 < M) *(float2*)&Cf[(size_t)(r + 8) * ldc + c] = make_float2(o2, o3);
            } else {
                __half* Ch = cfg.Ch[z];
                __half* Cl = cfg.Cl[z];
                __half h0, l0, h1, l1;
                if (r < M) {
                    split_h(o0, h0, l0); split_h(o1, h1, l1);
                    *(__half2*)&Ch[(size_t)r * ldc + c] = __halves2half2(h0, h1);
                    *(__half2*)&Cl[(size_t)r * ldc + c] = __halves2half2(l0, l1);
                }
                if (r + 8 < M) {
                    split_h(o2, h0, l0); split_h(o3, h1, l1);
                    *(__half2*)&Ch[(size_t)(r + 8) * ldc + c] = __halves2half2(h0, h1);
                    *(__half2*)&Cl[(size_t)(r + 8) * ldc + c] = __halves2half2(l0, l1);
                }
            }
        }
    }
}

// ---------------- sentence-level graph attention ----------------
__global__ __launch_bounds__(256) void sent_attn(
    const float* __restrict__ qs, const float* __restrict__ ksn,
    const float* __restrict__ vsn, const float* __restrict__ bias_s,
    const float* __restrict__ gab,
    float* __restrict__ attns_out,
    __half* __restrict__ csh, __half* __restrict__ csl)
{
    const int h = blockIdx.x, b = blockIdx.y;
    const int q = threadIdx.x;

    __shared__ float Ks[NSd][DKd + 1];
    __shared__ float Vs[NSd][DKd + 1];
    __shared__ float G[NSd][NSd + 1];

    for (int idx = q; idx < NSd * DKd; idx += 256) {
        int s = idx >> 6, k = idx & 63;
        Ks[s][k] = ksn[(size_t)(b * NSd + s) * Dd + h * DKd + k];
        Vs[s][k] = vsn[(size_t)(b * NSd + s) * Dd + h * DKd + k];
    }
    for (int idx = q; idx < NSd * NSd; idx += 256) {
        int s = idx / NSd, tt = idx % NSd;
        G[s][tt] = gab[((size_t)(b * Hd + h) * NSd + s) * NSd + tt];
    }
    __syncthreads();

    float qreg[DKd];
    const float* qrow = qs + (size_t)(b * LQd + q) * Dd + h * DKd;
    #pragma unroll
    for (int k = 0; k < DKd; k++) qreg[k] = qrow[k] * 0.125f;

    float a[NSd];
    const float* bsrow = bias_s + ((size_t)(b * Hd + h) * LQd + q) * NSd;
    #pragma unroll
    for (int s = 0; s < NSd; s++) {
        float dd = 0.f;
        #pragma unroll
        for (int k = 0; k < DKd; k++) dd += qreg[k] * Ks[s][k];
        a[s] = dd + bsrow[s];
    }

    float m = -1e30f;
    #pragma unroll
    for (int s = 0; s < NSd; s++) m = fmaxf(m, a[s]);
    float smx[NSd]; float sum = 0.f;
    #pragma unroll
    for (int s = 0; s < NSd; s++) { smx[s] = __expf(a[s] - m); sum += smx[s]; }
    float inv = 1.f / sum;

    float gg[NSd];
    #pragma unroll
    for (int tt = 0; tt < NSd; tt++) {
        float dd = 0.f;
        #pragma unroll
        for (int s = 0; s < NSd; s++) dd += smx[s] * G[s][tt];
        gg[tt] = dd * inv;
    }
    #pragma unroll
    for (int s = 0; s < NSd; s++) a[s] -= 0.5f * gg[s] * gg[s];

    m = -1e30f;
    #pragma unroll
    for (int s = 0; s < NSd; s++) m = fmaxf(m, a[s]);
    sum = 0.f;
    #pragma unroll
    for (int s = 0; s < NSd; s++) { a[s] = __expf(a[s] - m); sum += a[s]; }
    inv = 1.f / sum;

    float* arow = attns_out + ((size_t)(b * Hd + h) * LQd + q) * NSd;
    #pragma unroll
    for (int s = 0; s < NSd; s++) { a[s] *= inv; arow[s] = a[s]; }

    size_t cbase = (size_t)(b * LQd + q) * Dd + h * DKd;
    #pragma unroll
    for (int dd = 0; dd < DKd; dd++) {
        float acc = 0.f;
        #pragma unroll
        for (int s = 0; s < NSd; s++) acc += a[s] * Vs[s][dd];
        __half hi, lo;
        split_h(acc, hi, lo);
        csh[cbase + dd] = hi;
        csl[cbase + dd] = lo;
    }
}

// ---------------- word-level attention v3: single stage, 2 CTAs/SM ----------------
// smem (halves): QH[32][72], QL[32][72], KH/KL/VH/VL[128][72],
// P union: 32 rows x 264 halves (row r: PH [0,128), PL [128,256), shared w/ Ps fp32 [r*132..])
#define HQS 72
#define W_QH 0
#define W_QL (32 * HQS)
#define W_KV (2 * 32 * HQS)
#define W_ARR (128 * HQS)
#define W_P  (W_KV + 4 * W_ARR)          // 41472 halves
#define PROW 264                          // union row stride in halves (= 132 floats)
#define WSMEM_BYTES ((W_P + 32 * PROW) * 2)   // 99840 B

__global__ __launch_bounds__(512, 2) void word_attn_h3(
    const __half* __restrict__ qwh, const __half* __restrict__ qwl,
    const __half* __restrict__ kwh, const __half* __restrict__ kwl,
    const __half* __restrict__ vwh, const __half* __restrict__ vwl,
    const float* __restrict__ bias_w, const float* __restrict__ attns,
    __half* __restrict__ cwh, __half* __restrict__ cwl)
{
    extern __shared__ __half hsm[];
    float* Ps = (float*)(hsm + W_P);      // rows of 132 floats
    __half* PU = hsm + W_P;               // rows of 264 halves: [0,128)=PH, [128,256)=PL

    const int tid = threadIdx.x;
    const int wid = tid >> 5;
    const int lane = tid & 31;
    const int g = lane >> 2;
    const int t = lane & 3;
    const int wm = wid & 1;
    const int wn = wid >> 1;
    const int q0 = blockIdx.x * 32;
    const int h  = blockIdx.y;
    const int b  = blockIdx.z;

    // issue Q + stage-0 K/V loads
    {
        {
            int arr = tid >> 8, rem = tid & 255;
            int row = rem >> 3, ch = rem & 7;
            const __half* src = (arr == 0 ? qwh : qwl) + (size_t)(b * LQd + q0 + row) * Dd + h * DKd + ch * 8;
            uint32_t dst = (uint32_t)__cvta_generic_to_shared(
                &hsm[(arr == 0 ? W_QH : W_QL) + row * HQS + ch * 8]);
            cp_async16(dst, src, 16);
        }
        const size_t kvb = (size_t)(b * NSd) * NTd * Dd + h * DKd;
        const __half* srcs[4] = {kwh, kwl, vwh, vwl};
        #pragma unroll
        for (int i = 0; i < 8; i++) {
            int id = tid + 512 * i;
            int arr = id >> 10, rem = id & 1023;
            int row = rem >> 3, ch = rem & 7;
            const __half* src = srcs[arr] + kvb + (size_t)row * Dd + ch * 8;
            uint32_t dst = (uint32_t)__cvta_generic_to_shared(
                &hsm[W_KV + arr * W_ARR + row * HQS + ch * 8]);
            cp_async16(dst, src, 16);
        }
        cp_commit();
        cp_wait<0>();
    }
    __syncthreads();

    float om[4], oc[4];
    #pragma unroll
    for (int j = 0; j < 4; j++) { om[j] = 0.f; oc[j] = 0.f; }

    const __half* QH = hsm + W_QH;
    const __half* QL = hsm + W_QL;
    const __half* KH = hsm + W_KV;
    const __half* KL = hsm + W_KV + W_ARR;
    const __half* VH = hsm + W_KV + 2 * W_ARR;
    const __half* VL = hsm + W_KV + 3 * W_ARR;

    for (int s = 0; s < NSd; s++) {
        // ---- P = Q @ K^T (warp tile 16x16) ----
        float pm[2][4], pc[2][4];
        #pragma unroll
        for (int nt = 0; nt < 2; nt++)
            #pragma unroll
            for (int j = 0; j < 4; j++) { pm[nt][j] = 0.f; pc[nt][j] = 0.f; }

        #pragma unroll
        for (int ks = 0; ks < 4; ks++) {
            const int kb = ks * 16;
            int r0 = wm * 16 + g;
            uint32_t ah0 = *(const uint32_t*)&QH[r0 * HQS + kb + 2 * t];
            uint32_t ah1 = *(const uint32_t*)&QH[(r0 + 8) * HQS + kb + 2 * t];
            uint32_t ah2 = *(const uint32_t*)&QH[r0 * HQS + kb + 2 * t + 8];
            uint32_t ah3 = *(const uint32_t*)&QH[(r0 + 8) * HQS + kb + 2 * t + 8];
            uint32_t al0 = *(const uint32_t*)&QL[r0 * HQS + kb + 2 * t];
            uint32_t al1 = *(const uint32_t*)&QL[(r0 + 8) * HQS + kb + 2 * t];
            uint32_t al2 = *(const uint32_t*)&QL[r0 * HQS + kb + 2 * t + 8];
            uint32_t al3 = *(const uint32_t*)&QL[(r0 + 8) * HQS + kb + 2 * t + 8];
            #pragma unroll
            for (int nt = 0; nt < 2; nt++) {
                int c = wn * 16 + nt * 8 + g;
                uint32_t bh0 = *(const uint32_t*)&KH[c * HQS + kb + 2 * t];
                uint32_t bh1 = *(const uint32_t*)&KH[c * HQS + kb + 2 * t + 8];
                uint32_t bl0 = *(const uint32_t*)&KL[c * HQS + kb + 2 * t];
                uint32_t bl1 = *(const uint32_t*)&KL[c * HQS + kb + 2 * t + 8];
                mma_f16(pm[nt], ah0, ah1, ah2, ah3, bh0, bh1);
                mma_f16(pc[nt], ah0, ah1, ah2, ah3, bl0, bl1);
                mma_f16(pc[nt], al0, al1, al2, al3, bh0, bh1);
            }
        }
        #pragma unroll
        for (int nt = 0; nt < 2; nt++) {
            int r = wm * 16 + g;
            int c = wn * 16 + nt * 8 + 2 * t;
            *(float2*)&Ps[r * 132 + c] = make_float2(pm[nt][0] + pc[nt][0], pm[nt][1] + pc[nt][1]);
            *(float2*)&Ps[(r + 8) * 132 + c] = make_float2(pm[nt][2] + pc[nt][2], pm[nt][3] + pc[nt][3]);
        }
        __syncthreads();

        // ---- softmax + bias + attns scale; write split-fp16 into union rows ----
        const float* bb = bias_w + ((size_t)((b * NSd + s) * Hd + h) * LQd + q0) * NTd;
        #pragma unroll
        for (int rr = 0; rr < 2; rr++) {
            int r = wid * 2 + rr;
            float x0 = Ps[r * 132 + lane]       + bb[r * NTd + lane];
            float x1 = Ps[r * 132 + lane + 32]  + bb[r * NTd + lane + 32];
            float x2 = Ps[r * 132 + lane + 64]  + bb[r * NTd + lane + 64];
            float x3 = Ps[r * 132 + lane + 96]  + bb[r * NTd + lane + 96];
            float mx = fmaxf(fmaxf(x0, x1), fmaxf(x2, x3));
            #pragma unroll
            for (int o = 16; o; o >>= 1) mx = fmaxf(mx, __shfl_xor_sync(0xffffffffu, mx, o));
            x0 = __expf(x0 - mx); x1 = __expf(x1 - mx);
            x2 = __expf(x2 - mx); x3 = __expf(x3 - mx);
            float su = x0 + x1 + x2 + x3;
            #pragma unroll
            for (int o = 16; o; o >>= 1) su += __shfl_xor_sync(0xffffffffu, su, o);
            float wsc = attns[((size_t)(b * Hd + h) * LQd + q0 + r) * NSd + s] / su;
            __half h0, l0, h1, l1, h2, l2, h3, l3;
            split_h(x0 * wsc, h0, l0);
            split_h(x1 * wsc, h1, l1);
            split_h(x2 * wsc, h2, l2);
            split_h(x3 * wsc, h3, l3);
            __syncwarp();   // whole row read before overwrite (union aliasing)
            __half* prow = PU + r * PROW;
            prow[lane]       = h0;  prow[128 + lane]       = l0;
            prow[lane + 32]  = h1;  prow[128 + lane + 32]  = l1;
            prow[lane + 64]  = h2;  prow[128 + lane + 64]  = l2;
            prow[lane + 96]  = h3;  prow[128 + lane + 96]  = l3;
        }
        __syncthreads();

        // ---- O += P @ V (warp tile 16x8) ----
        #pragma unroll
        for (int ks = 0; ks < 8; ks++) {
            const int kb = ks * 16;
            int r0 = wm * 16 + g;
            uint32_t ph0 = *(const uint32_t*)&PU[r0 * PROW + kb + 2 * t];
            uint32_t ph1 = *(const uint32_t*)&PU[(r0 + 8) * PROW + kb + 2 * t];
            uint32_t ph2 = *(const uint32_t*)&PU[r0 * PROW + kb + 2 * t + 8];
            uint32_t ph3 = *(const uint32_t*)&PU[(r0 + 8) * PROW + kb + 2 * t + 8];
            uint32_t pl0 = *(const uint32_t*)&PU[r0 * PROW + 128 + kb + 2 * t];
            uint32_t pl1 = *(const uint32_t*)&PU[(r0 + 8) * PROW + 128 + kb + 2 * t];
            uint32_t pl2 = *(const uint32_t*)&PU[r0 * PROW + 128 + kb + 2 * t + 8];
            uint32_t pl3 = *(const uint32_t*)&PU[(r0 + 8) * PROW + 128 + kb + 2 * t + 8];
            int c = wn * 8 + g;
            int k0r = kb + 2 * t;
            uint32_t bh0 = pack_h2(VH[k0r * HQS + c],        VH[(k0r + 1) * HQS + c]);
            uint32_t bh1 = pack_h2(VH[(k0r + 8) * HQS + c],  VH[(k0r + 9) * HQS + c]);
            uint32_t bl0 = pack_h2(VL[k0r * HQS + c],        VL[(k0r + 1) * HQS + c]);
            uint32_t bl1 = pack_h2(VL[(k0r + 8) * HQS + c],  VL[(k0r + 9) * HQS + c]);
            mma_f16(om, ph0, ph1, ph2, ph3, bh0, bh1);
            mma_f16(oc, ph0, ph1, ph2, ph3, bl0, bl1);
            mma_f16(oc, pl0, pl1, pl2, pl3, bh0, bh1);
        }

        // load next K/V stage (single buffer: sync, issue, wait, sync)
        if (s + 1 < NSd) {
            __syncthreads();   // everyone done reading K/V + P of stage s
            const size_t kvb = (size_t)(b * NSd + s + 1) * NTd * Dd + h * DKd;
            const __half* srcs[4] = {kwh, kwl, vwh, vwl};
            #pragma unroll
            for (int i = 0; i < 8; i++) {
                int id = tid + 512 * i;
                int arr = id >> 10, rem = id & 1023;
                int row = rem >> 3, ch = rem & 7;
                const __half* src = srcs[arr] + kvb + (size_t)row * Dd + ch * 8;
                uint32_t dst = (uint32_t)__cvta_generic_to_shared(
                    &hsm[W_KV + arr * W_ARR + row * HQS + ch * 8]);
                cp_async16(dst, src, 16);
            }
            cp_commit();
            cp_wait<0>();
            __syncthreads();
        }
    }

    {
        int r = q0 + wm * 16 + g;
        int c = h * DKd + wn * 8 + 2 * t;
        float v0 = om[0] + oc[0], v1 = om[1] + oc[1];
        float v2 = om[2] + oc[2], v3 = om[3] + oc[3];
        __half h0, l0, h1, l1;
        split_h(v0, h0, l0); split_h(v1, h1, l1);
        *(__half2*)&cwh[(size_t)(b * LQd + r) * Dd + c] = __halves2half2(h0, h1);
        *(__half2*)&cwl[(size_t)(b * LQd + r) * Dd + c] = __halves2half2(l0, l1);
        split_h(v2, h0, l0); split_h(v3, h1, l1);
        *(__half2*)&cwh[(size_t)(b * LQd + r + 8) * Dd + c] = __halves2half2(h0, h1);
        *(__half2*)&cwl[(size_t)(b * LQd + r + 8) * Dd + c] = __halves2half2(l0, l1);
    }
}

// ---------------- host ----------------
extern "C" void kernel_launch(void* const* d_in, const int* in_sizes, int n_in,
                              void* d_out, int out_size)
{
    const float* q      = (const float*)d_in[0];
    const float* k_s    = (const float*)d_in[1];
    const float* v_s    = (const float*)d_in[2];
    const float* k_w    = (const float*)d_in[3];
    const float* v_w    = (const float*)d_in[4];
    const float* bias_w = (const float*)d_in[5];
    const float* bias_s = (const float*)d_in[6];
    const float* gab    = (const float*)d_in[7];

    const float *wq_s, *bq_s, *wk_s, *bk_s, *wv_s, *bv_s;
    const float *wq_w, *bq_w, *wk_w, *bk_w, *wv_w, *bv_w;
    const float *fcs_w, *fcs_b, *fcw_w, *fcw_b, *fco_w, *fco_b;

    if (in_sizes[9] == 512) {
        wq_s = (const float*)d_in[8];  bq_s = (const float*)d_in[9];
        wk_s = (const float*)d_in[10]; bk_s = (const float*)d_in[11];
        wv_s = (const float*)d_in[12]; bv_s = (const float*)d_in[13];
        wq_w = (const float*)d_in[14]; bq_w = (const float*)d_in[15];
        wk_w = (const float*)d_in[16]; bk_w = (const float*)d_in[17];
        wv_w = (const float*)d_in[18]; bv_w = (const float*)d_in[19];
        fcs_w = (const float*)d_in[20]; fcs_b = (const float*)d_in[21];
        fcw_w = (const float*)d_in[22]; fcw_b = (const float*)d_in[23];
        fco_w = (const float*)d_in[24]; fco_b = (const float*)d_in[25];
    } else {
        wq_s = (const float*)d_in[8];  wk_s = (const float*)d_in[9];
        wv_s = (const float*)d_in[10]; wq_w = (const float*)d_in[11];
        wk_w = (const float*)d_in[12]; wv_w = (const float*)d_in[13];
        fcs_w = (const float*)d_in[14]; fcw_w = (const float*)d_in[15];
        bq_s = (const float*)d_in[16]; bk_s = (const float*)d_in[17];
        bv_s = (const float*)d_in[18]; bq_w = (const float*)d_in[19];
        bk_w = (const float*)d_in[20]; bv_w = (const float*)d_in[21];
        fcs_b = (const float*)d_in[22]; fcw_b = (const float*)d_in[23];
        fco_w = (const float*)d_in[24]; fco_b = (const float*)d_in[25];
    }

    float* scratch = nullptr;
    cudaGetSymbolAddress((void**)&scratch, g_scratch);
    float* s_qs  = scratch + OFF_QS;
    float* s_ks  = scratch + OFF_KS;
    float* s_vs  = scratch + OFF_VS;
    float* s_att = scratch + OFF_ATT;
    __half* hb = (__half*)(scratch + OFF_HALF);
    __half* acth = hb + H_ACTH;
    __half* actl = hb + H_ACTL;
    __half* wth  = hb + H_WTH;
    __half* wtl  = hb + H_WTL;
    __half* qwh  = hb + H_QWH;
    __half* qwl  = hb + H_QWL;
    __half* kwh  = hb + H_KWH;
    __half* kwl  = hb + H_KWL;
    __half* vwh  = hb + H_VWH;
    __half* vwl  = hb + H_VWL;
    __half* csh  = hb + H_CSH;
    __half* csl  = hb + H_CSL;
    __half* cwh  = hb + H_CWH;
    __half* cwl  = hb + H_CWL;
    __half* cath = hb + H_CATH;
    __half* catl = hb + H_CATL;

    cudaFuncSetAttribute(gemm_cfg, cudaFuncAttributeMaxDynamicSharedMemorySize, HSMEM_BYTES);
    cudaFuncSetAttribute(word_attn_h3, cudaFuncAttributeMaxDynamicSharedMemorySize, WSMEM_BYTES);

    // prep
    ASplitArgs aa;
    aa.src[0] = q; aa.src[1] = k_s; aa.src[2] = v_s; aa.src[3] = k_w; aa.src[4] = v_w;
    act_split<<<dim3(256, 5), 256>>>(aa, acth, actl);
    WSplitArgs wa;
    wa.src[0] = wq_s; wa.src[1] = wk_s; wa.src[2] = wv_s;
    wa.src[3] = wq_w; wa.src[4] = wk_w; wa.src[5] = wv_w;
    wa.src[6] = fcs_w; wa.src[7] = fcw_w; wa.src[8] = fco_w;
    w_transplit<<<dim3(16, 32, 9), dim3(32, 8)>>>(wa, wth, wtl);

    // merged projections
    {
        GemmCfg c = {};
        c.K = 512; c.ldc = 512;
        c.Ah[0] = acth + AQ;  c.Al[0] = actl + AQ;
        c.Ah[1] = acth + AQ;  c.Al[1] = actl + AQ;
        c.Ah[2] = acth + AKS; c.Al[2] = actl + AKS;
        c.Ah[3] = acth + AVS; c.Al[3] = actl + AVS;
        c.Bh[0] = wth + WOFF(0); c.Bl[0] = wtl + WOFF(0);
        c.Bh[1] = wth + WOFF(3); c.Bl[1] = wtl + WOFF(3);
        c.Bh[2] = wth + WOFF(1); c.Bl[2] = wtl + WOFF(1);
        c.Bh[3] = wth + WOFF(2); c.Bl[3] = wtl + WOFF(2);
        c.bias[0] = bq_s; c.bias[1] = bq_w; c.bias[2] = bk_s; c.bias[3] = bv_s;
        c.bscale[0] = 1.f; c.bscale[1] = 0.125f; c.bscale[2] = 1.f; c.bscale[3] = 1.f;
        c.M[0] = 1024; c.M[1] = 1024; c.M[2] = 96; c.M[3] = 96;
        c.mode[0] = 0; c.mode[1] = 1; c.mode[2] = 0; c.mode[3] = 0;
        c.Cf[0] = s_qs; c.Cf[2] = s_ks; c.Cf[3] = s_vs;
        c.Ch[1] = qwh;  c.Cl[1] = qwl;
        gemm_cfg<<<dim3(8, 8, 4), 256, HSMEM_BYTES>>>(c);
    }
    // big word projections
    {
        GemmCfg c = {};
        c.K = 512; c.ldc = 512;
        c.Ah[0] = acth + AKW; c.Al[0] = actl + AKW;
        c.Ah[1] = acth + AVW; c.Al[1] = actl + AVW;
        c.Bh[0] = wth + WOFF(4); c.Bl[0] = wtl + WOFF(4);
        c.Bh[1] = wth + WOFF(5); c.Bl[1] = wtl + WOFF(5);
        c.bias[0] = bk_w; c.bias[1] = bv_w;
        c.bscale[0] = 1.f; c.bscale[1] = 1.f;
        c.M[0] = 12288; c.M[1] = 12288;
        c.mode[0] = 1; c.mode[1] = 1;
        c.Ch[0] = kwh; c.Cl[0] = kwl;
        c.Ch[1] = vwh; c.Cl[1] = vwl;
        gemm_cfg<<<dim3(8, 96, 2), 256, HSMEM_BYTES>>>(c);
    }

    sent_attn<<<dim3(Hd, BB), 256>>>(s_qs, s_ks, s_vs, bias_s, gab, s_att, csh, csl);

    word_attn_h3<<<dim3(8, Hd, BB), 512, WSMEM_BYTES>>>(
        qwh, qwl, kwh, kwl, vwh, vwl, bias_w, s_att, cwh, cwl);

    // fcs / fcw -> split cat
    {
        GemmCfg c = {};
        c.K = 512; c.ldc = 1024;
        c.Ah[0] = csh; c.Al[0] = csl;
        c.Ah[1] = cwh; c.Al[1] = cwl;
        c.Bh[0] = wth + WOFF(6); c.Bl[0] = wtl + WOFF(6);
        c.Bh[1] = wth + WOFF(7); c.Bl[1] = wtl + WOFF(7);
        c.bias[0] = fcs_b; c.bias[1] = fcw_b;
        c.bscale[0] = 1.f; c.bscale[1] = 1.f;
        c.M[0] = 1024; c.M[1] = 1024;
        c.mode[0] = 1; c.mode[1] = 1;
        c.Ch[0] = cath;       c.Cl[0] = catl;
        c.Ch[1] = cath + 512; c.Cl[1] = catl + 512;
        gemm_cfg<<<dim3(8, 8, 2), 256, HSMEM_BYTES>>>(c);
    }
    // final fco -> fp32 out
    {
        GemmCfg c = {};
        c.K = 1024; c.ldc = 512;
        c.Ah[0] = cath; c.Al[0] = catl;
        c.Bh[0] = wth + WOFF(8); c.Bl[0] = wtl + WOFF(8);
        c.bias[0] = fco_b;
        c.bscale[0] = 1.f;
        c.M[0] = 1024;
        c.mode[0] = 0;
        c.Cf[0] = (float*)d_out;
        gemm_cfg<<<dim3(8, 8, 1), 256, HSMEM_BYTES>>>(c);
    }
}

// round 10
// speedup vs baseline: 1.7915x; 1.0750x over previous
#include <cuda_runtime.h>
#include <cuda_fp16.h>
#include <math.h>
#include <stdint.h>

// Problem constants
#define BB   4
#define LQd  256
#define NSd  24
#define NTd  128
#define Dd   512
#define Hd   8
#define DKd  64

// ---------------- scratch layout ----------------
#define OFF_QS   0
#define OFF_KS   524288
#define OFF_VS   573440
#define OFF_ATT  622592
#define OFF_HALF 819200
#define H_ACTH 0
#define H_ACTL 13205504
#define H_WTH  26411008
#define H_WTL  29032448
#define H_QWH  31653888
#define H_QWL  32178176
#define H_KWH  32702464
#define H_KWL  38993920
#define H_VWH  45285376
#define H_VWL  51576832
#define H_CSH  57868288
#define H_CSL  58392576
#define H_CWH  58916864
#define H_CWL  59441152
#define H_CATH 59965440
#define H_CATL 61014016
#define H_TOTAL 62062592
#define SCRATCH_TOTAL (OFF_HALF + H_TOTAL / 2)
__device__ float g_scratch[SCRATCH_TOTAL];

#define AQ   0
#define AKS  524288
#define AVS  573440
#define AKW  622592
#define AVW  6914048
#define WOFF(i) ((i) * 262144)

// ---------------- helpers ----------------
__device__ __forceinline__ void split_h(float x, __half& hi, __half& lo) {
    hi = __float2half_rn(x);
    lo = __float2half_rn(x - __half2float(hi));
}
__device__ __forceinline__ void mma_f16(float d[4],
                                        uint32_t a0, uint32_t a1, uint32_t a2, uint32_t a3,
                                        uint32_t b0, uint32_t b1) {
    asm volatile(
        "mma.sync.aligned.m16n8k16.row.col.f32.f16.f16.f32 "
        "{%0,%1,%2,%3},{%4,%5,%6,%7},{%8,%9},{%0,%1,%2,%3};"
        : "+f"(d[0]), "+f"(d[1]), "+f"(d[2]), "+f"(d[3])
        : "r"(a0), "r"(a1), "r"(a2), "r"(a3), "r"(b0), "r"(b1));
}
__device__ __forceinline__ void ldsm_x4(uint32_t r[4], uint32_t addr) {
    asm volatile("ldmatrix.sync.aligned.m8n8.x4.shared.b16 {%0,%1,%2,%3}, [%4];"
                 : "=r"(r[0]), "=r"(r[1]), "=r"(r[2]), "=r"(r[3]) : "r"(addr));
}
__device__ __forceinline__ void ldsm_x4_t(uint32_t r[4], uint32_t addr) {
    asm volatile("ldmatrix.sync.aligned.m8n8.x4.trans.shared.b16 {%0,%1,%2,%3}, [%4];"
                 : "=r"(r[0]), "=r"(r[1]), "=r"(r[2]), "=r"(r[3]) : "r"(addr));
}
__device__ __forceinline__ void cp_async16(uint32_t smem_addr, const void* gptr, int src_bytes) {
    asm volatile("cp.async.cg.shared.global [%0], [%1], 16, %2;"
                 :: "r"(smem_addr), "l"(gptr), "r"(src_bytes) : "memory");
}
__device__ __forceinline__ void cp_commit() { asm volatile("cp.async.commit_group;" ::: "memory"); }
template <int N>
__device__ __forceinline__ void cp_wait() { asm volatile("cp.async.wait_group %0;" :: "n"(N) : "memory"); }

// ---------------- prep: split activations ----------------
struct ASplitArgs { const float* src[5]; };
__constant__ int c_alen[5] = {524288, 49152, 49152, 6291456, 6291456};
__constant__ int c_aoff[5] = {AQ, AKS, AVS, AKW, AVW};

__global__ __launch_bounds__(256) void act_split(ASplitArgs args, __half* acth, __half* actl)
{
    int z = blockIdx.y;
    int n = c_alen[z];
    const float* s = args.src[z];
    __half* dh = acth + c_aoff[z];
    __half* dl = actl + c_aoff[z];
    for (int i = blockIdx.x * 256 + threadIdx.x; i < n; i += gridDim.x * 256) {
        __half hi, lo;
        split_h(s[i], hi, lo);
        dh[i] = hi;
        dl[i] = lo;
    }
}

// ---------------- prep: transpose+split weights ----------------
struct WSplitArgs { const float* src[9]; };
__constant__ int c_wK[9] = {512, 512, 512, 512, 512, 512, 512, 512, 1024};
__constant__ int c_woff[9] = {WOFF(0), WOFF(1), WOFF(2), WOFF(3), WOFF(4),
                              WOFF(5), WOFF(6), WOFF(7), WOFF(8)};
__constant__ float c_wscale[9] = {1.f, 1.f, 1.f, 0.125f, 1.f, 1.f, 1.f, 1.f, 1.f};

__global__ void w_transplit(WSplitArgs args, __half* wth, __half* wtl)
{
    int z = blockIdx.z;
    int Kw = c_wK[z];
    int k0 = blockIdx.y * 32;
    if (k0 >= Kw) return;
    int n0 = blockIdx.x * 32;
    const float* W = args.src[z];
    float sc = c_wscale[z];
    __half* th = wth + c_woff[z];
    __half* tl = wtl + c_woff[z];

    __shared__ float ts[32][33];
    int tx = threadIdx.x, ty = threadIdx.y;
    #pragma unroll
    for (int r = 0; r < 4; r++)
        ts[ty + 8 * r][tx] = W[(size_t)(k0 + ty + 8 * r) * 512 + n0 + tx];
    __syncthreads();
    #pragma unroll
    for (int r = 0; r < 4; r++) {
        int n = n0 + ty + 8 * r;
        int k = k0 + tx;
        __half hi, lo;
        split_h(sc * ts[tx][ty + 8 * r], hi, lo);
        th[(size_t)n * Kw + k] = hi;
        tl[(size_t)n * Kw + k] = lo;
    }
}

// ---------------- split-FP16 GEMM: 128x64 tile, 256 threads, 2 CTAs/SM, ldmatrix ----------------
#define HAS 40
#define G_A 128
#define G_B 64
#define HSTAGE ((2 * G_A + 2 * G_B) * HAS)
#define HSMEM_BYTES (2 * HSTAGE * 2)

struct GemmCfg {
    const __half* Ah[4]; const __half* Al[4];
    const __half* Bh[4]; const __half* Bl[4];
    const float* bias[4];
    float* Cf[4];
    __half* Ch[4]; __half* Cl[4];
    int M[4]; int mode[4]; float bscale[4];
    int K; int ldc;
};

__global__ __launch_bounds__(256, 2) void gemm_cfg(GemmCfg cfg)
{
    extern __shared__ __half hsm[];

    const int z = blockIdx.z;
    const int M = cfg.M[z];
    const int row0 = blockIdx.y * 128;
    if (row0 >= M) return;

    const __half* Ah_g = cfg.Ah[z];
    const __half* Al_g = cfg.Al[z];
    const __half* Bh_g = cfg.Bh[z];
    const __half* Bl_g = cfg.Bl[z];
    const float* bias  = cfg.bias[z];
    const int mode     = cfg.mode[z];
    const float bsc    = cfg.bscale[z];
    const int K        = cfg.K;
    const int ldc      = cfg.ldc;

    const int tid = threadIdx.x;
    const int wid = tid >> 5;
    const int lane = tid & 31;
    const int g = lane >> 2;
    const int t = lane & 3;
    const int wm = wid & 3;
    const int wn = wid >> 2;
    const int col0 = blockIdx.x * 64;

    const int q8 = lane & 7;
    const int seg = lane >> 3;
    const uint32_t smem_base = (uint32_t)__cvta_generic_to_shared(hsm);
    const uint32_t a_off = (uint32_t)((q8 + (seg & 1) * 8) * HAS + (seg >> 1) * 8);
    const uint32_t b_off = (uint32_t)((q8 + (seg >> 1) * 8) * HAS + (seg & 1) * 8);

    float dm[2][4][4], dc[2][4][4];
    #pragma unroll
    for (int mt = 0; mt < 2; mt++)
        #pragma unroll
        for (int nt = 0; nt < 4; nt++)
            #pragma unroll
            for (int j = 0; j < 4; j++) { dm[mt][nt][j] = 0.f; dc[mt][nt][j] = 0.f; }

    const int ktiles = K >> 5;

    {
        __half* Ahs = hsm;
        __half* Als = Ahs + G_A * HAS;
        __half* Bhs = Als + G_A * HAS;
        __half* Bls = Bhs + G_B * HAS;
        #pragma unroll
        for (int i = 0; i < 4; i++) {
            int id = tid + 256 * i;
            int arr = id >> 9, rem = id & 511;
            int row = rem >> 2, ch = rem & 3;
            int r = row0 + row;
            int rc = r < M ? r : (M - 1);
            int pb = r < M ? 16 : 0;
            const __half* src = (arr ? Al_g : Ah_g) + (size_t)rc * K + ch * 8;
            __half* dst = (arr ? Als : Ahs) + row * HAS + ch * 8;
            cp_async16((uint32_t)__cvta_generic_to_shared(dst), src, pb);
        }
        #pragma unroll
        for (int i = 0; i < 2; i++) {
            int id = tid + 256 * i;
            int arr = id >> 8, rem = id & 255;
            int row = rem >> 2, ch = rem & 3;
            const __half* src = (arr ? Bl_g : Bh_g) + (size_t)(col0 + row) * K + ch * 8;
            __half* dst = (arr ? Bls : Bhs) + row * HAS + ch * 8;
            cp_async16((uint32_t)__cvta_generic_to_shared(dst), src, 16);
        }
        cp_commit();
    }

    for (int kt = 0; kt < ktiles; kt++) {
        if (kt + 1 < ktiles) {
            __half* Ahs = hsm + ((kt + 1) & 1) * HSTAGE;
            __half* Als = Ahs + G_A * HAS;
            __half* Bhs = Als + G_A * HAS;
            __half* Bls = Bhs + G_B * HAS;
            int k0 = (kt + 1) << 5;
            #pragma unroll
            for (int i = 0; i < 4; i++) {
                int id = tid + 256 * i;
                int arr = id >> 9, rem = id & 511;
                int row = rem >> 2, ch = rem & 3;
                int r = row0 + row;
                int rc = r < M ? r : (M - 1);
                int pb = r < M ? 16 : 0;
                const __half* src = (arr ? Al_g : Ah_g) + (size_t)rc * K + k0 + ch * 8;
                __half* dst = (arr ? Als : Ahs) + row * HAS + ch * 8;
                cp_async16((uint32_t)__cvta_generic_to_shared(dst), src, pb);
            }
            #pragma unroll
            for (int i = 0; i < 2; i++) {
                int id = tid + 256 * i;
                int arr = id >> 8, rem = id & 255;
                int row = rem >> 2, ch = rem & 3;
                const __half* src = (arr ? Bl_g : Bh_g) + (size_t)(col0 + row) * K + k0 + ch * 8;
                __half* dst = (arr ? Bls : Bhs) + row * HAS + ch * 8;
                cp_async16((uint32_t)__cvta_generic_to_shared(dst), src, 16);
            }
            cp_commit();
            cp_wait<1>();
        } else {
            cp_wait<0>();
        }
        __syncthreads();

        const uint32_t stage = smem_base + (uint32_t)(((kt & 1) * HSTAGE) * 2);

        #pragma unroll
        for (int ks = 0; ks < 2; ks++) {
            const uint32_t kb = (uint32_t)(ks * 16);
            uint32_t ah[2][4], al[2][4];
            #pragma unroll
            for (int mt = 0; mt < 2; mt++) {
                uint32_t rbase = (uint32_t)((wm * 32 + mt * 16) * HAS) + kb;
                ldsm_x4(ah[mt], stage + 2 * (rbase + a_off));
                ldsm_x4(al[mt], stage + 2 * (G_A * HAS + rbase + a_off));
            }
            uint32_t bh[4][2], bl[4][2];
            #pragma unroll
            for (int p = 0; p < 2; p++) {
                uint32_t nbase = (uint32_t)((wn * 32 + p * 16) * HAS) + kb;
                uint32_t r4[4];
                ldsm_x4(r4, stage + 2 * (2 * G_A * HAS + nbase + b_off));
                bh[2 * p][0] = r4[0]; bh[2 * p][1] = r4[1];
                bh[2 * p + 1][0] = r4[2]; bh[2 * p + 1][1] = r4[3];
                ldsm_x4(r4, stage + 2 * (2 * G_A * HAS + G_B * HAS + nbase + b_off));
                bl[2 * p][0] = r4[0]; bl[2 * p][1] = r4[1];
                bl[2 * p + 1][0] = r4[2]; bl[2 * p + 1][1] = r4[3];
            }
            #pragma unroll
            for (int nt = 0; nt < 4; nt++) {
                #pragma unroll
                for (int mt = 0; mt < 2; mt++) {
                    mma_f16(dm[mt][nt], ah[mt][0], ah[mt][1], ah[mt][2], ah[mt][3], bh[nt][0], bh[nt][1]);
                    mma_f16(dc[mt][nt], ah[mt][0], ah[mt][1], ah[mt][2], ah[mt][3], bl[nt][0], bl[nt][1]);
                    mma_f16(dc[mt][nt], al[mt][0], al[mt][1], al[mt][2], al[mt][3], bh[nt][0], bh[nt][1]);
                }
            }
        }
        __syncthreads();
    }

    #pragma unroll
    for (int mt = 0; mt < 2; mt++) {
        #pragma unroll
        for (int nt = 0; nt < 4; nt++) {
            int r = row0 + wm * 32 + mt * 16 + g;
            int c = col0 + wn * 32 + nt * 8 + 2 * t;
            float2 bz = *(const float2*)&bias[c];
            float o0 = dm[mt][nt][0] + dc[mt][nt][0] + bsc * bz.x;
            float o1 = dm[mt][nt][1] + dc[mt][nt][1] + bsc * bz.y;
            float o2 = dm[mt][nt][2] + dc[mt][nt][2] + bsc * bz.x;
            float o3 = dm[mt][nt][3] + dc[mt][nt][3] + bsc * bz.y;
            if (mode == 0) {
                float* Cf = cfg.Cf[z];
                if (r < M)     *(float2*)&Cf[(size_t)r * ldc + c] = make_float2(o0, o1);
                if (r + 8 < M) *(float2*)&Cf[(size_t)(r + 8) * ldc + c] = make_float2(o2, o3);
            } else {
                __half* Ch = cfg.Ch[z];
                __half* Cl = cfg.Cl[z];
                __half h0, l0, h1, l1;
                if (r < M) {
                    split_h(o0, h0, l0); split_h(o1, h1, l1);
                    *(__half2*)&Ch[(size_t)r * ldc + c] = __halves2half2(h0, h1);
                    *(__half2*)&Cl[(size_t)r * ldc + c] = __halves2half2(l0, l1);
                }
                if (r + 8 < M) {
                    split_h(o2, h0, l0); split_h(o3, h1, l1);
                    *(__half2*)&Ch[(size_t)(r + 8) * ldc + c] = __halves2half2(h0, h1);
                    *(__half2*)&Cl[(size_t)(r + 8) * ldc + c] = __halves2half2(l0, l1);
                }
            }
        }
    }
}

// ---------------- sentence-level graph attention ----------------
__global__ __launch_bounds__(256) void sent_attn(
    const float* __restrict__ qs, const float* __restrict__ ksn,
    const float* __restrict__ vsn, const float* __restrict__ bias_s,
    const float* __restrict__ gab,
    float* __restrict__ attns_out,
    __half* __restrict__ csh, __half* __restrict__ csl)
{
    const int h = blockIdx.x, b = blockIdx.y;
    const int q = threadIdx.x;

    __shared__ float Ks[NSd][DKd + 1];
    __shared__ float Vs[NSd][DKd + 1];
    __shared__ float G[NSd][NSd + 1];

    for (int idx = q; idx < NSd * DKd; idx += 256) {
        int s = idx >> 6, k = idx & 63;
        Ks[s][k] = ksn[(size_t)(b * NSd + s) * Dd + h * DKd + k];
        Vs[s][k] = vsn[(size_t)(b * NSd + s) * Dd + h * DKd + k];
    }
    for (int idx = q; idx < NSd * NSd; idx += 256) {
        int s = idx / NSd, tt = idx % NSd;
        G[s][tt] = gab[((size_t)(b * Hd + h) * NSd + s) * NSd + tt];
    }
    __syncthreads();

    float qreg[DKd];
    const float* qrow = qs + (size_t)(b * LQd + q) * Dd + h * DKd;
    #pragma unroll
    for (int k = 0; k < DKd; k++) qreg[k] = qrow[k] * 0.125f;

    float a[NSd];
    const float* bsrow = bias_s + ((size_t)(b * Hd + h) * LQd + q) * NSd;
    #pragma unroll
    for (int s = 0; s < NSd; s++) {
        float dd = 0.f;
        #pragma unroll
        for (int k = 0; k < DKd; k++) dd += qreg[k] * Ks[s][k];
        a[s] = dd + bsrow[s];
    }

    float m = -1e30f;
    #pragma unroll
    for (int s = 0; s < NSd; s++) m = fmaxf(m, a[s]);
    float smx[NSd]; float sum = 0.f;
    #pragma unroll
    for (int s = 0; s < NSd; s++) { smx[s] = __expf(a[s] - m); sum += smx[s]; }
    float inv = 1.f / sum;

    float gg[NSd];
    #pragma unroll
    for (int tt = 0; tt < NSd; tt++) {
        float dd = 0.f;
        #pragma unroll
        for (int s = 0; s < NSd; s++) dd += smx[s] * G[s][tt];
        gg[tt] = dd * inv;
    }
    #pragma unroll
    for (int s = 0; s < NSd; s++) a[s] -= 0.5f * gg[s] * gg[s];

    m = -1e30f;
    #pragma unroll
    for (int s = 0; s < NSd; s++) m = fmaxf(m, a[s]);
    sum = 0.f;
    #pragma unroll
    for (int s = 0; s < NSd; s++) { a[s] = __expf(a[s] - m); sum += a[s]; }
    inv = 1.f / sum;

    float* arow = attns_out + ((size_t)(b * Hd + h) * LQd + q) * NSd;
    #pragma unroll
    for (int s = 0; s < NSd; s++) { a[s] *= inv; arow[s] = a[s]; }

    size_t cbase = (size_t)(b * LQd + q) * Dd + h * DKd;
    #pragma unroll
    for (int dd = 0; dd < DKd; dd++) {
        float acc = 0.f;
        #pragma unroll
        for (int s = 0; s < NSd; s++) acc += a[s] * Vs[s][dd];
        __half hi, lo;
        split_h(acc, hi, lo);
        csh[cbase + dd] = hi;
        csl[cbase + dd] = lo;
    }
}

// ---------------- word-level attention v4: ldmatrix everywhere ----------------
#define HQS 72
#define W_QH 0
#define W_QL (32 * HQS)
#define W_KV (2 * 32 * HQS)
#define W_ARR (128 * HQS)
#define W_P  (W_KV + 4 * W_ARR)
#define PROW 264
#define WSMEM_BYTES ((W_P + 32 * PROW) * 2)

__global__ __launch_bounds__(512, 2) void word_attn_h4(
    const __half* __restrict__ qwh, const __half* __restrict__ qwl,
    const __half* __restrict__ kwh, const __half* __restrict__ kwl,
    const __half* __restrict__ vwh, const __half* __restrict__ vwl,
    const float* __restrict__ bias_w, const float* __restrict__ attns,
    __half* __restrict__ cwh, __half* __restrict__ cwl)
{
    extern __shared__ __half hsm[];
    float* Ps = (float*)(hsm + W_P);
    __half* PU = hsm + W_P;

    const int tid = threadIdx.x;
    const int wid = tid >> 5;
    const int lane = tid & 31;
    const int g = lane >> 2;
    const int t = lane & 3;
    const int wm = wid & 1;
    const int wn = wid >> 1;
    const int q0 = blockIdx.x * 32;
    const int h  = blockIdx.y;
    const int b  = blockIdx.z;

    const int q8 = lane & 7;
    const int seg = lane >> 3;
    const uint32_t smem_base = (uint32_t)__cvta_generic_to_shared(hsm);
    const uint32_t aq_off = (uint32_t)((q8 + (seg & 1) * 8) * HQS + (seg >> 1) * 8);
    const uint32_t bk_off = (uint32_t)((q8 + (seg >> 1) * 8) * HQS + (seg & 1) * 8);
    const uint32_t ap_off = (uint32_t)((q8 + (seg & 1) * 8) * PROW + (seg >> 1) * 8);
    const uint32_t v_arr  = (seg >> 1) ? (uint32_t)(W_KV + 3 * W_ARR) : (uint32_t)(W_KV + 2 * W_ARR);
    const uint32_t v_off  = (uint32_t)((q8 + (seg & 1) * 8) * HQS + wn * 8);

    // issue Q + stage-0 K/V loads
    {
        {
            int arr = tid >> 8, rem = tid & 255;
            int row = rem >> 3, ch = rem & 7;
            const __half* src = (arr == 0 ? qwh : qwl) + (size_t)(b * LQd + q0 + row) * Dd + h * DKd + ch * 8;
            uint32_t dst = (uint32_t)__cvta_generic_to_shared(
                &hsm[(arr == 0 ? W_QH : W_QL) + row * HQS + ch * 8]);
            cp_async16(dst, src, 16);
        }
        const size_t kvb = (size_t)(b * NSd) * NTd * Dd + h * DKd;
        const __half* srcs[4] = {kwh, kwl, vwh, vwl};
        #pragma unroll
        for (int i = 0; i < 8; i++) {
            int id = tid + 512 * i;
            int arr = id >> 10, rem = id & 1023;
            int row = rem >> 3, ch = rem & 7;
            const __half* src = srcs[arr] + kvb + (size_t)row * Dd + ch * 8;
            uint32_t dst = (uint32_t)__cvta_generic_to_shared(
                &hsm[W_KV + arr * W_ARR + row * HQS + ch * 8]);
            cp_async16(dst, src, 16);
        }
        cp_commit();
        cp_wait<0>();
    }
    __syncthreads();

    float om[4], oc[4];
    #pragma unroll
    for (int j = 0; j < 4; j++) { om[j] = 0.f; oc[j] = 0.f; }

    for (int s = 0; s < NSd; s++) {
        // ---- P = Q @ K^T (warp tile 16x16) ----
        float pm[2][4], pc[2][4];
        #pragma unroll
        for (int nt = 0; nt < 2; nt++)
            #pragma unroll
            for (int j = 0; j < 4; j++) { pm[nt][j] = 0.f; pc[nt][j] = 0.f; }

        #pragma unroll
        for (int ks = 0; ks < 4; ks++) {
            const uint32_t kb = (uint32_t)(ks * 16);
            uint32_t ahq[4], alq[4], kh4[4], kl4[4];
            uint32_t qrb = (uint32_t)(wm * 16 * HQS) + kb;
            ldsm_x4(ahq, smem_base + 2 * (W_QH + qrb + aq_off));
            ldsm_x4(alq, smem_base + 2 * (W_QL + qrb + aq_off));
            uint32_t krb = (uint32_t)(wn * 16 * HQS) + kb;
            ldsm_x4(kh4, smem_base + 2 * (W_KV + krb + bk_off));
            ldsm_x4(kl4, smem_base + 2 * (W_KV + W_ARR + krb + bk_off));
            #pragma unroll
            for (int nt = 0; nt < 2; nt++) {
                mma_f16(pm[nt], ahq[0], ahq[1], ahq[2], ahq[3], kh4[2 * nt], kh4[2 * nt + 1]);
                mma_f16(pc[nt], ahq[0], ahq[1], ahq[2], ahq[3], kl4[2 * nt], kl4[2 * nt + 1]);
                mma_f16(pc[nt], alq[0], alq[1], alq[2], alq[3], kh4[2 * nt], kh4[2 * nt + 1]);
            }
        }
        #pragma unroll
        for (int nt = 0; nt < 2; nt++) {
            int r = wm * 16 + g;
            int c = wn * 16 + nt * 8 + 2 * t;
            *(float2*)&Ps[r * 132 + c] = make_float2(pm[nt][0] + pc[nt][0], pm[nt][1] + pc[nt][1]);
            *(float2*)&Ps[(r + 8) * 132 + c] = make_float2(pm[nt][2] + pc[nt][2], pm[nt][3] + pc[nt][3]);
        }
        __syncthreads();

        // ---- softmax + bias + attns scale; write split-fp16 into union rows ----
        const float* bb = bias_w + ((size_t)((b * NSd + s) * Hd + h) * LQd + q0) * NTd;
        #pragma unroll
        for (int rr = 0; rr < 2; rr++) {
            int r = wid * 2 + rr;
            float x0 = Ps[r * 132 + lane]       + bb[r * NTd + lane];
            float x1 = Ps[r * 132 + lane + 32]  + bb[r * NTd + lane + 32];
            float x2 = Ps[r * 132 + lane + 64]  + bb[r * NTd + lane + 64];
            float x3 = Ps[r * 132 + lane + 96]  + bb[r * NTd + lane + 96];
            float mx = fmaxf(fmaxf(x0, x1), fmaxf(x2, x3));
            #pragma unroll
            for (int o = 16; o; o >>= 1) mx = fmaxf(mx, __shfl_xor_sync(0xffffffffu, mx, o));
            x0 = __expf(x0 - mx); x1 = __expf(x1 - mx);
            x2 = __expf(x2 - mx); x3 = __expf(x3 - mx);
            float su = x0 + x1 + x2 + x3;
            #pragma unroll
            for (int o = 16; o; o >>= 1) su += __shfl_xor_sync(0xffffffffu, su, o);
            float wsc = attns[((size_t)(b * Hd + h) * LQd + q0 + r) * NSd + s] / su;
            __half h0, l0, h1, l1, h2, l2, h3, l3;
            split_h(x0 * wsc, h0, l0);
            split_h(x1 * wsc, h1, l1);
            split_h(x2 * wsc, h2, l2);
            split_h(x3 * wsc, h3, l3);
            __syncwarp();   // whole row read before overwrite (union aliasing)
            __half* prow = PU + r * PROW;
            prow[lane]       = h0;  prow[128 + lane]       = l0;
            prow[lane + 32]  = h1;  prow[128 + lane + 32]  = l1;
            prow[lane + 64]  = h2;  prow[128 + lane + 64]  = l2;
            prow[lane + 96]  = h3;  prow[128 + lane + 96]  = l3;
        }
        __syncthreads();

        // ---- O += P @ V (warp tile 16x8, ldmatrix + trans-V) ----
        #pragma unroll
        for (int ks = 0; ks < 8; ks++) {
            const uint32_t kb = (uint32_t)(ks * 16);
            uint32_t ph4[4], pl4[4], v4[4];
            uint32_t prb = (uint32_t)(wm * 16 * PROW) + kb;
            ldsm_x4(ph4, smem_base + 2 * (W_P + prb + ap_off));
            ldsm_x4(pl4, smem_base + 2 * (W_P + prb + 128 + ap_off));
            ldsm_x4_t(v4, smem_base + 2 * (v_arr + kb * HQS + v_off));
            mma_f16(om, ph4[0], ph4[1], ph4[2], ph4[3], v4[0], v4[1]);
            mma_f16(oc, ph4[0], ph4[1], ph4[2], ph4[3], v4[2], v4[3]);
            mma_f16(oc, pl4[0], pl4[1], pl4[2], pl4[3], v4[0], v4[1]);
        }

        // load next K/V stage
        if (s + 1 < NSd) {
            __syncthreads();
            const size_t kvb = (size_t)(b * NSd + s + 1) * NTd * Dd + h * DKd;
            const __half* srcs[4] = {kwh, kwl, vwh, vwl};
            #pragma unroll
            for (int i = 0; i < 8; i++) {
                int id = tid + 512 * i;
                int arr = id >> 10, rem = id & 1023;
                int row = rem >> 3, ch = rem & 7;
                const __half* src = srcs[arr] + kvb + (size_t)row * Dd + ch * 8;
                uint32_t dst = (uint32_t)__cvta_generic_to_shared(
                    &hsm[W_KV + arr * W_ARR + row * HQS + ch * 8]);
                cp_async16(dst, src, 16);
            }
            cp_commit();
            cp_wait<0>();
            __syncthreads();
        }
    }

    {
        int r = q0 + wm * 16 + g;
        int c = h * DKd + wn * 8 + 2 * t;
        float v0 = om[0] + oc[0], v1 = om[1] + oc[1];
        float v2 = om[2] + oc[2], v3 = om[3] + oc[3];
        __half h0, l0, h1, l1;
        split_h(v0, h0, l0); split_h(v1, h1, l1);
        *(__half2*)&cwh[(size_t)(b * LQd + r) * Dd + c] = __halves2half2(h0, h1);
        *(__half2*)&cwl[(size_t)(b * LQd + r) * Dd + c] = __halves2half2(l0, l1);
        split_h(v2, h0, l0); split_h(v3, h1, l1);
        *(__half2*)&cwh[(size_t)(b * LQd + r + 8) * Dd + c] = __halves2half2(h0, h1);
        *(__half2*)&cwl[(size_t)(b * LQd + r + 8) * Dd + c] = __halves2half2(l0, l1);
    }
}

// ---------------- host ----------------
extern "C" void kernel_launch(void* const* d_in, const int* in_sizes, int n_in,
                              void* d_out, int out_size)
{
    const float* q      = (const float*)d_in[0];
    const float* k_s    = (const float*)d_in[1];
    const float* v_s    = (const float*)d_in[2];
    const float* k_w    = (const float*)d_in[3];
    const float* v_w    = (const float*)d_in[4];
    const float* bias_w = (const float*)d_in[5];
    const float* bias_s = (const float*)d_in[6];
    const float* gab    = (const float*)d_in[7];

    const float *wq_s, *bq_s, *wk_s, *bk_s, *wv_s, *bv_s;
    const float *wq_w, *bq_w, *wk_w, *bk_w, *wv_w, *bv_w;
    const float *fcs_w, *fcs_b, *fcw_w, *fcw_b, *fco_w, *fco_b;

    if (in_sizes[9] == 512) {
        wq_s = (const float*)d_in[8];  bq_s = (const float*)d_in[9];
        wk_s = (const float*)d_in[10]; bk_s = (const float*)d_in[11];
        wv_s = (const float*)d_in[12]; bv_s = (const float*)d_in[13];
        wq_w = (const float*)d_in[14]; bq_w = (const float*)d_in[15];
        wk_w = (const float*)d_in[16]; bk_w = (const float*)d_in[17];
        wv_w = (const float*)d_in[18]; bv_w = (const float*)d_in[19];
        fcs_w = (const float*)d_in[20]; fcs_b = (const float*)d_in[21];
        fcw_w = (const float*)d_in[22]; fcw_b = (const float*)d_in[23];
        fco_w = (const float*)d_in[24]; fco_b = (const float*)d_in[25];
    } else {
        wq_s = (const float*)d_in[8];  wk_s = (const float*)d_in[9];
        wv_s = (const float*)d_in[10]; wq_w = (const float*)d_in[11];
        wk_w = (const float*)d_in[12]; wv_w = (const float*)d_in[13];
        fcs_w = (const float*)d_in[14]; fcw_w = (const float*)d_in[15];
        bq_s = (const float*)d_in[16]; bk_s = (const float*)d_in[17];
        bv_s = (const float*)d_in[18]; bq_w = (const float*)d_in[19];
        bk_w = (const float*)d_in[20]; bv_w = (const float*)d_in[21];
        fcs_b = (const float*)d_in[22]; fcw_b = (const float*)d_in[23];
        fco_w = (const float*)d_in[24]; fco_b = (const float*)d_in[25];
    }

    float* scratch = nullptr;
    cudaGetSymbolAddress((void**)&scratch, g_scratch);
    float* s_qs  = scratch + OFF_QS;
    float* s_ks  = scratch + OFF_KS;
    float* s_vs  = scratch + OFF_VS;
    float* s_att = scratch + OFF_ATT;
    __half* hb = (__half*)(scratch + OFF_HALF);
    __half* acth = hb + H_ACTH;
    __half* actl = hb + H_ACTL;
    __half* wth  = hb + H_WTH;
    __half* wtl  = hb + H_WTL;
    __half* qwh  = hb + H_QWH;
    __half* qwl  = hb + H_QWL;
    __half* kwh  = hb + H_KWH;
    __half* kwl  = hb + H_KWL;
    __half* vwh  = hb + H_VWH;
    __half* vwl  = hb + H_VWL;
    __half* csh  = hb + H_CSH;
    __half* csl  = hb + H_CSL;
    __half* cwh  = hb + H_CWH;
    __half* cwl  = hb + H_CWL;
    __half* cath = hb + H_CATH;
    __half* catl = hb + H_CATL;

    cudaFuncSetAttribute(gemm_cfg, cudaFuncAttributeMaxDynamicSharedMemorySize, HSMEM_BYTES);
    cudaFuncSetAttribute(word_attn_h4, cudaFuncAttributeMaxDynamicSharedMemorySize, WSMEM_BYTES);

    // prep
    ASplitArgs aa;
    aa.src[0] = q; aa.src[1] = k_s; aa.src[2] = v_s; aa.src[3] = k_w; aa.src[4] = v_w;
    act_split<<<dim3(256, 5), 256>>>(aa, acth, actl);
    WSplitArgs wa;
    wa.src[0] = wq_s; wa.src[1] = wk_s; wa.src[2] = wv_s;
    wa.src[3] = wq_w; wa.src[4] = wk_w; wa.src[5] = wv_w;
    wa.src[6] = fcs_w; wa.src[7] = fcw_w; wa.src[8] = fco_w;
    w_transplit<<<dim3(16, 32, 9), dim3(32, 8)>>>(wa, wth, wtl);

    // merged projections
    {
        GemmCfg c = {};
        c.K = 512; c.ldc = 512;
        c.Ah[0] = acth + AQ;  c.Al[0] = actl + AQ;
        c.Ah[1] = acth + AQ;  c.Al[1] = actl + AQ;
        c.Ah[2] = acth + AKS; c.Al[2] = actl + AKS;
        c.Ah[3] = acth + AVS; c.Al[3] = actl + AVS;
        c.Bh[0] = wth + WOFF(0); c.Bl[0] = wtl + WOFF(0);
        c.Bh[1] = wth + WOFF(3); c.Bl[1] = wtl + WOFF(3);
        c.Bh[2] = wth + WOFF(1); c.Bl[2] = wtl + WOFF(1);
        c.Bh[3] = wth + WOFF(2); c.Bl[3] = wtl + WOFF(2);
        c.bias[0] = bq_s; c.bias[1] = bq_w; c.bias[2] = bk_s; c.bias[3] = bv_s;
        c.bscale[0] = 1.f; c.bscale[1] = 0.125f; c.bscale[2] = 1.f; c.bscale[3] = 1.f;
        c.M[0] = 1024; c.M[1] = 1024; c.M[2] = 96; c.M[3] = 96;
        c.mode[0] = 0; c.mode[1] = 1; c.mode[2] = 0; c.mode[3] = 0;
        c.Cf[0] = s_qs; c.Cf[2] = s_ks; c.Cf[3] = s_vs;
        c.Ch[1] = qwh;  c.Cl[1] = qwl;
        gemm_cfg<<<dim3(8, 8, 4), 256, HSMEM_BYTES>>>(c);
    }
    // big word projections
    {
        GemmCfg c = {};
        c.K = 512; c.ldc = 512;
        c.Ah[0] = acth + AKW; c.Al[0] = actl + AKW;
        c.Ah[1] = acth + AVW; c.Al[1] = actl + AVW;
        c.Bh[0] = wth + WOFF(4); c.Bl[0] = wtl + WOFF(4);
        c.Bh[1] = wth + WOFF(5); c.Bl[1] = wtl + WOFF(5);
        c.bias[0] = bk_w; c.bias[1] = bv_w;
        c.bscale[0] = 1.f; c.bscale[1] = 1.f;
        c.M[0] = 12288; c.M[1] = 12288;
        c.mode[0] = 1; c.mode[1] = 1;
        c.Ch[0] = kwh; c.Cl[0] = kwl;
        c.Ch[1] = vwh; c.Cl[1] = vwl;
        gemm_cfg<<<dim3(8, 96, 2), 256, HSMEM_BYTES>>>(c);
    }

    sent_attn<<<dim3(Hd, BB), 256>>>(s_qs, s_ks, s_vs, bias_s, gab, s_att, csh, csl);

    word_attn_h4<<<dim3(8, Hd, BB), 512, WSMEM_BYTES>>>(
        qwh, qwl, kwh, kwl, vwh, vwl, bias_w, s_att, cwh, cwl);

    // fcs / fcw -> split cat
    {
        GemmCfg c = {};
        c.K = 512; c.ldc = 1024;
        c.Ah[0] = csh; c.Al[0] = csl;
        c.Ah[1] = cwh; c.Al[1] = cwl;
        c.Bh[0] = wth + WOFF(6); c.Bl[0] = wtl + WOFF(6);
        c.Bh[1] = wth + WOFF(7); c.Bl[1] = wtl + WOFF(7);
        c.bias[0] = fcs_b; c.bias[1] = fcw_b;
        c.bscale[0] = 1.f; c.bscale[1] = 1.f;
        c.M[0] = 1024; c.M[1] = 1024;
        c.mode[0] = 1; c.mode[1] = 1;
        c.Ch[0] = cath;       c.Cl[0] = catl;
        c.Ch[1] = cath + 512; c.Cl[1] = catl + 512;
        gemm_cfg<<<dim3(8, 8, 2), 256, HSMEM_BYTES>>>(c);
    }
    // final fco -> fp32 out
    {
        GemmCfg c = {};
        c.K = 1024; c.ldc = 512;
        c.Ah[0] = cath; c.Al[0] = catl;
        c.Bh[0] = wth + WOFF(8); c.Bl[0] = wtl + WOFF(8);
        c.bias[0] = fco_b;
        c.bscale[0] = 1.f;
        c.M[0] = 1024;
        c.mode[0] = 0;
        c.Cf[0] = (float*)d_out;
        gemm_cfg<<<dim3(8, 8, 1), 256, HSMEM_BYTES>>>(c);
    }
}

// round 11
// speedup vs baseline: 1.8668x; 1.0421x over previous
#include <cuda_runtime.h>
#include <cuda_fp16.h>
#include <math.h>
#include <stdint.h>

// Problem constants
#define BB   4
#define LQd  256
#define NSd  24
#define NTd  128
#define Dd   512
#define Hd   8
#define DKd  64

// ---------------- scratch layout ----------------
#define OFF_QS   0
#define OFF_KS   524288
#define OFF_VS   573440
#define OFF_ATT  622592
#define OFF_HALF 819200
#define H_ACTH 0
#define H_ACTL 13205504
#define H_WTH  26411008
#define H_WTL  29032448
#define H_QWH  31653888
#define H_QWL  32178176
#define H_KWH  32702464
#define H_KWL  38993920
#define H_VWH  45285376
#define H_VWL  51576832
#define H_CSH  57868288
#define H_CSL  58392576
#define H_CWH  58916864
#define H_CWL  59441152
#define H_CATH 59965440
#define H_CATL 61014016
#define H_TOTAL 62062592
#define SCRATCH_TOTAL (OFF_HALF + H_TOTAL / 2)
__device__ float g_scratch[SCRATCH_TOTAL];

#define AQ   0
#define AKS  524288
#define AVS  573440
#define AKW  622592
#define AVW  6914048
#define WOFF(i) ((i) * 262144)

// ---------------- helpers ----------------
__device__ __forceinline__ void split_h(float x, __half& hi, __half& lo) {
    hi = __float2half_rn(x);
    lo = __float2half_rn(x - __half2float(hi));
}
__device__ __forceinline__ void mma_f16(float d[4],
                                        uint32_t a0, uint32_t a1, uint32_t a2, uint32_t a3,
                                        uint32_t b0, uint32_t b1) {
    asm volatile(
        "mma.sync.aligned.m16n8k16.row.col.f32.f16.f16.f32 "
        "{%0,%1,%2,%3},{%4,%5,%6,%7},{%8,%9},{%0,%1,%2,%3};"
        : "+f"(d[0]), "+f"(d[1]), "+f"(d[2]), "+f"(d[3])
        : "r"(a0), "r"(a1), "r"(a2), "r"(a3), "r"(b0), "r"(b1));
}
__device__ __forceinline__ void ldsm_x4(uint32_t r[4], uint32_t addr) {
    asm volatile("ldmatrix.sync.aligned.m8n8.x4.shared.b16 {%0,%1,%2,%3}, [%4];"
                 : "=r"(r[0]), "=r"(r[1]), "=r"(r[2]), "=r"(r[3]) : "r"(addr));
}
__device__ __forceinline__ void ldsm_x4_t(uint32_t r[4], uint32_t addr) {
    asm volatile("ldmatrix.sync.aligned.m8n8.x4.trans.shared.b16 {%0,%1,%2,%3}, [%4];"
                 : "=r"(r[0]), "=r"(r[1]), "=r"(r[2]), "=r"(r[3]) : "r"(addr));
}
__device__ __forceinline__ void cp_async16(uint32_t smem_addr, const void* gptr, int src_bytes) {
    asm volatile("cp.async.cg.shared.global [%0], [%1], 16, %2;"
                 :: "r"(smem_addr), "l"(gptr), "r"(src_bytes) : "memory");
}
__device__ __forceinline__ void cp_commit() { asm volatile("cp.async.commit_group;" ::: "memory"); }
template <int N>
__device__ __forceinline__ void cp_wait() { asm volatile("cp.async.wait_group %0;" :: "n"(N) : "memory"); }

// ---------------- prep: split activations ----------------
struct ASplitArgs { const float* src[5]; };
__constant__ int c_alen[5] = {524288, 49152, 49152, 6291456, 6291456};
__constant__ int c_aoff[5] = {AQ, AKS, AVS, AKW, AVW};

__global__ __launch_bounds__(256) void act_split(ASplitArgs args, __half* acth, __half* actl)
{
    int z = blockIdx.y;
    int n = c_alen[z];
    const float* s = args.src[z];
    __half* dh = acth + c_aoff[z];
    __half* dl = actl + c_aoff[z];
    for (int i = blockIdx.x * 256 + threadIdx.x; i < n; i += gridDim.x * 256) {
        __half hi, lo;
        split_h(s[i], hi, lo);
        dh[i] = hi;
        dl[i] = lo;
    }
}

// ---------------- prep: transpose+split weights ----------------
struct WSplitArgs { const float* src[9]; };
__constant__ int c_wK[9] = {512, 512, 512, 512, 512, 512, 512, 512, 1024};
__constant__ int c_woff[9] = {WOFF(0), WOFF(1), WOFF(2), WOFF(3), WOFF(4),
                              WOFF(5), WOFF(6), WOFF(7), WOFF(8)};
__constant__ float c_wscale[9] = {1.f, 1.f, 1.f, 0.125f, 1.f, 1.f, 1.f, 1.f, 1.f};

__global__ void w_transplit(WSplitArgs args, __half* wth, __half* wtl)
{
    int z = blockIdx.z;
    int Kw = c_wK[z];
    int k0 = blockIdx.y * 32;
    if (k0 >= Kw) return;
    int n0 = blockIdx.x * 32;
    const float* W = args.src[z];
    float sc = c_wscale[z];
    __half* th = wth + c_woff[z];
    __half* tl = wtl + c_woff[z];

    __shared__ float ts[32][33];
    int tx = threadIdx.x, ty = threadIdx.y;
    #pragma unroll
    for (int r = 0; r < 4; r++)
        ts[ty + 8 * r][tx] = W[(size_t)(k0 + ty + 8 * r) * 512 + n0 + tx];
    __syncthreads();
    #pragma unroll
    for (int r = 0; r < 4; r++) {
        int n = n0 + ty + 8 * r;
        int k = k0 + tx;
        __half hi, lo;
        split_h(sc * ts[tx][ty + 8 * r], hi, lo);
        th[(size_t)n * Kw + k] = hi;
        tl[(size_t)n * Kw + k] = lo;
    }
}

// ---------------- split-FP16 GEMM: 3-stage pipeline, 128x64 tile, 2 CTAs/SM ----------------
#define HAS 40
#define G_A 128
#define G_B 64
#define HSTAGE ((2 * G_A + 2 * G_B) * HAS)   // 15360 halves per stage
#define HSMEM_BYTES (3 * HSTAGE * 2)         // 92160 B

struct GemmCfg {
    const __half* Ah[4]; const __half* Al[4];
    const __half* Bh[4]; const __half* Bl[4];
    const float* bias[4];
    float* Cf[4];
    __half* Ch[4]; __half* Cl[4];
    int M[4]; int mode[4]; float bscale[4];
    int K; int ldc;
};

__global__ __launch_bounds__(256, 2) void gemm_cfg(GemmCfg cfg)
{
    extern __shared__ __half hsm[];

    const int z = blockIdx.z;
    const int M = cfg.M[z];
    const int row0 = blockIdx.y * 128;
    if (row0 >= M) return;

    const __half* Ah_g = cfg.Ah[z];
    const __half* Al_g = cfg.Al[z];
    const __half* Bh_g = cfg.Bh[z];
    const __half* Bl_g = cfg.Bl[z];
    const float* bias  = cfg.bias[z];
    const int mode     = cfg.mode[z];
    const float bsc    = cfg.bscale[z];
    const int K        = cfg.K;
    const int ldc      = cfg.ldc;

    const int tid = threadIdx.x;
    const int wid = tid >> 5;
    const int lane = tid & 31;
    const int g = lane >> 2;
    const int t = lane & 3;
    const int wm = wid & 3;
    const int wn = wid >> 2;
    const int col0 = blockIdx.x * 64;

    const int q8 = lane & 7;
    const int seg = lane >> 3;
    const uint32_t smem_base = (uint32_t)__cvta_generic_to_shared(hsm);
    const uint32_t a_off = (uint32_t)((q8 + (seg & 1) * 8) * HAS + (seg >> 1) * 8);
    const uint32_t b_off = (uint32_t)((q8 + (seg >> 1) * 8) * HAS + (seg & 1) * 8);

    // per-thread load slots
    const int la_arr = tid >> 9;            // unused split below; recomputed per i
    (void)la_arr;

    float dm[2][4][4], dc[2][4][4];
    #pragma unroll
    for (int mt = 0; mt < 2; mt++)
        #pragma unroll
        for (int nt = 0; nt < 4; nt++)
            #pragma unroll
            for (int j = 0; j < 4; j++) { dm[mt][nt][j] = 0.f; dc[mt][nt][j] = 0.f; }

    const int ktiles = K >> 5;

    // ---- prologue: fill stages 0 and 1 ----
    #pragma unroll
    for (int p = 0; p < 2; p++) {
        __half* Ahs = hsm + p * HSTAGE;
        __half* Als = Ahs + G_A * HAS;
        __half* Bhs = Als + G_A * HAS;
        __half* Bls = Bhs + G_B * HAS;
        int k0 = p << 5;
        #pragma unroll
        for (int i = 0; i < 4; i++) {
            int id = tid + 256 * i;
            int arr = id >> 9, rem = id & 511;
            int row = rem >> 2, ch = rem & 3;
            int r = row0 + row;
            int rc = r < M ? r : (M - 1);
            int pb = r < M ? 16 : 0;
            const __half* src = (arr ? Al_g : Ah_g) + (size_t)rc * K + k0 + ch * 8;
            __half* dst = (arr ? Als : Ahs) + row * HAS + ch * 8;
            cp_async16((uint32_t)__cvta_generic_to_shared(dst), src, pb);
        }
        #pragma unroll
        for (int i = 0; i < 2; i++) {
            int id = tid + 256 * i;
            int arr = id >> 8, rem = id & 255;
            int row = rem >> 2, ch = rem & 3;
            const __half* src = (arr ? Bl_g : Bh_g) + (size_t)(col0 + row) * K + k0 + ch * 8;
            __half* dst = (arr ? Bls : Bhs) + row * HAS + ch * 8;
            cp_async16((uint32_t)__cvta_generic_to_shared(dst), src, 16);
        }
        cp_commit();
    }
    cp_wait<1>();
    __syncthreads();

    int cst = 0;   // compute stage index = kt % 3

    for (int kt = 0; kt < ktiles; kt++) {
        // ---- compute stage cst ----
        const uint32_t stage = smem_base + (uint32_t)((cst * HSTAGE) * 2);

        #pragma unroll
        for (int ks = 0; ks < 2; ks++) {
            const uint32_t kb = (uint32_t)(ks * 16);
            uint32_t ah[2][4], al[2][4];
            #pragma unroll
            for (int mt = 0; mt < 2; mt++) {
                uint32_t rbase = (uint32_t)((wm * 32 + mt * 16) * HAS) + kb;
                ldsm_x4(ah[mt], stage + 2 * (rbase + a_off));
                ldsm_x4(al[mt], stage + 2 * (G_A * HAS + rbase + a_off));
            }
            uint32_t bh[4][2], bl[4][2];
            #pragma unroll
            for (int p = 0; p < 2; p++) {
                uint32_t nbase = (uint32_t)((wn * 32 + p * 16) * HAS) + kb;
                uint32_t r4[4];
                ldsm_x4(r4, stage + 2 * (2 * G_A * HAS + nbase + b_off));
                bh[2 * p][0] = r4[0]; bh[2 * p][1] = r4[1];
                bh[2 * p + 1][0] = r4[2]; bh[2 * p + 1][1] = r4[3];
                ldsm_x4(r4, stage + 2 * (2 * G_A * HAS + G_B * HAS + nbase + b_off));
                bl[2 * p][0] = r4[0]; bl[2 * p][1] = r4[1];
                bl[2 * p + 1][0] = r4[2]; bl[2 * p + 1][1] = r4[3];
            }
            #pragma unroll
            for (int nt = 0; nt < 4; nt++) {
                #pragma unroll
                for (int mt = 0; mt < 2; mt++) {
                    mma_f16(dm[mt][nt], ah[mt][0], ah[mt][1], ah[mt][2], ah[mt][3], bh[nt][0], bh[nt][1]);
                    mma_f16(dc[mt][nt], ah[mt][0], ah[mt][1], ah[mt][2], ah[mt][3], bl[nt][0], bl[nt][1]);
                    mma_f16(dc[mt][nt], al[mt][0], al[mt][1], al[mt][2], al[mt][3], bh[nt][0], bh[nt][1]);
                }
            }
        }

        // ---- issue stage kt+2 (overwrites stage (kt+2)%3, last read at kt-1; safe
        //      because the kt-1 iteration ended with a full barrier) ----
        int nk = kt + 2;
        if (nk < ktiles) {
            int st = nk % 3;
            __half* Ahs = hsm + st * HSTAGE;
            __half* Als = Ahs + G_A * HAS;
            __half* Bhs = Als + G_A * HAS;
            __half* Bls = Bhs + G_B * HAS;
            int k0 = nk << 5;
            #pragma unroll
            for (int i = 0; i < 4; i++) {
                int id = tid + 256 * i;
                int arr = id >> 9, rem = id & 511;
                int row = rem >> 2, ch = rem & 3;
                int r = row0 + row;
                int rc = r < M ? r : (M - 1);
                int pb = r < M ? 16 : 0;
                const __half* src = (arr ? Al_g : Ah_g) + (size_t)rc * K + k0 + ch * 8;
                __half* dst = (arr ? Als : Ahs) + row * HAS + ch * 8;
                cp_async16((uint32_t)__cvta_generic_to_shared(dst), src, pb);
            }
            #pragma unroll
            for (int i = 0; i < 2; i++) {
                int id = tid + 256 * i;
                int arr = id >> 8, rem = id & 255;
                int row = rem >> 2, ch = rem & 3;
                const __half* src = (arr ? Bl_g : Bh_g) + (size_t)(col0 + row) * K + k0 + ch * 8;
                __half* dst = (arr ? Bls : Bhs) + row * HAS + ch * 8;
                cp_async16((uint32_t)__cvta_generic_to_shared(dst), src, 16);
            }
        }
        cp_commit();        // empty group when nk >= ktiles keeps wait counts uniform
        cp_wait<1>();       // stage kt+1 ready; stage kt+2 may still fly
        __syncthreads();

        cst = (cst == 2) ? 0 : cst + 1;
    }

    #pragma unroll
    for (int mt = 0; mt < 2; mt++) {
        #pragma unroll
        for (int nt = 0; nt < 4; nt++) {
            int r = row0 + wm * 32 + mt * 16 + g;
            int c = col0 + wn * 32 + nt * 8 + 2 * t;
            float2 bz = *(const float2*)&bias[c];
            float o0 = dm[mt][nt][0] + dc[mt][nt][0] + bsc * bz.x;
            float o1 = dm[mt][nt][1] + dc[mt][nt][1] + bsc * bz.y;
            float o2 = dm[mt][nt][2] + dc[mt][nt][2] + bsc * bz.x;
            float o3 = dm[mt][nt][3] + dc[mt][nt][3] + bsc * bz.y;
            if (mode == 0) {
                float* Cf = cfg.Cf[z];
                if (r < M)     *(float2*)&Cf[(size_t)r * ldc + c] = make_float2(o0, o1);
                if (r + 8 < M) *(float2*)&Cf[(size_t)(r + 8) * ldc + c] = make_float2(o2, o3);
            } else {
                __half* Ch = cfg.Ch[z];
                __half* Cl = cfg.Cl[z];
                __half h0, l0, h1, l1;
                if (r < M) {
                    split_h(o0, h0, l0); split_h(o1, h1, l1);
                    *(__half2*)&Ch[(size_t)r * ldc + c] = __halves2half2(h0, h1);
                    *(__half2*)&Cl[(size_t)r * ldc + c] = __halves2half2(l0, l1);
                }
                if (r + 8 < M) {
                    split_h(o2, h0, l0); split_h(o3, h1, l1);
                    *(__half2*)&Ch[(size_t)(r + 8) * ldc + c] = __halves2half2(h0, h1);
                    *(__half2*)&Cl[(size_t)(r + 8) * ldc + c] = __halves2half2(l0, l1);
                }
            }
        }
    }
}

// ---------------- sentence-level graph attention ----------------
__global__ __launch_bounds__(256) void sent_attn(
    const float* __restrict__ qs, const float* __restrict__ ksn,
    const float* __restrict__ vsn, const float* __restrict__ bias_s,
    const float* __restrict__ gab,
    float* __restrict__ attns_out,
    __half* __restrict__ csh, __half* __restrict__ csl)
{
    const int h = blockIdx.x, b = blockIdx.y;
    const int q = threadIdx.x;

    __shared__ float Ks[NSd][DKd + 1];
    __shared__ float Vs[NSd][DKd + 1];
    __shared__ float G[NSd][NSd + 1];

    for (int idx = q; idx < NSd * DKd; idx += 256) {
        int s = idx >> 6, k = idx & 63;
        Ks[s][k] = ksn[(size_t)(b * NSd + s) * Dd + h * DKd + k];
        Vs[s][k] = vsn[(size_t)(b * NSd + s) * Dd + h * DKd + k];
    }
    for (int idx = q; idx < NSd * NSd; idx += 256) {
        int s = idx / NSd, tt = idx % NSd;
        G[s][tt] = gab[((size_t)(b * Hd + h) * NSd + s) * NSd + tt];
    }
    __syncthreads();

    float qreg[DKd];
    const float* qrow = qs + (size_t)(b * LQd + q) * Dd + h * DKd;
    #pragma unroll
    for (int k = 0; k < DKd; k++) qreg[k] = qrow[k] * 0.125f;

    float a[NSd];
    const float* bsrow = bias_s + ((size_t)(b * Hd + h) * LQd + q) * NSd;
    #pragma unroll
    for (int s = 0; s < NSd; s++) {
        float dd = 0.f;
        #pragma unroll
        for (int k = 0; k < DKd; k++) dd += qreg[k] * Ks[s][k];
        a[s] = dd + bsrow[s];
    }

    float m = -1e30f;
    #pragma unroll
    for (int s = 0; s < NSd; s++) m = fmaxf(m, a[s]);
    float smx[NSd]; float sum = 0.f;
    #pragma unroll
    for (int s = 0; s < NSd; s++) { smx[s] = __expf(a[s] - m); sum += smx[s]; }
    float inv = 1.f / sum;

    float gg[NSd];
    #pragma unroll
    for (int tt = 0; tt < NSd; tt++) {
        float dd = 0.f;
        #pragma unroll
        for (int s = 0; s < NSd; s++) dd += smx[s] * G[s][tt];
        gg[tt] = dd * inv;
    }
    #pragma unroll
    for (int s = 0; s < NSd; s++) a[s] -= 0.5f * gg[s] * gg[s];

    m = -1e30f;
    #pragma unroll
    for (int s = 0; s < NSd; s++) m = fmaxf(m, a[s]);
    sum = 0.f;
    #pragma unroll
    for (int s = 0; s < NSd; s++) { a[s] = __expf(a[s] - m); sum += a[s]; }
    inv = 1.f / sum;

    float* arow = attns_out + ((size_t)(b * Hd + h) * LQd + q) * NSd;
    #pragma unroll
    for (int s = 0; s < NSd; s++) { a[s] *= inv; arow[s] = a[s]; }

    size_t cbase = (size_t)(b * LQd + q) * Dd + h * DKd;
    #pragma unroll
    for (int dd = 0; dd < DKd; dd++) {
        float acc = 0.f;
        #pragma unroll
        for (int s = 0; s < NSd; s++) acc += a[s] * Vs[s][dd];
        __half hi, lo;
        split_h(acc, hi, lo);
        csh[cbase + dd] = hi;
        csl[cbase + dd] = lo;
    }
}

// ---------------- word-level attention v4: ldmatrix everywhere ----------------
#define HQS 72
#define W_QH 0
#define W_QL (32 * HQS)
#define W_KV (2 * 32 * HQS)
#define W_ARR (128 * HQS)
#define W_P  (W_KV + 4 * W_ARR)
#define PROW 264
#define WSMEM_BYTES ((W_P + 32 * PROW) * 2)

__global__ __launch_bounds__(512, 2) void word_attn_h4(
    const __half* __restrict__ qwh, const __half* __restrict__ qwl,
    const __half* __restrict__ kwh, const __half* __restrict__ kwl,
    const __half* __restrict__ vwh, const __half* __restrict__ vwl,
    const float* __restrict__ bias_w, const float* __restrict__ attns,
    __half* __restrict__ cwh, __half* __restrict__ cwl)
{
    extern __shared__ __half hsm[];
    float* Ps = (float*)(hsm + W_P);
    __half* PU = hsm + W_P;

    const int tid = threadIdx.x;
    const int wid = tid >> 5;
    const int lane = tid & 31;
    const int g = lane >> 2;
    const int t = lane & 3;
    const int wm = wid & 1;
    const int wn = wid >> 1;
    const int q0 = blockIdx.x * 32;
    const int h  = blockIdx.y;
    const int b  = blockIdx.z;

    const int q8 = lane & 7;
    const int seg = lane >> 3;
    const uint32_t smem_base = (uint32_t)__cvta_generic_to_shared(hsm);
    const uint32_t aq_off = (uint32_t)((q8 + (seg & 1) * 8) * HQS + (seg >> 1) * 8);
    const uint32_t bk_off = (uint32_t)((q8 + (seg >> 1) * 8) * HQS + (seg & 1) * 8);
    const uint32_t ap_off = (uint32_t)((q8 + (seg & 1) * 8) * PROW + (seg >> 1) * 8);
    const uint32_t v_arr  = (seg >> 1) ? (uint32_t)(W_KV + 3 * W_ARR) : (uint32_t)(W_KV + 2 * W_ARR);
    const uint32_t v_off  = (uint32_t)((q8 + (seg & 1) * 8) * HQS + wn * 8);

    // issue Q + stage-0 K/V loads
    {
        {
            int arr = tid >> 8, rem = tid & 255;
            int row = rem >> 3, ch = rem & 7;
            const __half* src = (arr == 0 ? qwh : qwl) + (size_t)(b * LQd + q0 + row) * Dd + h * DKd + ch * 8;
            uint32_t dst = (uint32_t)__cvta_generic_to_shared(
                &hsm[(arr == 0 ? W_QH : W_QL) + row * HQS + ch * 8]);
            cp_async16(dst, src, 16);
        }
        const size_t kvb = (size_t)(b * NSd) * NTd * Dd + h * DKd;
        const __half* srcs[4] = {kwh, kwl, vwh, vwl};
        #pragma unroll
        for (int i = 0; i < 8; i++) {
            int id = tid + 512 * i;
            int arr = id >> 10, rem = id & 1023;
            int row = rem >> 3, ch = rem & 7;
            const __half* src = srcs[arr] + kvb + (size_t)row * Dd + ch * 8;
            uint32_t dst = (uint32_t)__cvta_generic_to_shared(
                &hsm[W_KV + arr * W_ARR + row * HQS + ch * 8]);
            cp_async16(dst, src, 16);
        }
        cp_commit();
        cp_wait<0>();
    }
    __syncthreads();

    float om[4], oc[4];
    #pragma unroll
    for (int j = 0; j < 4; j++) { om[j] = 0.f; oc[j] = 0.f; }

    for (int s = 0; s < NSd; s++) {
        // ---- P = Q @ K^T (warp tile 16x16) ----
        float pm[2][4], pc[2][4];
        #pragma unroll
        for (int nt = 0; nt < 2; nt++)
            #pragma unroll
            for (int j = 0; j < 4; j++) { pm[nt][j] = 0.f; pc[nt][j] = 0.f; }

        #pragma unroll
        for (int ks = 0; ks < 4; ks++) {
            const uint32_t kb = (uint32_t)(ks * 16);
            uint32_t ahq[4], alq[4], kh4[4], kl4[4];
            uint32_t qrb = (uint32_t)(wm * 16 * HQS) + kb;
            ldsm_x4(ahq, smem_base + 2 * (W_QH + qrb + aq_off));
            ldsm_x4(alq, smem_base + 2 * (W_QL + qrb + aq_off));
            uint32_t krb = (uint32_t)(wn * 16 * HQS) + kb;
            ldsm_x4(kh4, smem_base + 2 * (W_KV + krb + bk_off));
            ldsm_x4(kl4, smem_base + 2 * (W_KV + W_ARR + krb + bk_off));
            #pragma unroll
            for (int nt = 0; nt < 2; nt++) {
                mma_f16(pm[nt], ahq[0], ahq[1], ahq[2], ahq[3], kh4[2 * nt], kh4[2 * nt + 1]);
                mma_f16(pc[nt], ahq[0], ahq[1], ahq[2], ahq[3], kl4[2 * nt], kl4[2 * nt + 1]);
                mma_f16(pc[nt], alq[0], alq[1], alq[2], alq[3], kh4[2 * nt], kh4[2 * nt + 1]);
            }
        }
        #pragma unroll
        for (int nt = 0; nt < 2; nt++) {
            int r = wm * 16 + g;
            int c = wn * 16 + nt * 8 + 2 * t;
            *(float2*)&Ps[r * 132 + c] = make_float2(pm[nt][0] + pc[nt][0], pm[nt][1] + pc[nt][1]);
            *(float2*)&Ps[(r + 8) * 132 + c] = make_float2(pm[nt][2] + pc[nt][2], pm[nt][3] + pc[nt][3]);
        }
        __syncthreads();

        // ---- softmax + bias + attns scale; write split-fp16 into union rows ----
        const float* bb = bias_w + ((size_t)((b * NSd + s) * Hd + h) * LQd + q0) * NTd;
        #pragma unroll
        for (int rr = 0; rr < 2; rr++) {
            int r = wid * 2 + rr;
            float x0 = Ps[r * 132 + lane]       + bb[r * NTd + lane];
            float x1 = Ps[r * 132 + lane + 32]  + bb[r * NTd + lane + 32];
            float x2 = Ps[r * 132 + lane + 64]  + bb[r * NTd + lane + 64];
            float x3 = Ps[r * 132 + lane + 96]  + bb[r * NTd + lane + 96];
            float mx = fmaxf(fmaxf(x0, x1), fmaxf(x2, x3));
            #pragma unroll
            for (int o = 16; o; o >>= 1) mx = fmaxf(mx, __shfl_xor_sync(0xffffffffu, mx, o));
            x0 = __expf(x0 - mx); x1 = __expf(x1 - mx);
            x2 = __expf(x2 - mx); x3 = __expf(x3 - mx);
            float su = x0 + x1 + x2 + x3;
            #pragma unroll
            for (int o = 16; o; o >>= 1) su += __shfl_xor_sync(0xffffffffu, su, o);
            float wsc = attns[((size_t)(b * Hd + h) * LQd + q0 + r) * NSd + s] / su;
            __half h0, l0, h1, l1, h2, l2, h3, l3;
            split_h(x0 * wsc, h0, l0);
            split_h(x1 * wsc, h1, l1);
            split_h(x2 * wsc, h2, l2);
            split_h(x3 * wsc, h3, l3);
            __syncwarp();   // whole row read before overwrite (union aliasing)
            __half* prow = PU + r * PROW;
            prow[lane]       = h0;  prow[128 + lane]       = l0;
            prow[lane + 32]  = h1;  prow[128 + lane + 32]  = l1;
            prow[lane + 64]  = h2;  prow[128 + lane + 64]  = l2;
            prow[lane + 96]  = h3;  prow[128 + lane + 96]  = l3;
        }
        __syncthreads();

        // ---- O += P @ V (warp tile 16x8, ldmatrix + trans-V) ----
        #pragma unroll
        for (int ks = 0; ks < 8; ks++) {
            const uint32_t kb = (uint32_t)(ks * 16);
            uint32_t ph4[4], pl4[4], v4[4];
            uint32_t prb = (uint32_t)(wm * 16 * PROW) + kb;
            ldsm_x4(ph4, smem_base + 2 * (W_P + prb + ap_off));
            ldsm_x4(pl4, smem_base + 2 * (W_P + prb + 128 + ap_off));
            ldsm_x4_t(v4, smem_base + 2 * (v_arr + kb * HQS + v_off));
            mma_f16(om, ph4[0], ph4[1], ph4[2], ph4[3], v4[0], v4[1]);
            mma_f16(oc, ph4[0], ph4[1], ph4[2], ph4[3], v4[2], v4[3]);
            mma_f16(oc, pl4[0], pl4[1], pl4[2], pl4[3], v4[0], v4[1]);
        }

        // load next K/V stage
        if (s + 1 < NSd) {
            __syncthreads();
            const size_t kvb = (size_t)(b * NSd + s + 1) * NTd * Dd + h * DKd;
            const __half* srcs[4] = {kwh, kwl, vwh, vwl};
            #pragma unroll
            for (int i = 0; i < 8; i++) {
                int id = tid + 512 * i;
                int arr = id >> 10, rem = id & 1023;
                int row = rem >> 3, ch = rem & 7;
                const __half* src = srcs[arr] + kvb + (size_t)row * Dd + ch * 8;
                uint32_t dst = (uint32_t)__cvta_generic_to_shared(
                    &hsm[W_KV + arr * W_ARR + row * HQS + ch * 8]);
                cp_async16(dst, src, 16);
            }
            cp_commit();
            cp_wait<0>();
            __syncthreads();
        }
    }

    {
        int r = q0 + wm * 16 + g;
        int c = h * DKd + wn * 8 + 2 * t;
        float v0 = om[0] + oc[0], v1 = om[1] + oc[1];
        float v2 = om[2] + oc[2], v3 = om[3] + oc[3];
        __half h0, l0, h1, l1;
        split_h(v0, h0, l0); split_h(v1, h1, l1);
        *(__half2*)&cwh[(size_t)(b * LQd + r) * Dd + c] = __halves2half2(h0, h1);
        *(__half2*)&cwl[(size_t)(b * LQd + r) * Dd + c] = __halves2half2(l0, l1);
        split_h(v2, h0, l0); split_h(v3, h1, l1);
        *(__half2*)&cwh[(size_t)(b * LQd + r + 8) * Dd + c] = __halves2half2(h0, h1);
        *(__half2*)&cwl[(size_t)(b * LQd + r + 8) * Dd + c] = __halves2half2(l0, l1);
    }
}

// ---------------- host ----------------
extern "C" void kernel_launch(void* const* d_in, const int* in_sizes, int n_in,
                              void* d_out, int out_size)
{
    const float* q      = (const float*)d_in[0];
    const float* k_s    = (const float*)d_in[1];
    const float* v_s    = (const float*)d_in[2];
    const float* k_w    = (const float*)d_in[3];
    const float* v_w    = (const float*)d_in[4];
    const float* bias_w = (const float*)d_in[5];
    const float* bias_s = (const float*)d_in[6];
    const float* gab    = (const float*)d_in[7];

    const float *wq_s, *bq_s, *wk_s, *bk_s, *wv_s, *bv_s;
    const float *wq_w, *bq_w, *wk_w, *bk_w, *wv_w, *bv_w;
    const float *fcs_w, *fcs_b, *fcw_w, *fcw_b, *fco_w, *fco_b;

    if (in_sizes[9] == 512) {
        wq_s = (const float*)d_in[8];  bq_s = (const float*)d_in[9];
        wk_s = (const float*)d_in[10]; bk_s = (const float*)d_in[11];
        wv_s = (const float*)d_in[12]; bv_s = (const float*)d_in[13];
        wq_w = (const float*)d_in[14]; bq_w = (const float*)d_in[15];
        wk_w = (const float*)d_in[16]; bk_w = (const float*)d_in[17];
        wv_w = (const float*)d_in[18]; bv_w = (const float*)d_in[19];
        fcs_w = (const float*)d_in[20]; fcs_b = (const float*)d_in[21];
        fcw_w = (const float*)d_in[22]; fcw_b = (const float*)d_in[23];
        fco_w = (const float*)d_in[24]; fco_b = (const float*)d_in[25];
    } else {
        wq_s = (const float*)d_in[8];  wk_s = (const float*)d_in[9];
        wv_s = (const float*)d_in[10]; wq_w = (const float*)d_in[11];
        wk_w = (const float*)d_in[12]; wv_w = (const float*)d_in[13];
        fcs_w = (const float*)d_in[14]; fcw_w = (const float*)d_in[15];
        bq_s = (const float*)d_in[16]; bk_s = (const float*)d_in[17];
        bv_s = (const float*)d_in[18]; bq_w = (const float*)d_in[19];
        bk_w = (const float*)d_in[20]; bv_w = (const float*)d_in[21];
        fcs_b = (const float*)d_in[22]; fcw_b = (const float*)d_in[23];
        fco_w = (const float*)d_in[24]; fco_b = (const float*)d_in[25];
    }

    float* scratch = nullptr;
    cudaGetSymbolAddress((void**)&scratch, g_scratch);
    float* s_qs  = scratch + OFF_QS;
    float* s_ks  = scratch + OFF_KS;
    float* s_vs  = scratch + OFF_VS;
    float* s_att = scratch + OFF_ATT;
    __half* hb = (__half*)(scratch + OFF_HALF);
    __half* acth = hb + H_ACTH;
    __half* actl = hb + H_ACTL;
    __half* wth  = hb + H_WTH;
    __half* wtl  = hb + H_WTL;
    __half* qwh  = hb + H_QWH;
    __half* qwl  = hb + H_QWL;
    __half* kwh  = hb + H_KWH;
    __half* kwl  = hb + H_KWL;
    __half* vwh  = hb + H_VWH;
    __half* vwl  = hb + H_VWL;
    __half* csh  = hb + H_CSH;
    __half* csl  = hb + H_CSL;
    __half* cwh  = hb + H_CWH;
    __half* cwl  = hb + H_CWL;
    __half* cath = hb + H_CATH;
    __half* catl = hb + H_CATL;

    cudaFuncSetAttribute(gemm_cfg, cudaFuncAttributeMaxDynamicSharedMemorySize, HSMEM_BYTES);
    cudaFuncSetAttribute(word_attn_h4, cudaFuncAttributeMaxDynamicSharedMemorySize, WSMEM_BYTES);

    // prep
    ASplitArgs aa;
    aa.src[0] = q; aa.src[1] = k_s; aa.src[2] = v_s; aa.src[3] = k_w; aa.src[4] = v_w;
    act_split<<<dim3(256, 5), 256>>>(aa, acth, actl);
    WSplitArgs wa;
    wa.src[0] = wq_s; wa.src[1] = wk_s; wa.src[2] = wv_s;
    wa.src[3] = wq_w; wa.src[4] = wk_w; wa.src[5] = wv_w;
    wa.src[6] = fcs_w; wa.src[7] = fcw_w; wa.src[8] = fco_w;
    w_transplit<<<dim3(16, 32, 9), dim3(32, 8)>>>(wa, wth, wtl);

    // merged projections
    {
        GemmCfg c = {};
        c.K = 512; c.ldc = 512;
        c.Ah[0] = acth + AQ;  c.Al[0] = actl + AQ;
        c.Ah[1] = acth + AQ;  c.Al[1] = actl + AQ;
        c.Ah[2] = acth + AKS; c.Al[2] = actl + AKS;
        c.Ah[3] = acth + AVS; c.Al[3] = actl + AVS;
        c.Bh[0] = wth + WOFF(0); c.Bl[0] = wtl + WOFF(0);
        c.Bh[1] = wth + WOFF(3); c.Bl[1] = wtl + WOFF(3);
        c.Bh[2] = wth + WOFF(1); c.Bl[2] = wtl + WOFF(1);
        c.Bh[3] = wth + WOFF(2); c.Bl[3] = wtl + WOFF(2);
        c.bias[0] = bq_s; c.bias[1] = bq_w; c.bias[2] = bk_s; c.bias[3] = bv_s;
        c.bscale[0] = 1.f; c.bscale[1] = 0.125f; c.bscale[2] = 1.f; c.bscale[3] = 1.f;
        c.M[0] = 1024; c.M[1] = 1024; c.M[2] = 96; c.M[3] = 96;
        c.mode[0] = 0; c.mode[1] = 1; c.mode[2] = 0; c.mode[3] = 0;
        c.Cf[0] = s_qs; c.Cf[2] = s_ks; c.Cf[3] = s_vs;
        c.Ch[1] = qwh;  c.Cl[1] = qwl;
        gemm_cfg<<<dim3(8, 8, 4), 256, HSMEM_BYTES>>>(c);
    }
    // big word projections
    {
        GemmCfg c = {};
        c.K = 512; c.ldc = 512;
        c.Ah[0] = acth + AKW; c.Al[0] = actl + AKW;
        c.Ah[1] = acth + AVW; c.Al[1] = actl + AVW;
        c.Bh[0] = wth + WOFF(4); c.Bl[0] = wtl + WOFF(4);
        c.Bh[1] = wth + WOFF(5); c.Bl[1] = wtl + WOFF(5);
        c.bias[0] = bk_w; c.bias[1] = bv_w;
        c.bscale[0] = 1.f; c.bscale[1] = 1.f;
        c.M[0] = 12288; c.M[1] = 12288;
        c.mode[0] = 1; c.mode[1] = 1;
        c.Ch[0] = kwh; c.Cl[0] = kwl;
        c.Ch[1] = vwh; c.Cl[1] = vwl;
        gemm_cfg<<<dim3(8, 96, 2), 256, HSMEM_BYTES>>>(c);
    }

    sent_attn<<<dim3(Hd, BB), 256>>>(s_qs, s_ks, s_vs, bias_s, gab, s_att, csh, csl);

    word_attn_h4<<<dim3(8, Hd, BB), 512, WSMEM_BYTES>>>(
        qwh, qwl, kwh, kwl, vwh, vwl, bias_w, s_att, cwh, cwl);

    // fcs / fcw -> split cat
    {
        GemmCfg c = {};
        c.K = 512; c.ldc = 1024;
        c.Ah[0] = csh; c.Al[0] = csl;
        c.Ah[1] = cwh; c.Al[1] = cwl;
        c.Bh[0] = wth + WOFF(6); c.Bl[0] = wtl + WOFF(6);
        c.Bh[1] = wth + WOFF(7); c.Bl[1] = wtl + WOFF(7);
        c.bias[0] = fcs_b; c.bias[1] = fcw_b;
        c.bscale[0] = 1.f; c.bscale[1] = 1.f;
        c.M[0] = 1024; c.M[1] = 1024;
        c.mode[0] = 1; c.mode[1] = 1;
        c.Ch[0] = cath;       c.Cl[0] = catl;
        c.Ch[1] = cath + 512; c.Cl[1] = catl + 512;
        gemm_cfg<<<dim3(8, 8, 2), 256, HSMEM_BYTES>>>(c);
    }
    // final fco -> fp32 out
    {
        GemmCfg c = {};
        c.K = 1024; c.ldc = 512;
        c.Ah[0] = cath; c.Al[0] = catl;
        c.Bh[0] = wth + WOFF(8); c.Bl[0] = wtl + WOFF(8);
        c.bias[0] = fco_b;
        c.bscale[0] = 1.f;
        c.M[0] = 1024;
        c.mode[0] = 0;
        c.Cf[0] = (float*)d_out;
        gemm_cfg<<<dim3(8, 8, 1), 256, HSMEM_BYTES>>>(c);
    }
}

// round 12
// speedup vs baseline: 2.4498x; 1.3123x over previous
#include <cuda_runtime.h>
#include <cuda_fp16.h>
#include <math.h>
#include <stdint.h>

// Problem constants
#define BB   4
#define LQd  256
#define NSd  24
#define NTd  128
#define Dd   512
#define Hd   8
#define DKd  64

// ---------------- scratch layout ----------------
#define OFF_QS   0
#define OFF_KS   524288
#define OFF_VS   573440
#define OFF_ATT  622592
#define OFF_HALF 819200
#define H_ACTH 0
#define H_ACTL 13205504
#define H_WTH  26411008
#define H_WTL  29032448
#define H_QWH  31653888
#define H_QWL  32178176
#define H_KWH  32702464
#define H_KWL  38993920
#define H_VWH  45285376
#define H_VWL  51576832
#define H_CSH  57868288
#define H_CSL  58392576
#define H_CWH  58916864
#define H_CWL  59441152
#define H_CATH 59965440
#define H_CATL 61014016
#define H_TOTAL 62062592
#define SCRATCH_TOTAL (OFF_HALF + H_TOTAL / 2)
__device__ float g_scratch[SCRATCH_TOTAL];

#define AQ   0
#define AKS  524288
#define AVS  573440
#define AKW  622592
#define AVW  6914048
#define WOFF(i) ((i) * 262144)

// ---------------- helpers ----------------
__device__ __forceinline__ void split_h(float x, __half& hi, __half& lo) {
    hi = __float2half_rn(x);
    lo = __float2half_rn(x - __half2float(hi));
}
__device__ __forceinline__ void mma_f16(float d[4],
                                        uint32_t a0, uint32_t a1, uint32_t a2, uint32_t a3,
                                        uint32_t b0, uint32_t b1) {
    asm volatile(
        "mma.sync.aligned.m16n8k16.row.col.f32.f16.f16.f32 "
        "{%0,%1,%2,%3},{%4,%5,%6,%7},{%8,%9},{%0,%1,%2,%3};"
        : "+f"(d[0]), "+f"(d[1]), "+f"(d[2]), "+f"(d[3])
        : "r"(a0), "r"(a1), "r"(a2), "r"(a3), "r"(b0), "r"(b1));
}
__device__ __forceinline__ void ldsm_x4(uint32_t r[4], uint32_t addr) {
    asm volatile("ldmatrix.sync.aligned.m8n8.x4.shared.b16 {%0,%1,%2,%3}, [%4];"
                 : "=r"(r[0]), "=r"(r[1]), "=r"(r[2]), "=r"(r[3]) : "r"(addr));
}
__device__ __forceinline__ void ldsm_x4_t(uint32_t r[4], uint32_t addr) {
    asm volatile("ldmatrix.sync.aligned.m8n8.x4.trans.shared.b16 {%0,%1,%2,%3}, [%4];"
                 : "=r"(r[0]), "=r"(r[1]), "=r"(r[2]), "=r"(r[3]) : "r"(addr));
}
__device__ __forceinline__ void cp_async16(uint32_t smem_addr, const void* gptr, int src_bytes) {
    asm volatile("cp.async.cg.shared.global [%0], [%1], 16, %2;"
                 :: "r"(smem_addr), "l"(gptr), "r"(src_bytes) : "memory");
}
__device__ __forceinline__ void cp_commit() { asm volatile("cp.async.commit_group;" ::: "memory"); }
template <int N>
__device__ __forceinline__ void cp_wait() { asm volatile("cp.async.wait_group %0;" :: "n"(N) : "memory"); }

// ---------------- prep: convert activations to fp16 (hi only) ----------------
struct ASplitArgs { const float* src[5]; };
__constant__ int c_alen[5] = {524288, 49152, 49152, 6291456, 6291456};
__constant__ int c_aoff[5] = {AQ, AKS, AVS, AKW, AVW};

__global__ __launch_bounds__(256) void act_split(ASplitArgs args, __half* acth)
{
    int z = blockIdx.y;
    int n = c_alen[z];
    const float* s = args.src[z];
    __half* dh = acth + c_aoff[z];
    for (int i = blockIdx.x * 256 + threadIdx.x; i < n; i += gridDim.x * 256) {
        dh[i] = __float2half_rn(s[i]);
    }
}

// ---------------- prep: transpose+split weights (B keeps hi/lo) ----------------
struct WSplitArgs { const float* src[9]; };
__constant__ int c_wK[9] = {512, 512, 512, 512, 512, 512, 512, 512, 1024};
__constant__ int c_woff[9] = {WOFF(0), WOFF(1), WOFF(2), WOFF(3), WOFF(4),
                              WOFF(5), WOFF(6), WOFF(7), WOFF(8)};
__constant__ float c_wscale[9] = {1.f, 1.f, 1.f, 0.125f, 1.f, 1.f, 1.f, 1.f, 1.f};

__global__ void w_transplit(WSplitArgs args, __half* wth, __half* wtl)
{
    int z = blockIdx.z;
    int Kw = c_wK[z];
    int k0 = blockIdx.y * 32;
    if (k0 >= Kw) return;
    int n0 = blockIdx.x * 32;
    const float* W = args.src[z];
    float sc = c_wscale[z];
    __half* th = wth + c_woff[z];
    __half* tl = wtl + c_woff[z];

    __shared__ float ts[32][33];
    int tx = threadIdx.x, ty = threadIdx.y;
    #pragma unroll
    for (int r = 0; r < 4; r++)
        ts[ty + 8 * r][tx] = W[(size_t)(k0 + ty + 8 * r) * 512 + n0 + tx];
    __syncthreads();
    #pragma unroll
    for (int r = 0; r < 4; r++) {
        int n = n0 + ty + 8 * r;
        int k = k0 + tx;
        __half hi, lo;
        split_h(sc * ts[tx][ty + 8 * r], hi, lo);
        th[(size_t)n * Kw + k] = hi;
        tl[(size_t)n * Kw + k] = lo;
    }
}

// ---------------- 2-term GEMM: A fp16, B split hi/lo, 3-stage pipeline ----------------
#define HAS 40
#define G_A 128
#define G_B 64
#define HSTAGE ((G_A + 2 * G_B) * HAS)       // 10240 halves per stage
#define HSMEM_BYTES (3 * HSTAGE * 2)         // 61440 B

struct GemmCfg {
    const __half* Ah[6];
    const __half* Bh[6]; const __half* Bl[6];
    const float* bias[6];
    float* Cf[6];
    __half* Ch[6]; __half* Cl[6];
    int M[6]; int mode[6]; float bscale[6];
    int K; int ldc;
};

__global__ __launch_bounds__(256, 2) void gemm_cfg(GemmCfg cfg)
{
    extern __shared__ __half hsm[];

    const int z = blockIdx.z;
    const int M = cfg.M[z];
    const int row0 = blockIdx.y * 128;
    if (row0 >= M) return;

    const __half* Ah_g = cfg.Ah[z];
    const __half* Bh_g = cfg.Bh[z];
    const __half* Bl_g = cfg.Bl[z];
    const float* bias  = cfg.bias[z];
    const int mode     = cfg.mode[z];
    const float bsc    = cfg.bscale[z];
    const int K        = cfg.K;
    const int ldc      = cfg.ldc;

    const int tid = threadIdx.x;
    const int wid = tid >> 5;
    const int lane = tid & 31;
    const int g = lane >> 2;
    const int t = lane & 3;
    const int wm = wid & 3;
    const int wn = wid >> 2;
    const int col0 = blockIdx.x * 64;

    const int q8 = lane & 7;
    const int seg = lane >> 3;
    const uint32_t smem_base = (uint32_t)__cvta_generic_to_shared(hsm);
    const uint32_t a_off = (uint32_t)((q8 + (seg & 1) * 8) * HAS + (seg >> 1) * 8);
    const uint32_t b_off = (uint32_t)((q8 + (seg >> 1) * 8) * HAS + (seg & 1) * 8);

    float dm[2][4][4], dc[2][4][4];
    #pragma unroll
    for (int mt = 0; mt < 2; mt++)
        #pragma unroll
        for (int nt = 0; nt < 4; nt++)
            #pragma unroll
            for (int j = 0; j < 4; j++) { dm[mt][nt][j] = 0.f; dc[mt][nt][j] = 0.f; }

    const int ktiles = K >> 5;

    // ---- prologue: fill stages 0 and 1 ----
    #pragma unroll
    for (int p = 0; p < 2; p++) {
        __half* Ahs = hsm + p * HSTAGE;
        __half* Bhs = Ahs + G_A * HAS;
        __half* Bls = Bhs + G_B * HAS;
        int k0 = p << 5;
        #pragma unroll
        for (int i = 0; i < 2; i++) {       // A: 512 slots
            int id = tid + 256 * i;
            int row = id >> 2, ch = id & 3;
            int r = row0 + row;
            int rc = r < M ? r : (M - 1);
            int pb = r < M ? 16 : 0;
            cp_async16((uint32_t)__cvta_generic_to_shared(&Ahs[row * HAS + ch * 8]),
                       &Ah_g[(size_t)rc * K + k0 + ch * 8], pb);
        }
        #pragma unroll
        for (int i = 0; i < 2; i++) {       // B: 512 slots (hi+lo)
            int id = tid + 256 * i;
            int arr = id >> 8, rem = id & 255;
            int row = rem >> 2, ch = rem & 3;
            const __half* src = (arr ? Bl_g : Bh_g) + (size_t)(col0 + row) * K + k0 + ch * 8;
            __half* dst = (arr ? Bls : Bhs) + row * HAS + ch * 8;
            cp_async16((uint32_t)__cvta_generic_to_shared(dst), src, 16);
        }
        cp_commit();
    }
    cp_wait<1>();
    __syncthreads();

    int cst = 0;

    for (int kt = 0; kt < ktiles; kt++) {
        const uint32_t stage = smem_base + (uint32_t)((cst * HSTAGE) * 2);

        #pragma unroll
        for (int ks = 0; ks < 2; ks++) {
            const uint32_t kb = (uint32_t)(ks * 16);
            uint32_t ah[2][4];
            #pragma unroll
            for (int mt = 0; mt < 2; mt++) {
                uint32_t rbase = (uint32_t)((wm * 32 + mt * 16) * HAS) + kb;
                ldsm_x4(ah[mt], stage + 2 * (rbase + a_off));
            }
            uint32_t bh[4][2], bl[4][2];
            #pragma unroll
            for (int p = 0; p < 2; p++) {
                uint32_t nbase = (uint32_t)((wn * 32 + p * 16) * HAS) + kb;
                uint32_t r4[4];
                ldsm_x4(r4, stage + 2 * (G_A * HAS + nbase + b_off));
                bh[2 * p][0] = r4[0]; bh[2 * p][1] = r4[1];
                bh[2 * p + 1][0] = r4[2]; bh[2 * p + 1][1] = r4[3];
                ldsm_x4(r4, stage + 2 * (G_A * HAS + G_B * HAS + nbase + b_off));
                bl[2 * p][0] = r4[0]; bl[2 * p][1] = r4[1];
                bl[2 * p + 1][0] = r4[2]; bl[2 * p + 1][1] = r4[3];
            }
            #pragma unroll
            for (int nt = 0; nt < 4; nt++) {
                #pragma unroll
                for (int mt = 0; mt < 2; mt++) {
                    mma_f16(dm[mt][nt], ah[mt][0], ah[mt][1], ah[mt][2], ah[mt][3], bh[nt][0], bh[nt][1]);
                    mma_f16(dc[mt][nt], ah[mt][0], ah[mt][1], ah[mt][2], ah[mt][3], bl[nt][0], bl[nt][1]);
                }
            }
        }

        int nk = kt + 2;
        if (nk < ktiles) {
            int st = nk % 3;
            __half* Ahs = hsm + st * HSTAGE;
            __half* Bhs = Ahs + G_A * HAS;
            __half* Bls = Bhs + G_B * HAS;
            int k0 = nk << 5;
            #pragma unroll
            for (int i = 0; i < 2; i++) {
                int id = tid + 256 * i;
                int row = id >> 2, ch = id & 3;
                int r = row0 + row;
                int rc = r < M ? r : (M - 1);
                int pb = r < M ? 16 : 0;
                cp_async16((uint32_t)__cvta_generic_to_shared(&Ahs[row * HAS + ch * 8]),
                           &Ah_g[(size_t)rc * K + k0 + ch * 8], pb);
            }
            #pragma unroll
            for (int i = 0; i < 2; i++) {
                int id = tid + 256 * i;
                int arr = id >> 8, rem = id & 255;
                int row = rem >> 2, ch = rem & 3;
                const __half* src = (arr ? Bl_g : Bh_g) + (size_t)(col0 + row) * K + k0 + ch * 8;
                __half* dst = (arr ? Bls : Bhs) + row * HAS + ch * 8;
                cp_async16((uint32_t)__cvta_generic_to_shared(dst), src, 16);
            }
        }
        cp_commit();
        cp_wait<1>();
        __syncthreads();

        cst = (cst == 2) ? 0 : cst + 1;
    }

    #pragma unroll
    for (int mt = 0; mt < 2; mt++) {
        #pragma unroll
        for (int nt = 0; nt < 4; nt++) {
            int r = row0 + wm * 32 + mt * 16 + g;
            int c = col0 + wn * 32 + nt * 8 + 2 * t;
            float2 bz = *(const float2*)&bias[c];
            float o0 = dm[mt][nt][0] + dc[mt][nt][0] + bsc * bz.x;
            float o1 = dm[mt][nt][1] + dc[mt][nt][1] + bsc * bz.y;
            float o2 = dm[mt][nt][2] + dc[mt][nt][2] + bsc * bz.x;
            float o3 = dm[mt][nt][3] + dc[mt][nt][3] + bsc * bz.y;
            if (mode == 0) {
                float* Cf = cfg.Cf[z];
                if (r < M)     *(float2*)&Cf[(size_t)r * ldc + c] = make_float2(o0, o1);
                if (r + 8 < M) *(float2*)&Cf[(size_t)(r + 8) * ldc + c] = make_float2(o2, o3);
            } else {
                __half* Ch = cfg.Ch[z];
                __half* Cl = cfg.Cl[z];
                __half h0, l0, h1, l1;
                if (r < M) {
                    split_h(o0, h0, l0); split_h(o1, h1, l1);
                    *(__half2*)&Ch[(size_t)r * ldc + c] = __halves2half2(h0, h1);
                    *(__half2*)&Cl[(size_t)r * ldc + c] = __halves2half2(l0, l1);
                }
                if (r + 8 < M) {
                    split_h(o2, h0, l0); split_h(o3, h1, l1);
                    *(__half2*)&Ch[(size_t)(r + 8) * ldc + c] = __halves2half2(h0, h1);
                    *(__half2*)&Cl[(size_t)(r + 8) * ldc + c] = __halves2half2(l0, l1);
                }
            }
        }
    }
}

// ---------------- sentence-level graph attention ----------------
__global__ __launch_bounds__(256) void sent_attn(
    const float* __restrict__ qs, const float* __restrict__ ksn,
    const float* __restrict__ vsn, const float* __restrict__ bias_s,
    const float* __restrict__ gab,
    float* __restrict__ attns_out,
    __half* __restrict__ csh)
{
    const int h = blockIdx.x, b = blockIdx.y;
    const int q = threadIdx.x;

    __shared__ float Ks[NSd][DKd + 1];
    __shared__ float Vs[NSd][DKd + 1];
    __shared__ float G[NSd][NSd + 1];

    for (int idx = q; idx < NSd * DKd; idx += 256) {
        int s = idx >> 6, k = idx & 63;
        Ks[s][k] = ksn[(size_t)(b * NSd + s) * Dd + h * DKd + k];
        Vs[s][k] = vsn[(size_t)(b * NSd + s) * Dd + h * DKd + k];
    }
    for (int idx = q; idx < NSd * NSd; idx += 256) {
        int s = idx / NSd, tt = idx % NSd;
        G[s][tt] = gab[((size_t)(b * Hd + h) * NSd + s) * NSd + tt];
    }
    __syncthreads();

    float qreg[DKd];
    const float* qrow = qs + (size_t)(b * LQd + q) * Dd + h * DKd;
    #pragma unroll
    for (int k = 0; k < DKd; k++) qreg[k] = qrow[k] * 0.125f;

    float a[NSd];
    const float* bsrow = bias_s + ((size_t)(b * Hd + h) * LQd + q) * NSd;
    #pragma unroll
    for (int s = 0; s < NSd; s++) {
        float dd = 0.f;
        #pragma unroll
        for (int k = 0; k < DKd; k++) dd += qreg[k] * Ks[s][k];
        a[s] = dd + bsrow[s];
    }

    float m = -1e30f;
    #pragma unroll
    for (int s = 0; s < NSd; s++) m = fmaxf(m, a[s]);
    float smx[NSd]; float sum = 0.f;
    #pragma unroll
    for (int s = 0; s < NSd; s++) { smx[s] = __expf(a[s] - m); sum += smx[s]; }
    float inv = 1.f / sum;

    float gg[NSd];
    #pragma unroll
    for (int tt = 0; tt < NSd; tt++) {
        float dd = 0.f;
        #pragma unroll
        for (int s = 0; s < NSd; s++) dd += smx[s] * G[s][tt];
        gg[tt] = dd * inv;
    }
    #pragma unroll
    for (int s = 0; s < NSd; s++) a[s] -= 0.5f * gg[s] * gg[s];

    m = -1e30f;
    #pragma unroll
    for (int s = 0; s < NSd; s++) m = fmaxf(m, a[s]);
    sum = 0.f;
    #pragma unroll
    for (int s = 0; s < NSd; s++) { a[s] = __expf(a[s] - m); sum += a[s]; }
    inv = 1.f / sum;

    float* arow = attns_out + ((size_t)(b * Hd + h) * LQd + q) * NSd;
    #pragma unroll
    for (int s = 0; s < NSd; s++) { a[s] *= inv; arow[s] = a[s]; }

    size_t cbase = (size_t)(b * LQd + q) * Dd + h * DKd;
    #pragma unroll
    for (int dd = 0; dd < DKd; dd++) {
        float acc = 0.f;
        #pragma unroll
        for (int s = 0; s < NSd; s++) acc += a[s] * Vs[s][dd];
        csh[cbase + dd] = __float2half_rn(acc);
    }
}

// ---------------- word-level attention v5: 2-term split ----------------
// Q pure fp16; K/V split hi/lo; P pure fp16.
#define HQS 72
#define W_QH 0
#define W_KV (32 * HQS)
#define W_ARR (128 * HQS)
#define W_P  (W_KV + 4 * W_ARR)
#define PROW 264
#define WSMEM_BYTES ((W_P + 32 * PROW) * 2)

__global__ __launch_bounds__(512, 2) void word_attn_h5(
    const __half* __restrict__ qwh,
    const __half* __restrict__ kwh, const __half* __restrict__ kwl,
    const __half* __restrict__ vwh, const __half* __restrict__ vwl,
    const float* __restrict__ bias_w, const float* __restrict__ attns,
    __half* __restrict__ cwh)
{
    extern __shared__ __half hsm[];
    float* Ps = (float*)(hsm + W_P);
    __half* PU = hsm + W_P;

    const int tid = threadIdx.x;
    const int wid = tid >> 5;
    const int lane = tid & 31;
    const int g = lane >> 2;
    const int t = lane & 3;
    const int wm = wid & 1;
    const int wn = wid >> 1;
    const int q0 = blockIdx.x * 32;
    const int h  = blockIdx.y;
    const int b  = blockIdx.z;

    const int q8 = lane & 7;
    const int seg = lane >> 3;
    const uint32_t smem_base = (uint32_t)__cvta_generic_to_shared(hsm);
    const uint32_t aq_off = (uint32_t)((q8 + (seg & 1) * 8) * HQS + (seg >> 1) * 8);
    const uint32_t bk_off = (uint32_t)((q8 + (seg >> 1) * 8) * HQS + (seg & 1) * 8);
    const uint32_t ap_off = (uint32_t)((q8 + (seg & 1) * 8) * PROW + (seg >> 1) * 8);
    const uint32_t v_arr  = (seg >> 1) ? (uint32_t)(W_KV + 3 * W_ARR) : (uint32_t)(W_KV + 2 * W_ARR);
    const uint32_t v_off  = (uint32_t)((q8 + (seg & 1) * 8) * HQS + wn * 8);

    // issue Q + stage-0 K/V loads
    {
        if (tid < 256) {
            int row = tid >> 3, ch = tid & 7;
            const __half* src = qwh + (size_t)(b * LQd + q0 + row) * Dd + h * DKd + ch * 8;
            uint32_t dst = (uint32_t)__cvta_generic_to_shared(
                &hsm[W_QH + row * HQS + ch * 8]);
            cp_async16(dst, src, 16);
        }
        const size_t kvb = (size_t)(b * NSd) * NTd * Dd + h * DKd;
        const __half* srcs[4] = {kwh, kwl, vwh, vwl};
        #pragma unroll
        for (int i = 0; i < 8; i++) {
            int id = tid + 512 * i;
            int arr = id >> 10, rem = id & 1023;
            int row = rem >> 3, ch = rem & 7;
            const __half* src = srcs[arr] + kvb + (size_t)row * Dd + ch * 8;
            uint32_t dst = (uint32_t)__cvta_generic_to_shared(
                &hsm[W_KV + arr * W_ARR + row * HQS + ch * 8]);
            cp_async16(dst, src, 16);
        }
        cp_commit();
        cp_wait<0>();
    }
    __syncthreads();

    float om[4], oc[4];
    #pragma unroll
    for (int j = 0; j < 4; j++) { om[j] = 0.f; oc[j] = 0.f; }

    for (int s = 0; s < NSd; s++) {
        // ---- P = Q @ K^T (warp tile 16x16, 2-term) ----
        float pm[2][4], pc[2][4];
        #pragma unroll
        for (int nt = 0; nt < 2; nt++)
            #pragma unroll
            for (int j = 0; j < 4; j++) { pm[nt][j] = 0.f; pc[nt][j] = 0.f; }

        #pragma unroll
        for (int ks = 0; ks < 4; ks++) {
            const uint32_t kb = (uint32_t)(ks * 16);
            uint32_t ahq[4], kh4[4], kl4[4];
            uint32_t qrb = (uint32_t)(wm * 16 * HQS) + kb;
            ldsm_x4(ahq, smem_base + 2 * (W_QH + qrb + aq_off));
            uint32_t krb = (uint32_t)(wn * 16 * HQS) + kb;
            ldsm_x4(kh4, smem_base + 2 * (W_KV + krb + bk_off));
            ldsm_x4(kl4, smem_base + 2 * (W_KV + W_ARR + krb + bk_off));
            #pragma unroll
            for (int nt = 0; nt < 2; nt++) {
                mma_f16(pm[nt], ahq[0], ahq[1], ahq[2], ahq[3], kh4[2 * nt], kh4[2 * nt + 1]);
                mma_f16(pc[nt], ahq[0], ahq[1], ahq[2], ahq[3], kl4[2 * nt], kl4[2 * nt + 1]);
            }
        }
        #pragma unroll
        for (int nt = 0; nt < 2; nt++) {
            int r = wm * 16 + g;
            int c = wn * 16 + nt * 8 + 2 * t;
            *(float2*)&Ps[r * 132 + c] = make_float2(pm[nt][0] + pc[nt][0], pm[nt][1] + pc[nt][1]);
            *(float2*)&Ps[(r + 8) * 132 + c] = make_float2(pm[nt][2] + pc[nt][2], pm[nt][3] + pc[nt][3]);
        }
        __syncthreads();

        // ---- softmax + bias + attns scale; write fp16 P into union rows ----
        const float* bb = bias_w + ((size_t)((b * NSd + s) * Hd + h) * LQd + q0) * NTd;
        #pragma unroll
        for (int rr = 0; rr < 2; rr++) {
            int r = wid * 2 + rr;
            float x0 = Ps[r * 132 + lane]       + bb[r * NTd + lane];
            float x1 = Ps[r * 132 + lane + 32]  + bb[r * NTd + lane + 32];
            float x2 = Ps[r * 132 + lane + 64]  + bb[r * NTd + lane + 64];
            float x3 = Ps[r * 132 + lane + 96]  + bb[r * NTd + lane + 96];
            float mx = fmaxf(fmaxf(x0, x1), fmaxf(x2, x3));
            #pragma unroll
            for (int o = 16; o; o >>= 1) mx = fmaxf(mx, __shfl_xor_sync(0xffffffffu, mx, o));
            x0 = __expf(x0 - mx); x1 = __expf(x1 - mx);
            x2 = __expf(x2 - mx); x3 = __expf(x3 - mx);
            float su = x0 + x1 + x2 + x3;
            #pragma unroll
            for (int o = 16; o; o >>= 1) su += __shfl_xor_sync(0xffffffffu, su, o);
            float wsc = attns[((size_t)(b * Hd + h) * LQd + q0 + r) * NSd + s] / su;
            __half h0 = __float2half_rn(x0 * wsc);
            __half h1 = __float2half_rn(x1 * wsc);
            __half h2 = __float2half_rn(x2 * wsc);
            __half h3 = __float2half_rn(x3 * wsc);
            __syncwarp();   // whole row read before overwrite (union aliasing)
            __half* prow = PU + r * PROW;
            prow[lane]       = h0;
            prow[lane + 32]  = h1;
            prow[lane + 64]  = h2;
            prow[lane + 96]  = h3;
        }
        __syncthreads();

        // ---- O += P @ V (warp tile 16x8, 2-term) ----
        #pragma unroll
        for (int ks = 0; ks < 8; ks++) {
            const uint32_t kb = (uint32_t)(ks * 16);
            uint32_t ph4[4], v4[4];
            uint32_t prb = (uint32_t)(wm * 16 * PROW) + kb;
            ldsm_x4(ph4, smem_base + 2 * (W_P + prb + ap_off));
            ldsm_x4_t(v4, smem_base + 2 * (v_arr + kb * HQS + v_off));
            mma_f16(om, ph4[0], ph4[1], ph4[2], ph4[3], v4[0], v4[1]);
            mma_f16(oc, ph4[0], ph4[1], ph4[2], ph4[3], v4[2], v4[3]);
        }

        // load next K/V stage
        if (s + 1 < NSd) {
            __syncthreads();
            const size_t kvb = (size_t)(b * NSd + s + 1) * NTd * Dd + h * DKd;
            const __half* srcs[4] = {kwh, kwl, vwh, vwl};
            #pragma unroll
            for (int i = 0; i < 8; i++) {
                int id = tid + 512 * i;
                int arr = id >> 10, rem = id & 1023;
                int row = rem >> 3, ch = rem & 7;
                const __half* src = srcs[arr] + kvb + (size_t)row * Dd + ch * 8;
                uint32_t dst = (uint32_t)__cvta_generic_to_shared(
                    &hsm[W_KV + arr * W_ARR + row * HQS + ch * 8]);
                cp_async16(dst, src, 16);
            }
            cp_commit();
            cp_wait<0>();
            __syncthreads();
        }
    }

    {
        int r = q0 + wm * 16 + g;
        int c = h * DKd + wn * 8 + 2 * t;
        float v0 = om[0] + oc[0], v1 = om[1] + oc[1];
        float v2 = om[2] + oc[2], v3 = om[3] + oc[3];
        *(__half2*)&cwh[(size_t)(b * LQd + r) * Dd + c] =
            __halves2half2(__float2half_rn(v0), __float2half_rn(v1));
        *(__half2*)&cwh[(size_t)(b * LQd + r + 8) * Dd + c] =
            __halves2half2(__float2half_rn(v2), __float2half_rn(v3));
    }
}

// ---------------- host ----------------
extern "C" void kernel_launch(void* const* d_in, const int* in_sizes, int n_in,
                              void* d_out, int out_size)
{
    const float* q      = (const float*)d_in[0];
    const float* k_s    = (const float*)d_in[1];
    const float* v_s    = (const float*)d_in[2];
    const float* k_w    = (const float*)d_in[3];
    const float* v_w    = (const float*)d_in[4];
    const float* bias_w = (const float*)d_in[5];
    const float* bias_s = (const float*)d_in[6];
    const float* gab    = (const float*)d_in[7];

    const float *wq_s, *bq_s, *wk_s, *bk_s, *wv_s, *bv_s;
    const float *wq_w, *bq_w, *wk_w, *bk_w, *wv_w, *bv_w;
    const float *fcs_w, *fcs_b, *fcw_w, *fcw_b, *fco_w, *fco_b;

    if (in_sizes[9] == 512) {
        wq_s = (const float*)d_in[8];  bq_s = (const float*)d_in[9];
        wk_s = (const float*)d_in[10]; bk_s = (const float*)d_in[11];
        wv_s = (const float*)d_in[12]; bv_s = (const float*)d_in[13];
        wq_w = (const float*)d_in[14]; bq_w = (const float*)d_in[15];
        wk_w = (const float*)d_in[16]; bk_w = (const float*)d_in[17];
        wv_w = (const float*)d_in[18]; bv_w = (const float*)d_in[19];
        fcs_w = (const float*)d_in[20]; fcs_b = (const float*)d_in[21];
        fcw_w = (const float*)d_in[22]; fcw_b = (const float*)d_in[23];
        fco_w = (const float*)d_in[24]; fco_b = (const float*)d_in[25];
    } else {
        wq_s = (const float*)d_in[8];  wk_s = (const float*)d_in[9];
        wv_s = (const float*)d_in[10]; wq_w = (const float*)d_in[11];
        wk_w = (const float*)d_in[12]; wv_w = (const float*)d_in[13];
        fcs_w = (const float*)d_in[14]; fcw_w = (const float*)d_in[15];
        bq_s = (const float*)d_in[16]; bk_s = (const float*)d_in[17];
        bv_s = (const float*)d_in[18]; bq_w = (const float*)d_in[19];
        bk_w = (const float*)d_in[20]; bv_w = (const float*)d_in[21];
        fcs_b = (const float*)d_in[22]; fcw_b = (const float*)d_in[23];
        fco_w = (const float*)d_in[24]; fco_b = (const float*)d_in[25];
    }

    float* scratch = nullptr;
    cudaGetSymbolAddress((void**)&scratch, g_scratch);
    float* s_qs  = scratch + OFF_QS;
    float* s_ks  = scratch + OFF_KS;
    float* s_vs  = scratch + OFF_VS;
    float* s_att = scratch + OFF_ATT;
    __half* hb = (__half*)(scratch + OFF_HALF);
    __half* acth = hb + H_ACTH;
    __half* wth  = hb + H_WTH;
    __half* wtl  = hb + H_WTL;
    __half* qwh  = hb + H_QWH;
    __half* qwl  = hb + H_QWL;
    __half* kwh  = hb + H_KWH;
    __half* kwl  = hb + H_KWL;
    __half* vwh  = hb + H_VWH;
    __half* vwl  = hb + H_VWL;
    __half* csh  = hb + H_CSH;
    __half* cwh  = hb + H_CWH;
    __half* cath = hb + H_CATH;
    __half* catl = hb + H_CATL;

    cudaFuncSetAttribute(gemm_cfg, cudaFuncAttributeMaxDynamicSharedMemorySize, HSMEM_BYTES);
    cudaFuncSetAttribute(word_attn_h5, cudaFuncAttributeMaxDynamicSharedMemorySize, WSMEM_BYTES);

    // prep
    ASplitArgs aa;
    aa.src[0] = q; aa.src[1] = k_s; aa.src[2] = v_s; aa.src[3] = k_w; aa.src[4] = v_w;
    act_split<<<dim3(256, 5), 256>>>(aa, acth);
    WSplitArgs wa;
    wa.src[0] = wq_s; wa.src[1] = wk_s; wa.src[2] = wv_s;
    wa.src[3] = wq_w; wa.src[4] = wk_w; wa.src[5] = wv_w;
    wa.src[6] = fcs_w; wa.src[7] = fcw_w; wa.src[8] = fco_w;
    w_transplit<<<dim3(16, 32, 9), dim3(32, 8)>>>(wa, wth, wtl);

    // all projections in ONE launch: z0 kw, z1 vw (big, split out), z2 qs(f32),
    // z3 qw(fp16 out, 0.125 folded), z4 ks(f32), z5 vs(f32)
    {
        GemmCfg c = {};
        c.K = 512; c.ldc = 512;
        c.Ah[0] = acth + AKW; c.Bh[0] = wth + WOFF(4); c.Bl[0] = wtl + WOFF(4);
        c.Ah[1] = acth + AVW; c.Bh[1] = wth + WOFF(5); c.Bl[1] = wtl + WOFF(5);
        c.Ah[2] = acth + AQ;  c.Bh[2] = wth + WOFF(0); c.Bl[2] = wtl + WOFF(0);
        c.Ah[3] = acth + AQ;  c.Bh[3] = wth + WOFF(3); c.Bl[3] = wtl + WOFF(3);
        c.Ah[4] = acth + AKS; c.Bh[4] = wth + WOFF(1); c.Bl[4] = wtl + WOFF(1);
        c.Ah[5] = acth + AVS; c.Bh[5] = wth + WOFF(2); c.Bl[5] = wtl + WOFF(2);
        c.bias[0] = bk_w; c.bias[1] = bv_w; c.bias[2] = bq_s;
        c.bias[3] = bq_w; c.bias[4] = bk_s; c.bias[5] = bv_s;
        c.bscale[0] = 1.f; c.bscale[1] = 1.f; c.bscale[2] = 1.f;
        c.bscale[3] = 0.125f; c.bscale[4] = 1.f; c.bscale[5] = 1.f;
        c.M[0] = 12288; c.M[1] = 12288; c.M[2] = 1024;
        c.M[3] = 1024;  c.M[4] = 96;    c.M[5] = 96;
        c.mode[0] = 1; c.mode[1] = 1; c.mode[2] = 0;
        c.mode[3] = 1; c.mode[4] = 0; c.mode[5] = 0;
        c.Ch[0] = kwh; c.Cl[0] = kwl;
        c.Ch[1] = vwh; c.Cl[1] = vwl;
        c.Cf[2] = s_qs;
        c.Ch[3] = qwh; c.Cl[3] = qwl;   // qwl written but unused
        c.Cf[4] = s_ks;
        c.Cf[5] = s_vs;
        gemm_cfg<<<dim3(8, 96, 6), 256, HSMEM_BYTES>>>(c);
    }

    sent_attn<<<dim3(Hd, BB), 256>>>(s_qs, s_ks, s_vs, bias_s, gab, s_att, csh);

    word_attn_h5<<<dim3(8, Hd, BB), 512, WSMEM_BYTES>>>(
        qwh, kwh, kwl, vwh, vwl, bias_w, s_att, cwh);

    // fcs / fcw -> fp16 cat (A-side only, so hi is enough; mode 1 writes hi+lo, keep catl)
    {
        GemmCfg c = {};
        c.K = 512; c.ldc = 1024;
        c.Ah[0] = csh; c.Bh[0] = wth + WOFF(6); c.Bl[0] = wtl + WOFF(6);
        c.Ah[1] = cwh; c.Bh[1] = wth + WOFF(7); c.Bl[1] = wtl + WOFF(7);
        c.bias[0] = fcs_b; c.bias[1] = fcw_b;
        c.bscale[0] = 1.f; c.bscale[1] = 1.f;
        c.M[0] = 1024; c.M[1] = 1024;
        c.mode[0] = 1; c.mode[1] = 1;
        c.Ch[0] = cath;       c.Cl[0] = catl;
        c.Ch[1] = cath + 512; c.Cl[1] = catl + 512;
        gemm_cfg<<<dim3(8, 8, 2), 256, HSMEM_BYTES>>>(c);
    }
    // final fco -> fp32 out
    {
        GemmCfg c = {};
        c.K = 1024; c.ldc = 512;
        c.Ah[0] = cath; c.Bh[0] = wth + WOFF(8); c.Bl[0] = wtl + WOFF(8);
        c.bias[0] = fco_b;
        c.bscale[0] = 1.f;
        c.M[0] = 1024;
        c.mode[0] = 0;
        c.Cf[0] = (float*)d_out;
        gemm_cfg<<<dim3(8, 8, 1), 256, HSMEM_BYTES>>>(c);
    }
}

// round 13
// speedup vs baseline: 2.6341x; 1.0752x over previous
#include <cuda_runtime.h>
#include <cuda_fp16.h>
#include <math.h>
#include <stdint.h>

// Problem constants
#define BB   4
#define LQd  256
#define NSd  24
#define NTd  128
#define Dd   512
#define Hd   8
#define DKd  64

// ---------------- scratch layout ----------------
#define OFF_QS   0
#define OFF_KS   524288
#define OFF_VS   573440
#define OFF_ATT  622592
#define OFF_HALF 819200
#define H_ACTH 0
#define H_ACTL 13205504
#define H_WTH  26411008
#define H_WTL  29032448
#define H_QWH  31653888
#define H_QWL  32178176
#define H_KWH  32702464
#define H_KWL  38993920
#define H_VWH  45285376
#define H_VWL  51576832
#define H_CSH  57868288
#define H_CSL  58392576
#define H_CWH  58916864
#define H_CWL  59441152
#define H_CATH 59965440
#define H_CATL 61014016
#define H_TOTAL 62062592
#define SCRATCH_TOTAL (OFF_HALF + H_TOTAL / 2)
__device__ float g_scratch[SCRATCH_TOTAL];

#define AQ   0
#define AKS  524288
#define AVS  573440
#define AKW  622592
#define AVW  6914048
#define WOFF(i) ((i) * 262144)

// ---------------- helpers ----------------
__device__ __forceinline__ void split_h(float x, __half& hi, __half& lo) {
    hi = __float2half_rn(x);
    lo = __float2half_rn(x - __half2float(hi));
}
__device__ __forceinline__ void mma_f16(float d[4],
                                        uint32_t a0, uint32_t a1, uint32_t a2, uint32_t a3,
                                        uint32_t b0, uint32_t b1) {
    asm volatile(
        "mma.sync.aligned.m16n8k16.row.col.f32.f16.f16.f32 "
        "{%0,%1,%2,%3},{%4,%5,%6,%7},{%8,%9},{%0,%1,%2,%3};"
        : "+f"(d[0]), "+f"(d[1]), "+f"(d[2]), "+f"(d[3])
        : "r"(a0), "r"(a1), "r"(a2), "r"(a3), "r"(b0), "r"(b1));
}
__device__ __forceinline__ void ldsm_x4(uint32_t r[4], uint32_t addr) {
    asm volatile("ldmatrix.sync.aligned.m8n8.x4.shared.b16 {%0,%1,%2,%3}, [%4];"
                 : "=r"(r[0]), "=r"(r[1]), "=r"(r[2]), "=r"(r[3]) : "r"(addr));
}
__device__ __forceinline__ void ldsm_x4_t(uint32_t r[4], uint32_t addr) {
    asm volatile("ldmatrix.sync.aligned.m8n8.x4.trans.shared.b16 {%0,%1,%2,%3}, [%4];"
                 : "=r"(r[0]), "=r"(r[1]), "=r"(r[2]), "=r"(r[3]) : "r"(addr));
}
__device__ __forceinline__ void cp_async16(uint32_t smem_addr, const void* gptr, int src_bytes) {
    asm volatile("cp.async.cg.shared.global [%0], [%1], 16, %2;"
                 :: "r"(smem_addr), "l"(gptr), "r"(src_bytes) : "memory");
}
__device__ __forceinline__ void cp_commit() { asm volatile("cp.async.commit_group;" ::: "memory"); }
template <int N>
__device__ __forceinline__ void cp_wait() { asm volatile("cp.async.wait_group %0;" :: "n"(N) : "memory"); }

// ---------------- prep: convert activations to fp16 (hi only) ----------------
struct ASplitArgs { const float* src[5]; };
__constant__ int c_alen[5] = {524288, 49152, 49152, 6291456, 6291456};
__constant__ int c_aoff[5] = {AQ, AKS, AVS, AKW, AVW};

__global__ __launch_bounds__(256) void act_split(ASplitArgs args, __half* acth)
{
    int z = blockIdx.y;
    int n = c_alen[z];
    const float* s = args.src[z];
    __half* dh = acth + c_aoff[z];
    for (int i = blockIdx.x * 256 + threadIdx.x; i < n; i += gridDim.x * 256) {
        dh[i] = __float2half_rn(s[i]);
    }
}

// ---------------- prep: transpose+split weights ----------------
struct WSplitArgs { const float* src[9]; };
__constant__ int c_wK[9] = {512, 512, 512, 512, 512, 512, 512, 512, 1024};
__constant__ int c_woff[9] = {WOFF(0), WOFF(1), WOFF(2), WOFF(3), WOFF(4),
                              WOFF(5), WOFF(6), WOFF(7), WOFF(8)};
__constant__ float c_wscale[9] = {1.f, 1.f, 1.f, 0.125f, 1.f, 1.f, 1.f, 1.f, 1.f};

__global__ void w_transplit(WSplitArgs args, __half* wth, __half* wtl)
{
    int z = blockIdx.z;
    int Kw = c_wK[z];
    int k0 = blockIdx.y * 32;
    if (k0 >= Kw) return;
    int n0 = blockIdx.x * 32;
    const float* W = args.src[z];
    float sc = c_wscale[z];
    __half* th = wth + c_woff[z];
    __half* tl = wtl + c_woff[z];

    __shared__ float ts[32][33];
    int tx = threadIdx.x, ty = threadIdx.y;
    #pragma unroll
    for (int r = 0; r < 4; r++)
        ts[ty + 8 * r][tx] = W[(size_t)(k0 + ty + 8 * r) * 512 + n0 + tx];
    __syncthreads();
    #pragma unroll
    for (int r = 0; r < 4; r++) {
        int n = n0 + ty + 8 * r;
        int k = k0 + tx;
        __half hi, lo;
        split_h(sc * ts[tx][ty + 8 * r], hi, lo);
        th[(size_t)n * Kw + k] = hi;
        tl[(size_t)n * Kw + k] = lo;
    }
}

// ---------------- 2-term GEMM: A fp16, B split hi/lo, 3-stage pipeline ----------------
#define HAS 40
#define G_A 128
#define G_B 64
#define HSTAGE ((G_A + 2 * G_B) * HAS)
#define HSMEM_BYTES (3 * HSTAGE * 2)

struct GemmCfg {
    const __half* Ah[6];
    const __half* Bh[6]; const __half* Bl[6];
    const float* bias[6];
    float* Cf[6];
    __half* Ch[6]; __half* Cl[6];
    int M[6]; int mode[6]; float bscale[6];
    int K; int ldc;
};

__global__ __launch_bounds__(256, 2) void gemm_cfg(GemmCfg cfg)
{
    extern __shared__ __half hsm[];

    const int z = blockIdx.z;
    const int M = cfg.M[z];
    const int row0 = blockIdx.y * 128;
    if (row0 >= M) return;

    const __half* Ah_g = cfg.Ah[z];
    const __half* Bh_g = cfg.Bh[z];
    const __half* Bl_g = cfg.Bl[z];
    const float* bias  = cfg.bias[z];
    const int mode     = cfg.mode[z];
    const float bsc    = cfg.bscale[z];
    const int K        = cfg.K;
    const int ldc      = cfg.ldc;

    const int tid = threadIdx.x;
    const int wid = tid >> 5;
    const int lane = tid & 31;
    const int g = lane >> 2;
    const int t = lane & 3;
    const int wm = wid & 3;
    const int wn = wid >> 2;
    const int col0 = blockIdx.x * 64;

    const int q8 = lane & 7;
    const int seg = lane >> 3;
    const uint32_t smem_base = (uint32_t)__cvta_generic_to_shared(hsm);
    const uint32_t a_off = (uint32_t)((q8 + (seg & 1) * 8) * HAS + (seg >> 1) * 8);
    const uint32_t b_off = (uint32_t)((q8 + (seg >> 1) * 8) * HAS + (seg & 1) * 8);

    float dm[2][4][4], dc[2][4][4];
    #pragma unroll
    for (int mt = 0; mt < 2; mt++)
        #pragma unroll
        for (int nt = 0; nt < 4; nt++)
            #pragma unroll
            for (int j = 0; j < 4; j++) { dm[mt][nt][j] = 0.f; dc[mt][nt][j] = 0.f; }

    const int ktiles = K >> 5;

    #pragma unroll
    for (int p = 0; p < 2; p++) {
        __half* Ahs = hsm + p * HSTAGE;
        __half* Bhs = Ahs + G_A * HAS;
        __half* Bls = Bhs + G_B * HAS;
        int k0 = p << 5;
        #pragma unroll
        for (int i = 0; i < 2; i++) {
            int id = tid + 256 * i;
            int row = id >> 2, ch = id & 3;
            int r = row0 + row;
            int rc = r < M ? r : (M - 1);
            int pb = r < M ? 16 : 0;
            cp_async16((uint32_t)__cvta_generic_to_shared(&Ahs[row * HAS + ch * 8]),
                       &Ah_g[(size_t)rc * K + k0 + ch * 8], pb);
        }
        #pragma unroll
        for (int i = 0; i < 2; i++) {
            int id = tid + 256 * i;
            int arr = id >> 8, rem = id & 255;
            int row = rem >> 2, ch = rem & 3;
            const __half* src = (arr ? Bl_g : Bh_g) + (size_t)(col0 + row) * K + k0 + ch * 8;
            __half* dst = (arr ? Bls : Bhs) + row * HAS + ch * 8;
            cp_async16((uint32_t)__cvta_generic_to_shared(dst), src, 16);
        }
        cp_commit();
    }
    cp_wait<1>();
    __syncthreads();

    int cst = 0;

    for (int kt = 0; kt < ktiles; kt++) {
        const uint32_t stage = smem_base + (uint32_t)((cst * HSTAGE) * 2);

        #pragma unroll
        for (int ks = 0; ks < 2; ks++) {
            const uint32_t kb = (uint32_t)(ks * 16);
            uint32_t ah[2][4];
            #pragma unroll
            for (int mt = 0; mt < 2; mt++) {
                uint32_t rbase = (uint32_t)((wm * 32 + mt * 16) * HAS) + kb;
                ldsm_x4(ah[mt], stage + 2 * (rbase + a_off));
            }
            uint32_t bh[4][2], bl[4][2];
            #pragma unroll
            for (int p = 0; p < 2; p++) {
                uint32_t nbase = (uint32_t)((wn * 32 + p * 16) * HAS) + kb;
                uint32_t r4[4];
                ldsm_x4(r4, stage + 2 * (G_A * HAS + nbase + b_off));
                bh[2 * p][0] = r4[0]; bh[2 * p][1] = r4[1];
                bh[2 * p + 1][0] = r4[2]; bh[2 * p + 1][1] = r4[3];
                ldsm_x4(r4, stage + 2 * (G_A * HAS + G_B * HAS + nbase + b_off));
                bl[2 * p][0] = r4[0]; bl[2 * p][1] = r4[1];
                bl[2 * p + 1][0] = r4[2]; bl[2 * p + 1][1] = r4[3];
            }
            #pragma unroll
            for (int nt = 0; nt < 4; nt++) {
                #pragma unroll
                for (int mt = 0; mt < 2; mt++) {
                    mma_f16(dm[mt][nt], ah[mt][0], ah[mt][1], ah[mt][2], ah[mt][3], bh[nt][0], bh[nt][1]);
                    mma_f16(dc[mt][nt], ah[mt][0], ah[mt][1], ah[mt][2], ah[mt][3], bl[nt][0], bl[nt][1]);
                }
            }
        }

        int nk = kt + 2;
        if (nk < ktiles) {
            int st = nk % 3;
            __half* Ahs = hsm + st * HSTAGE;
            __half* Bhs = Ahs + G_A * HAS;
            __half* Bls = Bhs + G_B * HAS;
            int k0 = nk << 5;
            #pragma unroll
            for (int i = 0; i < 2; i++) {
                int id = tid + 256 * i;
                int row = id >> 2, ch = id & 3;
                int r = row0 + row;
                int rc = r < M ? r : (M - 1);
                int pb = r < M ? 16 : 0;
                cp_async16((uint32_t)__cvta_generic_to_shared(&Ahs[row * HAS + ch * 8]),
                           &Ah_g[(size_t)rc * K + k0 + ch * 8], pb);
            }
            #pragma unroll
            for (int i = 0; i < 2; i++) {
                int id = tid + 256 * i;
                int arr = id >> 8, rem = id & 255;
                int row = rem >> 2, ch = rem & 3;
                const __half* src = (arr ? Bl_g : Bh_g) + (size_t)(col0 + row) * K + k0 + ch * 8;
                __half* dst = (arr ? Bls : Bhs) + row * HAS + ch * 8;
                cp_async16((uint32_t)__cvta_generic_to_shared(dst), src, 16);
            }
        }
        cp_commit();
        cp_wait<1>();
        __syncthreads();

        cst = (cst == 2) ? 0 : cst + 1;
    }

    #pragma unroll
    for (int mt = 0; mt < 2; mt++) {
        #pragma unroll
        for (int nt = 0; nt < 4; nt++) {
            int r = row0 + wm * 32 + mt * 16 + g;
            int c = col0 + wn * 32 + nt * 8 + 2 * t;
            float2 bz = *(const float2*)&bias[c];
            float o0 = dm[mt][nt][0] + dc[mt][nt][0] + bsc * bz.x;
            float o1 = dm[mt][nt][1] + dc[mt][nt][1] + bsc * bz.y;
            float o2 = dm[mt][nt][2] + dc[mt][nt][2] + bsc * bz.x;
            float o3 = dm[mt][nt][3] + dc[mt][nt][3] + bsc * bz.y;
            if (mode == 0) {
                float* Cf = cfg.Cf[z];
                if (r < M)     *(float2*)&Cf[(size_t)r * ldc + c] = make_float2(o0, o1);
                if (r + 8 < M) *(float2*)&Cf[(size_t)(r + 8) * ldc + c] = make_float2(o2, o3);
            } else {
                __half* Ch = cfg.Ch[z];
                __half* Cl = cfg.Cl[z];
                __half h0, l0, h1, l1;
                if (r < M) {
                    split_h(o0, h0, l0); split_h(o1, h1, l1);
                    *(__half2*)&Ch[(size_t)r * ldc + c] = __halves2half2(h0, h1);
                    *(__half2*)&Cl[(size_t)r * ldc + c] = __halves2half2(l0, l1);
                }
                if (r + 8 < M) {
                    split_h(o2, h0, l0); split_h(o3, h1, l1);
                    *(__half2*)&Ch[(size_t)(r + 8) * ldc + c] = __halves2half2(h0, h1);
                    *(__half2*)&Cl[(size_t)(r + 8) * ldc + c] = __halves2half2(l0, l1);
                }
            }
        }
    }
}

// ---------------- sentence-level graph attention v2: 4 threads/row ----------------
// grid (H, B, 4): 64 query rows per block; row = tid>>2, sub = tid&3 owns 16 k-dims.
__global__ __launch_bounds__(256) void sent_attn4(
    const float* __restrict__ qs, const float* __restrict__ ksn,
    const float* __restrict__ vsn, const float* __restrict__ bias_s,
    const float* __restrict__ gab,
    float* __restrict__ attns_out,
    __half* __restrict__ csh)
{
    const int h = blockIdx.x, b = blockIdx.y;
    const int q0 = blockIdx.z * 64;
    const int tid = threadIdx.x;
    const int row = tid >> 2;
    const int sub = tid & 3;
    const int q = q0 + row;

    __shared__ float Ks[NSd][DKd + 1];
    __shared__ float Vs[NSd][DKd + 1];
    __shared__ float G[NSd][NSd + 1];
    __shared__ float Att[64][NSd + 1];

    for (int idx = tid; idx < NSd * DKd; idx += 256) {
        int s = idx >> 6, k = idx & 63;
        Ks[s][k] = ksn[(size_t)(b * NSd + s) * Dd + h * DKd + k];
        Vs[s][k] = vsn[(size_t)(b * NSd + s) * Dd + h * DKd + k];
    }
    for (int idx = tid; idx < NSd * NSd; idx += 256) {
        int s = idx / NSd, tt = idx % NSd;
        G[s][tt] = gab[((size_t)(b * Hd + h) * NSd + s) * NSd + tt];
    }
    __syncthreads();

    // partial QK over this thread's 16 dims
    float qreg[16];
    const float* qrow = qs + (size_t)(b * LQd + q) * Dd + h * DKd + sub * 16;
    #pragma unroll
    for (int k = 0; k < 16; k++) qreg[k] = qrow[k] * 0.125f;

    float a[NSd];
    #pragma unroll
    for (int s = 0; s < NSd; s++) {
        float dd = 0.f;
        #pragma unroll
        for (int k = 0; k < 16; k++) dd += qreg[k] * Ks[s][sub * 16 + k];
        a[s] = dd;
    }
    // group-of-4 reduction (lanes 4r..4r+3)
    #pragma unroll
    for (int s = 0; s < NSd; s++) {
        a[s] += __shfl_xor_sync(0xffffffffu, a[s], 1);
        a[s] += __shfl_xor_sync(0xffffffffu, a[s], 2);
    }
    const float* bsrow = bias_s + ((size_t)(b * Hd + h) * LQd + q) * NSd;
    #pragma unroll
    for (int s = 0; s < NSd; s++) a[s] += bsrow[s];

    // softmax #1 (redundant across the 4 threads — cheap)
    float m = -1e30f;
    #pragma unroll
    for (int s = 0; s < NSd; s++) m = fmaxf(m, a[s]);
    float smx[NSd]; float sum = 0.f;
    #pragma unroll
    for (int s = 0; s < NSd; s++) { smx[s] = __expf(a[s] - m); sum += smx[s]; }
    float inv = 1.f / sum;

    // graph prior: this thread owns t in [sub*6, sub*6+6)
    const int t0 = sub * 6;
    float an[6];
    #pragma unroll
    for (int j = 0; j < 6; j++) {
        float dd = 0.f;
        #pragma unroll
        for (int s = 0; s < NSd; s++) dd += smx[s] * G[s][t0 + j];
        float gg = dd * inv;
        an[j] = a[t0 + j] - 0.5f * gg * gg;
    }

    // softmax #2: group reduction over all 24 (6 local)
    float m2 = -1e30f;
    #pragma unroll
    for (int j = 0; j < 6; j++) m2 = fmaxf(m2, an[j]);
    m2 = fmaxf(m2, __shfl_xor_sync(0xffffffffu, m2, 1));
    m2 = fmaxf(m2, __shfl_xor_sync(0xffffffffu, m2, 2));
    float e[6]; float su = 0.f;
    #pragma unroll
    for (int j = 0; j < 6; j++) { e[j] = __expf(an[j] - m2); su += e[j]; }
    su += __shfl_xor_sync(0xffffffffu, su, 1);
    su += __shfl_xor_sync(0xffffffffu, su, 2);
    float inv2 = 1.f / su;

    float* arow = attns_out + ((size_t)(b * Hd + h) * LQd + q) * NSd;
    #pragma unroll
    for (int j = 0; j < 6; j++) {
        float v = e[j] * inv2;
        Att[row][t0 + j] = v;
        arow[t0 + j] = v;
    }
    __syncwarp();

    float att[NSd];
    #pragma unroll
    for (int s = 0; s < NSd; s++) att[s] = Att[row][s];

    // ctx over this thread's 16 dims
    size_t cbase = (size_t)(b * LQd + q) * Dd + h * DKd + sub * 16;
    #pragma unroll
    for (int dd = 0; dd < 16; dd++) {
        float acc = 0.f;
        #pragma unroll
        for (int s = 0; s < NSd; s++) acc += att[s] * Vs[s][sub * 16 + dd];
        csh[cbase + dd] = __float2half_rn(acc);
    }
}

// ---------------- word-level attention v5: 2-term split ----------------
#define HQS 72
#define W_QH 0
#define W_KV (32 * HQS)
#define W_ARR (128 * HQS)
#define W_P  (W_KV + 4 * W_ARR)
#define PROW 264
#define WSMEM_BYTES ((W_P + 32 * PROW) * 2)

__global__ __launch_bounds__(512, 2) void word_attn_h5(
    const __half* __restrict__ qwh,
    const __half* __restrict__ kwh, const __half* __restrict__ kwl,
    const __half* __restrict__ vwh, const __half* __restrict__ vwl,
    const float* __restrict__ bias_w, const float* __restrict__ attns,
    __half* __restrict__ cwh)
{
    extern __shared__ __half hsm[];
    float* Ps = (float*)(hsm + W_P);
    __half* PU = hsm + W_P;

    const int tid = threadIdx.x;
    const int wid = tid >> 5;
    const int lane = tid & 31;
    const int g = lane >> 2;
    const int t = lane & 3;
    const int wm = wid & 1;
    const int wn = wid >> 1;
    const int q0 = blockIdx.x * 32;
    const int h  = blockIdx.y;
    const int b  = blockIdx.z;

    const int q8 = lane & 7;
    const int seg = lane >> 3;
    const uint32_t smem_base = (uint32_t)__cvta_generic_to_shared(hsm);
    const uint32_t aq_off = (uint32_t)((q8 + (seg & 1) * 8) * HQS + (seg >> 1) * 8);
    const uint32_t bk_off = (uint32_t)((q8 + (seg >> 1) * 8) * HQS + (seg & 1) * 8);
    const uint32_t ap_off = (uint32_t)((q8 + (seg & 1) * 8) * PROW + (seg >> 1) * 8);
    const uint32_t v_arr  = (seg >> 1) ? (uint32_t)(W_KV + 3 * W_ARR) : (uint32_t)(W_KV + 2 * W_ARR);
    const uint32_t v_off  = (uint32_t)((q8 + (seg & 1) * 8) * HQS + wn * 8);

    {
        if (tid < 256) {
            int row = tid >> 3, ch = tid & 7;
            const __half* src = qwh + (size_t)(b * LQd + q0 + row) * Dd + h * DKd + ch * 8;
            uint32_t dst = (uint32_t)__cvta_generic_to_shared(
                &hsm[W_QH + row * HQS + ch * 8]);
            cp_async16(dst, src, 16);
        }
        const size_t kvb = (size_t)(b * NSd) * NTd * Dd + h * DKd;
        const __half* srcs[4] = {kwh, kwl, vwh, vwl};
        #pragma unroll
        for (int i = 0; i < 8; i++) {
            int id = tid + 512 * i;
            int arr = id >> 10, rem = id & 1023;
            int row = rem >> 3, ch = rem & 7;
            const __half* src = srcs[arr] + kvb + (size_t)row * Dd + ch * 8;
            uint32_t dst = (uint32_t)__cvta_generic_to_shared(
                &hsm[W_KV + arr * W_ARR + row * HQS + ch * 8]);
            cp_async16(dst, src, 16);
        }
        cp_commit();
        cp_wait<0>();
    }
    __syncthreads();

    float om[4], oc[4];
    #pragma unroll
    for (int j = 0; j < 4; j++) { om[j] = 0.f; oc[j] = 0.f; }

    for (int s = 0; s < NSd; s++) {
        float pm[2][4], pc[2][4];
        #pragma unroll
        for (int nt = 0; nt < 2; nt++)
            #pragma unroll
            for (int j = 0; j < 4; j++) { pm[nt][j] = 0.f; pc[nt][j] = 0.f; }

        #pragma unroll
        for (int ks = 0; ks < 4; ks++) {
            const uint32_t kb = (uint32_t)(ks * 16);
            uint32_t ahq[4], kh4[4], kl4[4];
            uint32_t qrb = (uint32_t)(wm * 16 * HQS) + kb;
            ldsm_x4(ahq, smem_base + 2 * (W_QH + qrb + aq_off));
            uint32_t krb = (uint32_t)(wn * 16 * HQS) + kb;
            ldsm_x4(kh4, smem_base + 2 * (W_KV + krb + bk_off));
            ldsm_x4(kl4, smem_base + 2 * (W_KV + W_ARR + krb + bk_off));
            #pragma unroll
            for (int nt = 0; nt < 2; nt++) {
                mma_f16(pm[nt], ahq[0], ahq[1], ahq[2], ahq[3], kh4[2 * nt], kh4[2 * nt + 1]);
                mma_f16(pc[nt], ahq[0], ahq[1], ahq[2], ahq[3], kl4[2 * nt], kl4[2 * nt + 1]);
            }
        }
        #pragma unroll
        for (int nt = 0; nt < 2; nt++) {
            int r = wm * 16 + g;
            int c = wn * 16 + nt * 8 + 2 * t;
            *(float2*)&Ps[r * 132 + c] = make_float2(pm[nt][0] + pc[nt][0], pm[nt][1] + pc[nt][1]);
            *(float2*)&Ps[(r + 8) * 132 + c] = make_float2(pm[nt][2] + pc[nt][2], pm[nt][3] + pc[nt][3]);
        }
        __syncthreads();

        const float* bb = bias_w + ((size_t)((b * NSd + s) * Hd + h) * LQd + q0) * NTd;
        #pragma unroll
        for (int rr = 0; rr < 2; rr++) {
            int r = wid * 2 + rr;
            float x0 = Ps[r * 132 + lane]       + bb[r * NTd + lane];
            float x1 = Ps[r * 132 + lane + 32]  + bb[r * NTd + lane + 32];
            float x2 = Ps[r * 132 + lane + 64]  + bb[r * NTd + lane + 64];
            float x3 = Ps[r * 132 + lane + 96]  + bb[r * NTd + lane + 96];
            float mx = fmaxf(fmaxf(x0, x1), fmaxf(x2, x3));
            #pragma unroll
            for (int o = 16; o; o >>= 1) mx = fmaxf(mx, __shfl_xor_sync(0xffffffffu, mx, o));
            x0 = __expf(x0 - mx); x1 = __expf(x1 - mx);
            x2 = __expf(x2 - mx); x3 = __expf(x3 - mx);
            float su = x0 + x1 + x2 + x3;
            #pragma unroll
            for (int o = 16; o; o >>= 1) su += __shfl_xor_sync(0xffffffffu, su, o);
            float wsc = attns[((size_t)(b * Hd + h) * LQd + q0 + r) * NSd + s] / su;
            __half h0 = __float2half_rn(x0 * wsc);
            __half h1 = __float2half_rn(x1 * wsc);
            __half h2 = __float2half_rn(x2 * wsc);
            __half h3 = __float2half_rn(x3 * wsc);
            __syncwarp();
            __half* prow = PU + r * PROW;
            prow[lane]       = h0;
            prow[lane + 32]  = h1;
            prow[lane + 64]  = h2;
            prow[lane + 96]  = h3;
        }
        __syncthreads();

        #pragma unroll
        for (int ks = 0; ks < 8; ks++) {
            const uint32_t kb = (uint32_t)(ks * 16);
            uint32_t ph4[4], v4[4];
            uint32_t prb = (uint32_t)(wm * 16 * PROW) + kb;
            ldsm_x4(ph4, smem_base + 2 * (W_P + prb + ap_off));
            ldsm_x4_t(v4, smem_base + 2 * (v_arr + kb * HQS + v_off));
            mma_f16(om, ph4[0], ph4[1], ph4[2], ph4[3], v4[0], v4[1]);
            mma_f16(oc, ph4[0], ph4[1], ph4[2], ph4[3], v4[2], v4[3]);
        }

        if (s + 1 < NSd) {
            __syncthreads();
            const size_t kvb = (size_t)(b * NSd + s + 1) * NTd * Dd + h * DKd;
            const __half* srcs[4] = {kwh, kwl, vwh, vwl};
            #pragma unroll
            for (int i = 0; i < 8; i++) {
                int id = tid + 512 * i;
                int arr = id >> 10, rem = id & 1023;
                int row = rem >> 3, ch = rem & 7;
                const __half* src = srcs[arr] + kvb + (size_t)row * Dd + ch * 8;
                uint32_t dst = (uint32_t)__cvta_generic_to_shared(
                    &hsm[W_KV + arr * W_ARR + row * HQS + ch * 8]);
                cp_async16(dst, src, 16);
            }
            cp_commit();
            cp_wait<0>();
            __syncthreads();
        }
    }

    {
        int r = q0 + wm * 16 + g;
        int c = h * DKd + wn * 8 + 2 * t;
        float v0 = om[0] + oc[0], v1 = om[1] + oc[1];
        float v2 = om[2] + oc[2], v3 = om[3] + oc[3];
        *(__half2*)&cwh[(size_t)(b * LQd + r) * Dd + c] =
            __halves2half2(__float2half_rn(v0), __float2half_rn(v1));
        *(__half2*)&cwh[(size_t)(b * LQd + r + 8) * Dd + c] =
            __halves2half2(__float2half_rn(v2), __float2half_rn(v3));
    }
}

// ---------------- host ----------------
extern "C" void kernel_launch(void* const* d_in, const int* in_sizes, int n_in,
                              void* d_out, int out_size)
{
    const float* q      = (const float*)d_in[0];
    const float* k_s    = (const float*)d_in[1];
    const float* v_s    = (const float*)d_in[2];
    const float* k_w    = (const float*)d_in[3];
    const float* v_w    = (const float*)d_in[4];
    const float* bias_w = (const float*)d_in[5];
    const float* bias_s = (const float*)d_in[6];
    const float* gab    = (const float*)d_in[7];

    const float *wq_s, *bq_s, *wk_s, *bk_s, *wv_s, *bv_s;
    const float *wq_w, *bq_w, *wk_w, *bk_w, *wv_w, *bv_w;
    const float *fcs_w, *fcs_b, *fcw_w, *fcw_b, *fco_w, *fco_b;

    if (in_sizes[9] == 512) {
        wq_s = (const float*)d_in[8];  bq_s = (const float*)d_in[9];
        wk_s = (const float*)d_in[10]; bk_s = (const float*)d_in[11];
        wv_s = (const float*)d_in[12]; bv_s = (const float*)d_in[13];
        wq_w = (const float*)d_in[14]; bq_w = (const float*)d_in[15];
        wk_w = (const float*)d_in[16]; bk_w = (const float*)d_in[17];
        wv_w = (const float*)d_in[18]; bv_w = (const float*)d_in[19];
        fcs_w = (const float*)d_in[20]; fcs_b = (const float*)d_in[21];
        fcw_w = (const float*)d_in[22]; fcw_b = (const float*)d_in[23];
        fco_w = (const float*)d_in[24]; fco_b = (const float*)d_in[25];
    } else {
        wq_s = (const float*)d_in[8];  wk_s = (const float*)d_in[9];
        wv_s = (const float*)d_in[10]; wq_w = (const float*)d_in[11];
        wk_w = (const float*)d_in[12]; wv_w = (const float*)d_in[13];
        fcs_w = (const float*)d_in[14]; fcw_w = (const float*)d_in[15];
        bq_s = (const float*)d_in[16]; bk_s = (const float*)d_in[17];
        bv_s = (const float*)d_in[18]; bq_w = (const float*)d_in[19];
        bk_w = (const float*)d_in[20]; bv_w = (const float*)d_in[21];
        fcs_b = (const float*)d_in[22]; fcw_b = (const float*)d_in[23];
        fco_w = (const float*)d_in[24]; fco_b = (const float*)d_in[25];
    }

    float* scratch = nullptr;
    cudaGetSymbolAddress((void**)&scratch, g_scratch);
    float* s_qs  = scratch + OFF_QS;
    float* s_ks  = scratch + OFF_KS;
    float* s_vs  = scratch + OFF_VS;
    float* s_att = scratch + OFF_ATT;
    __half* hb = (__half*)(scratch + OFF_HALF);
    __half* acth = hb + H_ACTH;
    __half* wth  = hb + H_WTH;
    __half* wtl  = hb + H_WTL;
    __half* qwh  = hb + H_QWH;
    __half* qwl  = hb + H_QWL;
    __half* kwh  = hb + H_KWH;
    __half* kwl  = hb + H_KWL;
    __half* vwh  = hb + H_VWH;
    __half* vwl  = hb + H_VWL;
    __half* csh  = hb + H_CSH;
    __half* cwh  = hb + H_CWH;
    __half* cath = hb + H_CATH;
    __half* catl = hb + H_CATL;

    cudaFuncSetAttribute(gemm_cfg, cudaFuncAttributeMaxDynamicSharedMemorySize, HSMEM_BYTES);
    cudaFuncSetAttribute(word_attn_h5, cudaFuncAttributeMaxDynamicSharedMemorySize, WSMEM_BYTES);

    // prep
    ASplitArgs aa;
    aa.src[0] = q; aa.src[1] = k_s; aa.src[2] = v_s; aa.src[3] = k_w; aa.src[4] = v_w;
    act_split<<<dim3(256, 5), 256>>>(aa, acth);
    WSplitArgs wa;
    wa.src[0] = wq_s; wa.src[1] = wk_s; wa.src[2] = wv_s;
    wa.src[3] = wq_w; wa.src[4] = wk_w; wa.src[5] = wv_w;
    wa.src[6] = fcs_w; wa.src[7] = fcw_w; wa.src[8] = fco_w;
    w_transplit<<<dim3(16, 32, 9), dim3(32, 8)>>>(wa, wth, wtl);

    // all projections in ONE launch
    {
        GemmCfg c = {};
        c.K = 512; c.ldc = 512;
        c.Ah[0] = acth + AKW; c.Bh[0] = wth + WOFF(4); c.Bl[0] = wtl + WOFF(4);
        c.Ah[1] = acth + AVW; c.Bh[1] = wth + WOFF(5); c.Bl[1] = wtl + WOFF(5);
        c.Ah[2] = acth + AQ;  c.Bh[2] = wth + WOFF(0); c.Bl[2] = wtl + WOFF(0);
        c.Ah[3] = acth + AQ;  c.Bh[3] = wth + WOFF(3); c.Bl[3] = wtl + WOFF(3);
        c.Ah[4] = acth + AKS; c.Bh[4] = wth + WOFF(1); c.Bl[4] = wtl + WOFF(1);
        c.Ah[5] = acth + AVS; c.Bh[5] = wth + WOFF(2); c.Bl[5] = wtl + WOFF(2);
        c.bias[0] = bk_w; c.bias[1] = bv_w; c.bias[2] = bq_s;
        c.bias[3] = bq_w; c.bias[4] = bk_s; c.bias[5] = bv_s;
        c.bscale[0] = 1.f; c.bscale[1] = 1.f; c.bscale[2] = 1.f;
        c.bscale[3] = 0.125f; c.bscale[4] = 1.f; c.bscale[5] = 1.f;
        c.M[0] = 12288; c.M[1] = 12288; c.M[2] = 1024;
        c.M[3] = 1024;  c.M[4] = 96;    c.M[5] = 96;
        c.mode[0] = 1; c.mode[1] = 1; c.mode[2] = 0;
        c.mode[3] = 1; c.mode[4] = 0; c.mode[5] = 0;
        c.Ch[0] = kwh; c.Cl[0] = kwl;
        c.Ch[1] = vwh; c.Cl[1] = vwl;
        c.Cf[2] = s_qs;
        c.Ch[3] = qwh; c.Cl[3] = qwl;
        c.Cf[4] = s_ks;
        c.Cf[5] = s_vs;
        gemm_cfg<<<dim3(8, 96, 6), 256, HSMEM_BYTES>>>(c);
    }

    sent_attn4<<<dim3(Hd, BB, 4), 256>>>(s_qs, s_ks, s_vs, bias_s, gab, s_att, csh);

    word_attn_h5<<<dim3(8, Hd, BB), 512, WSMEM_BYTES>>>(
        qwh, kwh, kwl, vwh, vwl, bias_w, s_att, cwh);

    // fcs / fcw -> fp16 cat
    {
        GemmCfg c = {};
        c.K = 512; c.ldc = 1024;
        c.Ah[0] = csh; c.Bh[0] = wth + WOFF(6); c.Bl[0] = wtl + WOFF(6);
        c.Ah[1] = cwh; c.Bh[1] = wth + WOFF(7); c.Bl[1] = wtl + WOFF(7);
        c.bias[0] = fcs_b; c.bias[1] = fcw_b;
        c.bscale[0] = 1.f; c.bscale[1] = 1.f;
        c.M[0] = 1024; c.M[1] = 1024;
        c.mode[0] = 1; c.mode[1] = 1;
        c.Ch[0] = cath;       c.Cl[0] = catl;
        c.Ch[1] = cath + 512; c.Cl[1] = catl + 512;
        gemm_cfg<<<dim3(8, 8, 2), 256, HSMEM_BYTES>>>(c);
    }
    // final fco -> fp32 out
    {
        GemmCfg c = {};
        c.K = 1024; c.ldc = 512;
        c.Ah[0] = cath; c.Bh[0] = wth + WOFF(8); c.Bl[0] = wtl + WOFF(8);
        c.bias[0] = fco_b;
        c.bscale[0] = 1.f;
        c.M[0] = 1024;
        c.mode[0] = 0;
        c.Cf[0] = (float*)d_out;
        gemm_cfg<<<dim3(8, 8, 1), 256, HSMEM_BYTES>>>(c);
    }
}

// round 14
// speedup vs baseline: 2.6701x; 1.0137x over previous
#include <cuda_runtime.h>
#include <cuda_fp16.h>
#include <math.h>
#include <stdint.h>

// Problem constants
#define BB   4
#define LQd  256
#define NSd  24
#define NTd  128
#define Dd   512
#define Hd   8
#define DKd  64

// ---------------- scratch layout ----------------
#define OFF_QS   0
#define OFF_KS   524288
#define OFF_VS   573440
#define OFF_ATT  622592
#define OFF_HALF 819200
#define H_ACTH 0
#define H_ACTL 13205504
#define H_WTH  26411008
#define H_WTL  29032448
#define H_QWH  31653888
#define H_QWL  32178176
#define H_KWH  32702464
#define H_KWL  38993920
#define H_VWH  45285376
#define H_VWL  51576832
#define H_CSH  57868288
#define H_CSL  58392576
#define H_CWH  58916864
#define H_CWL  59441152
#define H_CATH 59965440
#define H_CATL 61014016
#define H_TOTAL 62062592
#define SCRATCH_TOTAL (OFF_HALF + H_TOTAL / 2)
__device__ float g_scratch[SCRATCH_TOTAL];

#define AQ   0
#define AKS  524288
#define AVS  573440
#define AKW  622592
#define AVW  6914048
#define WOFF(i) ((i) * 262144)

// ---------------- helpers ----------------
__device__ __forceinline__ void split_h(float x, __half& hi, __half& lo) {
    hi = __float2half_rn(x);
    lo = __float2half_rn(x - __half2float(hi));
}
__device__ __forceinline__ void mma_f16(float d[4],
                                        uint32_t a0, uint32_t a1, uint32_t a2, uint32_t a3,
                                        uint32_t b0, uint32_t b1) {
    asm volatile(
        "mma.sync.aligned.m16n8k16.row.col.f32.f16.f16.f32 "
        "{%0,%1,%2,%3},{%4,%5,%6,%7},{%8,%9},{%0,%1,%2,%3};"
        : "+f"(d[0]), "+f"(d[1]), "+f"(d[2]), "+f"(d[3])
        : "r"(a0), "r"(a1), "r"(a2), "r"(a3), "r"(b0), "r"(b1));
}
__device__ __forceinline__ void ldsm_x4(uint32_t r[4], uint32_t addr) {
    asm volatile("ldmatrix.sync.aligned.m8n8.x4.shared.b16 {%0,%1,%2,%3}, [%4];"
                 : "=r"(r[0]), "=r"(r[1]), "=r"(r[2]), "=r"(r[3]) : "r"(addr));
}
__device__ __forceinline__ void ldsm_x4_t(uint32_t r[4], uint32_t addr) {
    asm volatile("ldmatrix.sync.aligned.m8n8.x4.trans.shared.b16 {%0,%1,%2,%3}, [%4];"
                 : "=r"(r[0]), "=r"(r[1]), "=r"(r[2]), "=r"(r[3]) : "r"(addr));
}
__device__ __forceinline__ void cp_async16(uint32_t smem_addr, const void* gptr, int src_bytes) {
    asm volatile("cp.async.cg.shared.global [%0], [%1], 16, %2;"
                 :: "r"(smem_addr), "l"(gptr), "r"(src_bytes) : "memory");
}
__device__ __forceinline__ void cp_commit() { asm volatile("cp.async.commit_group;" ::: "memory"); }
template <int N>
__device__ __forceinline__ void cp_wait() { asm volatile("cp.async.wait_group %0;" :: "n"(N) : "memory"); }

// ---------------- prep: convert activations to fp16 ----------------
struct ASplitArgs { const float* src[5]; };
__constant__ int c_alen[5] = {524288, 49152, 49152, 6291456, 6291456};
__constant__ int c_aoff[5] = {AQ, AKS, AVS, AKW, AVW};

__global__ __launch_bounds__(256) void act_split(ASplitArgs args, __half* acth)
{
    int z = blockIdx.y;
    int n = c_alen[z];
    const float* s = args.src[z];
    __half* dh = acth + c_aoff[z];
    for (int i = blockIdx.x * 256 + threadIdx.x; i < n; i += gridDim.x * 256) {
        dh[i] = __float2half_rn(s[i]);
    }
}

// ---------------- prep: transpose+split weights ----------------
struct WSplitArgs { const float* src[9]; };
__constant__ int c_wK[9] = {512, 512, 512, 512, 512, 512, 512, 512, 1024};
__constant__ int c_woff[9] = {WOFF(0), WOFF(1), WOFF(2), WOFF(3), WOFF(4),
                              WOFF(5), WOFF(6), WOFF(7), WOFF(8)};
__constant__ float c_wscale[9] = {1.f, 1.f, 1.f, 0.125f, 1.f, 1.f, 1.f, 1.f, 1.f};

__global__ void w_transplit(WSplitArgs args, __half* wth, __half* wtl)
{
    int z = blockIdx.z;
    int Kw = c_wK[z];
    int k0 = blockIdx.y * 32;
    if (k0 >= Kw) return;
    int n0 = blockIdx.x * 32;
    const float* W = args.src[z];
    float sc = c_wscale[z];
    __half* th = wth + c_woff[z];
    __half* tl = wtl + c_woff[z];

    __shared__ float ts[32][33];
    int tx = threadIdx.x, ty = threadIdx.y;
    #pragma unroll
    for (int r = 0; r < 4; r++)
        ts[ty + 8 * r][tx] = W[(size_t)(k0 + ty + 8 * r) * 512 + n0 + tx];
    __syncthreads();
    #pragma unroll
    for (int r = 0; r < 4; r++) {
        int n = n0 + ty + 8 * r;
        int k = k0 + tx;
        __half hi, lo;
        split_h(sc * ts[tx][ty + 8 * r], hi, lo);
        th[(size_t)n * Kw + k] = hi;
        tl[(size_t)n * Kw + k] = lo;
    }
}

// ---------------- 2-term GEMM: A fp16, B split hi/lo, 3-stage pipeline ----------------
#define HAS 40
#define G_A 128
#define G_B 64
#define HSTAGE ((G_A + 2 * G_B) * HAS)
#define HSMEM_BYTES (3 * HSTAGE * 2)

struct GemmCfg {
    const __half* Ah[6];
    const __half* Bh[6]; const __half* Bl[6];
    const float* bias[6];
    float* Cf[6];
    __half* Ch[6]; __half* Cl[6];
    int M[6]; int mode[6]; float bscale[6];
    int K; int ldc;
};

__global__ __launch_bounds__(256, 2) void gemm_cfg(GemmCfg cfg)
{
    extern __shared__ __half hsm[];

    const int z = blockIdx.z;
    const int M = cfg.M[z];
    const int row0 = blockIdx.y * 128;
    if (row0 >= M) return;

    const __half* Ah_g = cfg.Ah[z];
    const __half* Bh_g = cfg.Bh[z];
    const __half* Bl_g = cfg.Bl[z];
    const float* bias  = cfg.bias[z];
    const int mode     = cfg.mode[z];
    const float bsc    = cfg.bscale[z];
    const int K        = cfg.K;
    const int ldc      = cfg.ldc;

    const int tid = threadIdx.x;
    const int wid = tid >> 5;
    const int lane = tid & 31;
    const int g = lane >> 2;
    const int t = lane & 3;
    const int wm = wid & 3;
    const int wn = wid >> 2;
    const int col0 = blockIdx.x * 64;

    const int q8 = lane & 7;
    const int seg = lane >> 3;
    const uint32_t smem_base = (uint32_t)__cvta_generic_to_shared(hsm);
    const uint32_t a_off = (uint32_t)((q8 + (seg & 1) * 8) * HAS + (seg >> 1) * 8);
    const uint32_t b_off = (uint32_t)((q8 + (seg >> 1) * 8) * HAS + (seg & 1) * 8);

    float dm[2][4][4], dc[2][4][4];
    #pragma unroll
    for (int mt = 0; mt < 2; mt++)
        #pragma unroll
        for (int nt = 0; nt < 4; nt++)
            #pragma unroll
            for (int j = 0; j < 4; j++) { dm[mt][nt][j] = 0.f; dc[mt][nt][j] = 0.f; }

    const int ktiles = K >> 5;

    #pragma unroll
    for (int p = 0; p < 2; p++) {
        __half* Ahs = hsm + p * HSTAGE;
        __half* Bhs = Ahs + G_A * HAS;
        __half* Bls = Bhs + G_B * HAS;
        int k0 = p << 5;
        #pragma unroll
        for (int i = 0; i < 2; i++) {
            int id = tid + 256 * i;
            int row = id >> 2, ch = id & 3;
            int r = row0 + row;
            int rc = r < M ? r : (M - 1);
            int pb = r < M ? 16 : 0;
            cp_async16((uint32_t)__cvta_generic_to_shared(&Ahs[row * HAS + ch * 8]),
                       &Ah_g[(size_t)rc * K + k0 + ch * 8], pb);
        }
        #pragma unroll
        for (int i = 0; i < 2; i++) {
            int id = tid + 256 * i;
            int arr = id >> 8, rem = id & 255;
            int row = rem >> 2, ch = rem & 3;
            const __half* src = (arr ? Bl_g : Bh_g) + (size_t)(col0 + row) * K + k0 + ch * 8;
            __half* dst = (arr ? Bls : Bhs) + row * HAS + ch * 8;
            cp_async16((uint32_t)__cvta_generic_to_shared(dst), src, 16);
        }
        cp_commit();
    }
    cp_wait<1>();
    __syncthreads();

    int cst = 0;

    for (int kt = 0; kt < ktiles; kt++) {
        const uint32_t stage = smem_base + (uint32_t)((cst * HSTAGE) * 2);

        #pragma unroll
        for (int ks = 0; ks < 2; ks++) {
            const uint32_t kb = (uint32_t)(ks * 16);
            uint32_t ah[2][4];
            #pragma unroll
            for (int mt = 0; mt < 2; mt++) {
                uint32_t rbase = (uint32_t)((wm * 32 + mt * 16) * HAS) + kb;
                ldsm_x4(ah[mt], stage + 2 * (rbase + a_off));
            }
            uint32_t bh[4][2], bl[4][2];
            #pragma unroll
            for (int p = 0; p < 2; p++) {
                uint32_t nbase = (uint32_t)((wn * 32 + p * 16) * HAS) + kb;
                uint32_t r4[4];
                ldsm_x4(r4, stage + 2 * (G_A * HAS + nbase + b_off));
                bh[2 * p][0] = r4[0]; bh[2 * p][1] = r4[1];
                bh[2 * p + 1][0] = r4[2]; bh[2 * p + 1][1] = r4[3];
                ldsm_x4(r4, stage + 2 * (G_A * HAS + G_B * HAS + nbase + b_off));
                bl[2 * p][0] = r4[0]; bl[2 * p][1] = r4[1];
                bl[2 * p + 1][0] = r4[2]; bl[2 * p + 1][1] = r4[3];
            }
            #pragma unroll
            for (int nt = 0; nt < 4; nt++) {
                #pragma unroll
                for (int mt = 0; mt < 2; mt++) {
                    mma_f16(dm[mt][nt], ah[mt][0], ah[mt][1], ah[mt][2], ah[mt][3], bh[nt][0], bh[nt][1]);
                    mma_f16(dc[mt][nt], ah[mt][0], ah[mt][1], ah[mt][2], ah[mt][3], bl[nt][0], bl[nt][1]);
                }
            }
        }

        int nk = kt + 2;
        if (nk < ktiles) {
            int st = nk % 3;
            __half* Ahs = hsm + st * HSTAGE;
            __half* Bhs = Ahs + G_A * HAS;
            __half* Bls = Bhs + G_B * HAS;
            int k0 = nk << 5;
            #pragma unroll
            for (int i = 0; i < 2; i++) {
                int id = tid + 256 * i;
                int row = id >> 2, ch = id & 3;
                int r = row0 + row;
                int rc = r < M ? r : (M - 1);
                int pb = r < M ? 16 : 0;
                cp_async16((uint32_t)__cvta_generic_to_shared(&Ahs[row * HAS + ch * 8]),
                           &Ah_g[(size_t)rc * K + k0 + ch * 8], pb);
            }
            #pragma unroll
            for (int i = 0; i < 2; i++) {
                int id = tid + 256 * i;
                int arr = id >> 8, rem = id & 255;
                int row = rem >> 2, ch = rem & 3;
                const __half* src = (arr ? Bl_g : Bh_g) + (size_t)(col0 + row) * K + k0 + ch * 8;
                __half* dst = (arr ? Bls : Bhs) + row * HAS + ch * 8;
                cp_async16((uint32_t)__cvta_generic_to_shared(dst), src, 16);
            }
        }
        cp_commit();
        cp_wait<1>();
        __syncthreads();

        cst = (cst == 2) ? 0 : cst + 1;
    }

    #pragma unroll
    for (int mt = 0; mt < 2; mt++) {
        #pragma unroll
        for (int nt = 0; nt < 4; nt++) {
            int r = row0 + wm * 32 + mt * 16 + g;
            int c = col0 + wn * 32 + nt * 8 + 2 * t;
            float2 bz = *(const float2*)&bias[c];
            float o0 = dm[mt][nt][0] + dc[mt][nt][0] + bsc * bz.x;
            float o1 = dm[mt][nt][1] + dc[mt][nt][1] + bsc * bz.y;
            float o2 = dm[mt][nt][2] + dc[mt][nt][2] + bsc * bz.x;
            float o3 = dm[mt][nt][3] + dc[mt][nt][3] + bsc * bz.y;
            if (mode == 0) {
                float* Cf = cfg.Cf[z];
                if (r < M)     *(float2*)&Cf[(size_t)r * ldc + c] = make_float2(o0, o1);
                if (r + 8 < M) *(float2*)&Cf[(size_t)(r + 8) * ldc + c] = make_float2(o2, o3);
            } else {
                __half* Ch = cfg.Ch[z];
                __half* Cl = cfg.Cl[z];
                __half h0, l0, h1, l1;
                if (r < M) {
                    split_h(o0, h0, l0); split_h(o1, h1, l1);
                    *(__half2*)&Ch[(size_t)r * ldc + c] = __halves2half2(h0, h1);
                    *(__half2*)&Cl[(size_t)r * ldc + c] = __halves2half2(l0, l1);
                }
                if (r + 8 < M) {
                    split_h(o2, h0, l0); split_h(o3, h1, l1);
                    *(__half2*)&Ch[(size_t)(r + 8) * ldc + c] = __halves2half2(h0, h1);
                    *(__half2*)&Cl[(size_t)(r + 8) * ldc + c] = __halves2half2(l0, l1);
                }
            }
        }
    }
}

// ---------------- sentence-level graph attention v3: 8 threads/row ----------------
// grid (H, B, 8): 32 query rows per block; row = tid>>3, sub = tid&7 owns 8 k-dims.
__global__ __launch_bounds__(256) void sent_attn8(
    const float* __restrict__ qs, const float* __restrict__ ksn,
    const float* __restrict__ vsn, const float* __restrict__ bias_s,
    const float* __restrict__ gab,
    float* __restrict__ attns_out,
    __half* __restrict__ csh)
{
    const int h = blockIdx.x, b = blockIdx.y;
    const int q0 = blockIdx.z * 32;
    const int tid = threadIdx.x;
    const int row = tid >> 3;
    const int sub = tid & 7;
    const int q = q0 + row;

    __shared__ float Ks[NSd][DKd + 1];
    __shared__ float Vs[NSd][DKd + 1];
    __shared__ float G[NSd][NSd + 1];
    __shared__ float Att[32][NSd + 1];

    for (int idx = tid; idx < NSd * DKd; idx += 256) {
        int s = idx >> 6, k = idx & 63;
        Ks[s][k] = ksn[(size_t)(b * NSd + s) * Dd + h * DKd + k];
        Vs[s][k] = vsn[(size_t)(b * NSd + s) * Dd + h * DKd + k];
    }
    for (int idx = tid; idx < NSd * NSd; idx += 256) {
        int s = idx / NSd, tt = idx % NSd;
        G[s][tt] = gab[((size_t)(b * Hd + h) * NSd + s) * NSd + tt];
    }
    __syncthreads();

    float qreg[8];
    const float* qrow = qs + (size_t)(b * LQd + q) * Dd + h * DKd + sub * 8;
    #pragma unroll
    for (int k = 0; k < 8; k++) qreg[k] = qrow[k] * 0.125f;

    float a[NSd];
    #pragma unroll
    for (int s = 0; s < NSd; s++) {
        float dd = 0.f;
        #pragma unroll
        for (int k = 0; k < 8; k++) dd += qreg[k] * Ks[s][sub * 8 + k];
        a[s] = dd;
    }
    #pragma unroll
    for (int s = 0; s < NSd; s++) {
        a[s] += __shfl_xor_sync(0xffffffffu, a[s], 1);
        a[s] += __shfl_xor_sync(0xffffffffu, a[s], 2);
        a[s] += __shfl_xor_sync(0xffffffffu, a[s], 4);
    }
    const float* bsrow = bias_s + ((size_t)(b * Hd + h) * LQd + q) * NSd;
    #pragma unroll
    for (int s = 0; s < NSd; s++) a[s] += bsrow[s];

    float m = -1e30f;
    #pragma unroll
    for (int s = 0; s < NSd; s++) m = fmaxf(m, a[s]);
    float smx[NSd]; float sum = 0.f;
    #pragma unroll
    for (int s = 0; s < NSd; s++) { smx[s] = __expf(a[s] - m); sum += smx[s]; }
    float inv = 1.f / sum;

    // graph prior: this thread owns t in [sub*3, sub*3+3)
    const int t0 = sub * 3;
    float an[3];
    #pragma unroll
    for (int j = 0; j < 3; j++) {
        float dd = 0.f;
        #pragma unroll
        for (int s = 0; s < NSd; s++) dd += smx[s] * G[s][t0 + j];
        float gg = dd * inv;
        an[j] = a[t0 + j] - 0.5f * gg * gg;
    }

    float m2 = -1e30f;
    #pragma unroll
    for (int j = 0; j < 3; j++) m2 = fmaxf(m2, an[j]);
    m2 = fmaxf(m2, __shfl_xor_sync(0xffffffffu, m2, 1));
    m2 = fmaxf(m2, __shfl_xor_sync(0xffffffffu, m2, 2));
    m2 = fmaxf(m2, __shfl_xor_sync(0xffffffffu, m2, 4));
    float e[3]; float su = 0.f;
    #pragma unroll
    for (int j = 0; j < 3; j++) { e[j] = __expf(an[j] - m2); su += e[j]; }
    su += __shfl_xor_sync(0xffffffffu, su, 1);
    su += __shfl_xor_sync(0xffffffffu, su, 2);
    su += __shfl_xor_sync(0xffffffffu, su, 4);
    float inv2 = 1.f / su;

    float* arow = attns_out + ((size_t)(b * Hd + h) * LQd + q) * NSd;
    #pragma unroll
    for (int j = 0; j < 3; j++) {
        float v = e[j] * inv2;
        Att[row][t0 + j] = v;
        arow[t0 + j] = v;
    }
    __syncwarp();

    float att[NSd];
    #pragma unroll
    for (int s = 0; s < NSd; s++) att[s] = Att[row][s];

    size_t cbase = (size_t)(b * LQd + q) * Dd + h * DKd + sub * 8;
    #pragma unroll
    for (int dd = 0; dd < 8; dd++) {
        float acc = 0.f;
        #pragma unroll
        for (int s = 0; s < NSd; s++) acc += att[s] * Vs[s][sub * 8 + dd];
        csh[cbase + dd] = __float2half_rn(acc);
    }
}

// ---------------- word-level attention v6: split K/V pipelining ----------------
#define HQS 72
#define W_QH 0
#define W_KV (32 * HQS)
#define W_ARR (128 * HQS)
#define W_P  (W_KV + 4 * W_ARR)
#define PROW 264
#define WSMEM_BYTES ((W_P + 32 * PROW) * 2)

__global__ __launch_bounds__(512, 2) void word_attn_h6(
    const __half* __restrict__ qwh,
    const __half* __restrict__ kwh, const __half* __restrict__ kwl,
    const __half* __restrict__ vwh, const __half* __restrict__ vwl,
    const float* __restrict__ bias_w, const float* __restrict__ attns,
    __half* __restrict__ cwh)
{
    extern __shared__ __half hsm[];
    float* Ps = (float*)(hsm + W_P);
    __half* PU = hsm + W_P;

    const int tid = threadIdx.x;
    const int wid = tid >> 5;
    const int lane = tid & 31;
    const int g = lane >> 2;
    const int t = lane & 3;
    const int wm = wid & 1;
    const int wn = wid >> 1;
    const int q0 = blockIdx.x * 32;
    const int h  = blockIdx.y;
    const int b  = blockIdx.z;

    const int q8 = lane & 7;
    const int seg = lane >> 3;
    const uint32_t smem_base = (uint32_t)__cvta_generic_to_shared(hsm);
    const uint32_t aq_off = (uint32_t)((q8 + (seg & 1) * 8) * HQS + (seg >> 1) * 8);
    const uint32_t bk_off = (uint32_t)((q8 + (seg >> 1) * 8) * HQS + (seg & 1) * 8);
    const uint32_t ap_off = (uint32_t)((q8 + (seg & 1) * 8) * PROW + (seg >> 1) * 8);
    const uint32_t v_arr  = (seg >> 1) ? (uint32_t)(W_KV + 3 * W_ARR) : (uint32_t)(W_KV + 2 * W_ARR);
    const uint32_t v_off  = (uint32_t)((q8 + (seg & 1) * 8) * HQS + wn * 8);

    // per-thread load slot (2048 K-slots = kh+kl, 2048 V-slots = vh+vl; 512 threads x 4)
    // prologue: Q + K0 + V0 in one group
    {
        if (tid < 256) {
            int row = tid >> 3, ch = tid & 7;
            const __half* src = qwh + (size_t)(b * LQd + q0 + row) * Dd + h * DKd + ch * 8;
            cp_async16((uint32_t)__cvta_generic_to_shared(&hsm[W_QH + row * HQS + ch * 8]),
                       src, 16);
        }
        const size_t kvb = (size_t)(b * NSd) * NTd * Dd + h * DKd;
        const __half* srcs[4] = {kwh, kwl, vwh, vwl};
        #pragma unroll
        for (int i = 0; i < 8; i++) {
            int id = tid + 512 * i;
            int arr = id >> 10, rem = id & 1023;
            int row = rem >> 3, ch = rem & 7;
            const __half* src = srcs[arr] + kvb + (size_t)row * Dd + ch * 8;
            cp_async16((uint32_t)__cvta_generic_to_shared(
                           &hsm[W_KV + arr * W_ARR + row * HQS + ch * 8]),
                       src, 16);
        }
        cp_commit();
        cp_wait<0>();
    }
    __syncthreads();

    float om[4], oc[4];
    #pragma unroll
    for (int j = 0; j < 4; j++) { om[j] = 0.f; oc[j] = 0.f; }

    for (int s = 0; s < NSd; s++) {
        // ---- QK ----
        float pm[2][4], pc[2][4];
        #pragma unroll
        for (int nt = 0; nt < 2; nt++)
            #pragma unroll
            for (int j = 0; j < 4; j++) { pm[nt][j] = 0.f; pc[nt][j] = 0.f; }

        #pragma unroll
        for (int ks = 0; ks < 4; ks++) {
            const uint32_t kb = (uint32_t)(ks * 16);
            uint32_t ahq[4], kh4[4], kl4[4];
            uint32_t qrb = (uint32_t)(wm * 16 * HQS) + kb;
            ldsm_x4(ahq, smem_base + 2 * (W_QH + qrb + aq_off));
            uint32_t krb = (uint32_t)(wn * 16 * HQS) + kb;
            ldsm_x4(kh4, smem_base + 2 * (W_KV + krb + bk_off));
            ldsm_x4(kl4, smem_base + 2 * (W_KV + W_ARR + krb + bk_off));
            #pragma unroll
            for (int nt = 0; nt < 2; nt++) {
                mma_f16(pm[nt], ahq[0], ahq[1], ahq[2], ahq[3], kh4[2 * nt], kh4[2 * nt + 1]);
                mma_f16(pc[nt], ahq[0], ahq[1], ahq[2], ahq[3], kl4[2 * nt], kl4[2 * nt + 1]);
            }
        }
        #pragma unroll
        for (int nt = 0; nt < 2; nt++) {
            int r = wm * 16 + g;
            int c = wn * 16 + nt * 8 + 2 * t;
            *(float2*)&Ps[r * 132 + c] = make_float2(pm[nt][0] + pc[nt][0], pm[nt][1] + pc[nt][1]);
            *(float2*)&Ps[(r + 8) * 132 + c] = make_float2(pm[nt][2] + pc[nt][2], pm[nt][3] + pc[nt][3]);
        }
        __syncthreads();   // (a) Ps visible; K[s] dead

        // issue K(s+1) — overlaps softmax + PV
        if (s + 1 < NSd) {
            const size_t kvb = (size_t)(b * NSd + s + 1) * NTd * Dd + h * DKd;
            const __half* srcs[2] = {kwh, kwl};
            #pragma unroll
            for (int i = 0; i < 4; i++) {
                int id = tid + 512 * i;
                int arr = id >> 10, rem = id & 1023;
                int row = rem >> 3, ch = rem & 7;
                const __half* src = srcs[arr] + kvb + (size_t)row * Dd + ch * 8;
                cp_async16((uint32_t)__cvta_generic_to_shared(
                               &hsm[W_KV + arr * W_ARR + row * HQS + ch * 8]),
                           src, 16);
            }
            cp_commit();
        }

        // ---- softmax ----
        const float* bb = bias_w + ((size_t)((b * NSd + s) * Hd + h) * LQd + q0) * NTd;
        #pragma unroll
        for (int rr = 0; rr < 2; rr++) {
            int r = wid * 2 + rr;
            float x0 = Ps[r * 132 + lane]       + bb[r * NTd + lane];
            float x1 = Ps[r * 132 + lane + 32]  + bb[r * NTd + lane + 32];
            float x2 = Ps[r * 132 + lane + 64]  + bb[r * NTd + lane + 64];
            float x3 = Ps[r * 132 + lane + 96]  + bb[r * NTd + lane + 96];
            float mx = fmaxf(fmaxf(x0, x1), fmaxf(x2, x3));
            #pragma unroll
            for (int o = 16; o; o >>= 1) mx = fmaxf(mx, __shfl_xor_sync(0xffffffffu, mx, o));
            x0 = __expf(x0 - mx); x1 = __expf(x1 - mx);
            x2 = __expf(x2 - mx); x3 = __expf(x3 - mx);
            float su = x0 + x1 + x2 + x3;
            #pragma unroll
            for (int o = 16; o; o >>= 1) su += __shfl_xor_sync(0xffffffffu, su, o);
            float wsc = attns[((size_t)(b * Hd + h) * LQd + q0 + r) * NSd + s] / su;
            __half h0 = __float2half_rn(x0 * wsc);
            __half h1 = __float2half_rn(x1 * wsc);
            __half h2 = __float2half_rn(x2 * wsc);
            __half h3 = __float2half_rn(x3 * wsc);
            __syncwarp();
            __half* prow = PU + r * PROW;
            prow[lane]       = h0;
            prow[lane + 32]  = h1;
            prow[lane + 64]  = h2;
            prow[lane + 96]  = h3;
        }
        // wait for V[s] group from previous iteration (FIFO: oldest completes first;
        // allow the just-issued K(s+1) group to keep flying)
        if (s > 0) cp_wait<1>();
        __syncthreads();   // (b) PU visible; V[s] visible

        // ---- PV ----
        #pragma unroll
        for (int ks = 0; ks < 8; ks++) {
            const uint32_t kb = (uint32_t)(ks * 16);
            uint32_t ph4[4], v4[4];
            uint32_t prb = (uint32_t)(wm * 16 * PROW) + kb;
            ldsm_x4(ph4, smem_base + 2 * (W_P + prb + ap_off));
            ldsm_x4_t(v4, smem_base + 2 * (v_arr + kb * HQS + v_off));
            mma_f16(om, ph4[0], ph4[1], ph4[2], ph4[3], v4[0], v4[1]);
            mma_f16(oc, ph4[0], ph4[1], ph4[2], ph4[3], v4[2], v4[3]);
        }

        if (s + 1 < NSd) {
            __syncthreads();   // (c) V[s] dead
            // issue V(s+1) — overlaps next QK + softmax
            const size_t kvb = (size_t)(b * NSd + s + 1) * NTd * Dd + h * DKd;
            const __half* srcs[2] = {vwh, vwl};
            #pragma unroll
            for (int i = 0; i < 4; i++) {
                int id = tid + 512 * i;
                int arr = id >> 10, rem = id & 1023;
                int row = rem >> 3, ch = rem & 7;
                const __half* src = srcs[arr] + kvb + (size_t)row * Dd + ch * 8;
                cp_async16((uint32_t)__cvta_generic_to_shared(
                               &hsm[W_KV + (2 + arr) * W_ARR + row * HQS + ch * 8]),
                           src, 16);
            }
            cp_commit();
            cp_wait<1>();      // K(s+1) done (oldest); V(s+1) flying
            __syncthreads();   // (d) K(s+1) visible
        }
    }

    {
        int r = q0 + wm * 16 + g;
        int c = h * DKd + wn * 8 + 2 * t;
        float v0 = om[0] + oc[0], v1 = om[1] + oc[1];
        float v2 = om[2] + oc[2], v3 = om[3] + oc[3];
        *(__half2*)&cwh[(size_t)(b * LQd + r) * Dd + c] =
            __halves2half2(__float2half_rn(v0), __float2half_rn(v1));
        *(__half2*)&cwh[(size_t)(b * LQd + r + 8) * Dd + c] =
            __halves2half2(__float2half_rn(v2), __float2half_rn(v3));
    }
}

// ---------------- host ----------------
extern "C" void kernel_launch(void* const* d_in, const int* in_sizes, int n_in,
                              void* d_out, int out_size)
{
    const float* q      = (const float*)d_in[0];
    const float* k_s    = (const float*)d_in[1];
    const float* v_s    = (const float*)d_in[2];
    const float* k_w    = (const float*)d_in[3];
    const float* v_w    = (const float*)d_in[4];
    const float* bias_w = (const float*)d_in[5];
    const float* bias_s = (const float*)d_in[6];
    const float* gab    = (const float*)d_in[7];

    const float *wq_s, *bq_s, *wk_s, *bk_s, *wv_s, *bv_s;
    const float *wq_w, *bq_w, *wk_w, *bk_w, *wv_w, *bv_w;
    const float *fcs_w, *fcs_b, *fcw_w, *fcw_b, *fco_w, *fco_b;

    if (in_sizes[9] == 512) {
        wq_s = (const float*)d_in[8];  bq_s = (const float*)d_in[9];
        wk_s = (const float*)d_in[10]; bk_s = (const float*)d_in[11];
        wv_s = (const float*)d_in[12]; bv_s = (const float*)d_in[13];
        wq_w = (const float*)d_in[14]; bq_w = (const float*)d_in[15];
        wk_w = (const float*)d_in[16]; bk_w = (const float*)d_in[17];
        wv_w = (const float*)d_in[18]; bv_w = (const float*)d_in[19];
        fcs_w = (const float*)d_in[20]; fcs_b = (const float*)d_in[21];
        fcw_w = (const float*)d_in[22]; fcw_b = (const float*)d_in[23];
        fco_w = (const float*)d_in[24]; fco_b = (const float*)d_in[25];
    } else {
        wq_s = (const float*)d_in[8];  wk_s = (const float*)d_in[9];
        wv_s = (const float*)d_in[10]; wq_w = (const float*)d_in[11];
        wk_w = (const float*)d_in[12]; wv_w = (const float*)d_in[13];
        fcs_w = (const float*)d_in[14]; fcw_w = (const float*)d_in[15];
        bq_s = (const float*)d_in[16]; bk_s = (const float*)d_in[17];
        bv_s = (const float*)d_in[18]; bq_w = (const float*)d_in[19];
        bk_w = (const float*)d_in[20]; bv_w = (const float*)d_in[21];
        fcs_b = (const float*)d_in[22]; fcw_b = (const float*)d_in[23];
        fco_w = (const float*)d_in[24]; fco_b = (const float*)d_in[25];
    }

    float* scratch = nullptr;
    cudaGetSymbolAddress((void**)&scratch, g_scratch);
    float* s_qs  = scratch + OFF_QS;
    float* s_ks  = scratch + OFF_KS;
    float* s_vs  = scratch + OFF_VS;
    float* s_att = scratch + OFF_ATT;
    __half* hb = (__half*)(scratch + OFF_HALF);
    __half* acth = hb + H_ACTH;
    __half* wth  = hb + H_WTH;
    __half* wtl  = hb + H_WTL;
    __half* qwh  = hb + H_QWH;
    __half* qwl  = hb + H_QWL;
    __half* kwh  = hb + H_KWH;
    __half* kwl  = hb + H_KWL;
    __half* vwh  = hb + H_VWH;
    __half* vwl  = hb + H_VWL;
    __half* csh  = hb + H_CSH;
    __half* cwh  = hb + H_CWH;
    __half* cath = hb + H_CATH;
    __half* catl = hb + H_CATL;

    cudaFuncSetAttribute(gemm_cfg, cudaFuncAttributeMaxDynamicSharedMemorySize, HSMEM_BYTES);
    cudaFuncSetAttribute(word_attn_h6, cudaFuncAttributeMaxDynamicSharedMemorySize, WSMEM_BYTES);

    // prep
    ASplitArgs aa;
    aa.src[0] = q; aa.src[1] = k_s; aa.src[2] = v_s; aa.src[3] = k_w; aa.src[4] = v_w;
    act_split<<<dim3(256, 5), 256>>>(aa, acth);
    WSplitArgs wa;
    wa.src[0] = wq_s; wa.src[1] = wk_s; wa.src[2] = wv_s;
    wa.src[3] = wq_w; wa.src[4] = wk_w; wa.src[5] = wv_w;
    wa.src[6] = fcs_w; wa.src[7] = fcw_w; wa.src[8] = fco_w;
    w_transplit<<<dim3(16, 32, 9), dim3(32, 8)>>>(wa, wth, wtl);

    // all projections in ONE launch
    {
        GemmCfg c = {};
        c.K = 512; c.ldc = 512;
        c.Ah[0] = acth + AKW; c.Bh[0] = wth + WOFF(4); c.Bl[0] = wtl + WOFF(4);
        c.Ah[1] = acth + AVW; c.Bh[1] = wth + WOFF(5); c.Bl[1] = wtl + WOFF(5);
        c.Ah[2] = acth + AQ;  c.Bh[2] = wth + WOFF(0); c.Bl[2] = wtl + WOFF(0);
        c.Ah[3] = acth + AQ;  c.Bh[3] = wth + WOFF(3); c.Bl[3] = wtl + WOFF(3);
        c.Ah[4] = acth + AKS; c.Bh[4] = wth + WOFF(1); c.Bl[4] = wtl + WOFF(1);
        c.Ah[5] = acth + AVS; c.Bh[5] = wth + WOFF(2); c.Bl[5] = wtl + WOFF(2);
        c.bias[0] = bk_w; c.bias[1] = bv_w; c.bias[2] = bq_s;
        c.bias[3] = bq_w; c.bias[4] = bk_s; c.bias[5] = bv_s;
        c.bscale[0] = 1.f; c.bscale[1] = 1.f; c.bscale[2] = 1.f;
        c.bscale[3] = 0.125f; c.bscale[4] = 1.f; c.bscale[5] = 1.f;
        c.M[0] = 12288; c.M[1] = 12288; c.M[2] = 1024;
        c.M[3] = 1024;  c.M[4] = 96;    c.M[5] = 96;
        c.mode[0] = 1; c.mode[1] = 1; c.mode[2] = 0;
        c.mode[3] = 1; c.mode[4] = 0; c.mode[5] = 0;
        c.Ch[0] = kwh; c.Cl[0] = kwl;
        c.Ch[1] = vwh; c.Cl[1] = vwl;
        c.Cf[2] = s_qs;
        c.Ch[3] = qwh; c.Cl[3] = qwl;
        c.Cf[4] = s_ks;
        c.Cf[5] = s_vs;
        gemm_cfg<<<dim3(8, 96, 6), 256, HSMEM_BYTES>>>(c);
    }

    sent_attn8<<<dim3(Hd, BB, 8), 256>>>(s_qs, s_ks, s_vs, bias_s, gab, s_att, csh);

    word_attn_h6<<<dim3(8, Hd, BB), 512, WSMEM_BYTES>>>(
        qwh, kwh, kwl, vwh, vwl, bias_w, s_att, cwh);

    // fcs / fcw -> fp16 cat
    {
        GemmCfg c = {};
        c.K = 512; c.ldc = 1024;
        c.Ah[0] = csh; c.Bh[0] = wth + WOFF(6); c.Bl[0] = wtl + WOFF(6);
        c.Ah[1] = cwh; c.Bh[1] = wth + WOFF(7); c.Bl[1] = wtl + WOFF(7);
        c.bias[0] = fcs_b; c.bias[1] = fcw_b;
        c.bscale[0] = 1.f; c.bscale[1] = 1.f;
        c.M[0] = 1024; c.M[1] = 1024;
        c.mode[0] = 1; c.mode[1] = 1;
        c.Ch[0] = cath;       c.Cl[0] = catl;
        c.Ch[1] = cath + 512; c.Cl[1] = catl + 512;
        gemm_cfg<<<dim3(8, 8, 2), 256, HSMEM_BYTES>>>(c);
    }
    // final fco -> fp32 out
    {
        GemmCfg c = {};
        c.K = 1024; c.ldc = 512;
        c.Ah[0] = cath; c.Bh[0] = wth + WOFF(8); c.Bl[0] = wtl + WOFF(8);
        c.bias[0] = fco_b;
        c.bscale[0] = 1.f;
        c.M[0] = 1024;
        c.mode[0] = 0;
        c.Cf[0] = (float*)d_out;
        gemm_cfg<<<dim3(8, 8, 1), 256, HSMEM_BYTES>>>(c);
    }
}